// round 4
// baseline (speedup 1.0000x reference)
#include <cuda_runtime.h>
#include <math.h>

#define DIM   512
#define NH    8
#define HD    64
#define SEQ   2048
#define BATCH 2
#define MTOT  (BATCH * SEQ)   // 4096
#define KIN   (2 * DIM)       // 1024

typedef unsigned long long u64t;

// ---- packed f32x2 helpers (SASS FFMA2 path; ptxas never auto-fuses) ----
__device__ __forceinline__ u64t fma2(u64t a, u64t b, u64t c) {
    u64t d; asm("fma.rn.f32x2 %0, %1, %2, %3;" : "=l"(d) : "l"(a), "l"(b), "l"(c));
    return d;
}
__device__ __forceinline__ u64t mul2(u64t a, u64t b) {
    u64t d; asm("mul.rn.f32x2 %0, %1, %2;" : "=l"(d) : "l"(a), "l"(b));
    return d;
}
__device__ __forceinline__ u64t dup2f(float x) {
    u64t r; asm("mov.b64 %0, {%1, %1};" : "=l"(r) : "f"(x));
    return r;
}
__device__ __forceinline__ float2 unpk(u64t v) {
    float lo, hi; asm("mov.b64 {%0, %1}, %2;" : "=f"(lo), "=f"(hi) : "l"(v));
    float2 f; f.x = lo; f.y = hi; return f;
}

// Scratch (device globals: no allocation allowed in kernel_launch)
__device__ float g_Q[BATCH * NH * SEQ * HD];   // [b,h,s,d]  sqrt(softmax(Q))
__device__ float g_K[BATCH * NH * SEQ * HD];   //            sqrt(softmax(K))
__device__ float g_V[BATCH * NH * SEQ * HD];
__device__ float g_att[MTOT * DIM];            // [b,s, h*64+d]

// ---------------------------------------------------------------------------
// Projection GEMM: Y = concat(xr,xi) @ W + b.  M=4096, N=512, K=1024.
// 128x128 tile, BK=16, 256 threads, 8x8 reg tile as 4(i2)x8(j) FFMA2,
// double-buffered. DO_SM: fused per-head sqrt(softmax) epilogue.
// ---------------------------------------------------------------------------
template<bool DO_SM>
__global__ __launch_bounds__(256, 2) void proj_gemm(
    const float* __restrict__ xr, const float* __restrict__ xi,
    const float* __restrict__ W,  const float* __restrict__ bias,
    float* __restrict__ out)
{
    __shared__ __align__(16) float As[2][16][132];   // k-major, 528B rows
    __shared__ __align__(16) float Bs[2][16][128];

    const int tid = threadIdx.x;
    const int tx = tid & 15, ty = tid >> 4;
    const int m0 = blockIdx.y * 128;
    const int n0 = blockIdx.x * 128;

    const int ar  = tid >> 2;           // 0..63 (+64)
    const int ac4 = (tid & 3) << 2;
    const int br  = tid >> 5;           // 0..7 (+8)
    const int bc4 = (tid & 31) << 2;

    float4 a0, a1, b0, b1;
    {
        a0 = *(const float4*)(xr + (size_t)(m0 + ar)      * DIM + ac4);
        a1 = *(const float4*)(xr + (size_t)(m0 + ar + 64) * DIM + ac4);
        b0 = *(const float4*)(W + (size_t)(br)     * DIM + n0 + bc4);
        b1 = *(const float4*)(W + (size_t)(br + 8) * DIM + n0 + bc4);
        As[0][ac4+0][ar] = a0.x; As[0][ac4+1][ar] = a0.y;
        As[0][ac4+2][ar] = a0.z; As[0][ac4+3][ar] = a0.w;
        As[0][ac4+0][ar+64] = a1.x; As[0][ac4+1][ar+64] = a1.y;
        As[0][ac4+2][ar+64] = a1.z; As[0][ac4+3][ar+64] = a1.w;
        *(float4*)&Bs[0][br][bc4]     = b0;
        *(float4*)&Bs[0][br + 8][bc4] = b1;
    }
    __syncthreads();

    u64t acc2[4][8];
#pragma unroll
    for (int i = 0; i < 4; i++)
#pragma unroll
        for (int j = 0; j < 8; j++) acc2[i][j] = 0ull;

    const int NIT = KIN / 16;   // 64

    for (int it = 0; it < NIT; ++it) {
        const int cur = it & 1;
        if (it + 1 < NIT) {
            const int kt = (it + 1) * 16;
            const float* base = (kt < DIM) ? xr : xi;
            const int ko = (kt < DIM) ? kt : (kt - DIM);
            a0 = *(const float4*)(base + (size_t)(m0 + ar)      * DIM + ko + ac4);
            a1 = *(const float4*)(base + (size_t)(m0 + ar + 64) * DIM + ko + ac4);
            b0 = *(const float4*)(W + (size_t)(kt + br)     * DIM + n0 + bc4);
            b1 = *(const float4*)(W + (size_t)(kt + br + 8) * DIM + n0 + bc4);
        }
#pragma unroll
        for (int kk = 0; kk < 16; ++kk) {
            // a: packed i-pairs straight from smem
            longlong2 al0 = *(const longlong2*)&As[cur][kk][ty * 8];
            longlong2 al1 = *(const longlong2*)&As[cur][kk][ty * 8 + 4];
            u64t a2[4] = { (u64t)al0.x, (u64t)al0.y, (u64t)al1.x, (u64t)al1.y };
            float bf[8];
            *(float4*)&bf[0] = *(const float4*)&Bs[cur][kk][tx * 8];
            *(float4*)&bf[4] = *(const float4*)&Bs[cur][kk][tx * 8 + 4];
            u64t bd[8];
#pragma unroll
            for (int j = 0; j < 8; j++) bd[j] = dup2f(bf[j]);
#pragma unroll
            for (int i = 0; i < 4; i++)
#pragma unroll
                for (int j = 0; j < 8; j++)
                    acc2[i][j] = fma2(a2[i], bd[j], acc2[i][j]);
        }
        if (it + 1 < NIT) {
            const int nxt = cur ^ 1;
            As[nxt][ac4+0][ar] = a0.x; As[nxt][ac4+1][ar] = a0.y;
            As[nxt][ac4+2][ar] = a0.z; As[nxt][ac4+3][ar] = a0.w;
            As[nxt][ac4+0][ar+64] = a1.x; As[nxt][ac4+1][ar+64] = a1.y;
            As[nxt][ac4+2][ar+64] = a1.z; As[nxt][ac4+3][ar+64] = a1.w;
            *(float4*)&Bs[nxt][br][bc4]     = b0;
            *(float4*)&Bs[nxt][br + 8][bc4] = b1;
        }
        __syncthreads();
    }

    // epilogue
    float bb[8];
#pragma unroll
    for (int j = 0; j < 8; j++) bb[j] = bias[n0 + tx * 8 + j];
    const int h  = (n0 >> 6) + (tx >> 3);
    const int d0 = (tx & 7) * 8;

#pragma unroll
    for (int i2 = 0; i2 < 4; i2++) {
        float2 p[8];
#pragma unroll
        for (int j = 0; j < 8; j++) p[j] = unpk(acc2[i2][j]);
#pragma unroll
        for (int e = 0; e < 2; e++) {
            const int i = 2 * i2 + e;
            const int m = m0 + ty * 8 + i;
            const int b = m >> 11;
            const int s = m & (SEQ - 1);
            float v[8];
#pragma unroll
            for (int j = 0; j < 8; j++) v[j] = (e ? p[j].y : p[j].x) + bb[j];
            if (DO_SM) {
                float mx = v[0];
#pragma unroll
                for (int j = 1; j < 8; j++) mx = fmaxf(mx, v[j]);
#pragma unroll
                for (int off = 1; off < 8; off <<= 1)
                    mx = fmaxf(mx, __shfl_xor_sync(0xffffffffu, mx, off));
                float sum = 0.0f;
#pragma unroll
                for (int j = 0; j < 8; j++) { v[j] = __expf(v[j] - mx); sum += v[j]; }
#pragma unroll
                for (int off = 1; off < 8; off <<= 1)
                    sum += __shfl_xor_sync(0xffffffffu, sum, off);
                const float inv = 1.0f / sum;
#pragma unroll
                for (int j = 0; j < 8; j++) v[j] = sqrtf(v[j] * inv);
            }
            float* dst = out + ((size_t)(b * NH + h) * SEQ + s) * HD + d0;
            float4 v0 = { v[0], v[1], v[2], v[3] };
            float4 v1 = { v[4], v[5], v[6], v[7] };
            *(float4*)dst       = v0;
            *(float4*)(dst + 4) = v1;
        }
    }
}

// ---------------------------------------------------------------------------
// Attention, FFMA2 edition. Per block: 128 i-rows of one (b,h); 64-wide j-tiles.
//   bc = sp_i . sq_j  in (0,1] (Cauchy-Schwarz, rows unit-L2) -> no clamp
//   g' = -acos(1-u)^2 via negated degree-10 series, w = exp(g')
// smem: Ps[64d][132i], Qs[64d][68j], Vs[64j][64d], Ws[64j][132i] (j-major!).
// ---------------------------------------------------------------------------
__global__ __launch_bounds__(256, 2) void attn_kernel(
    const float* __restrict__ sp, const float* __restrict__ sq,
    const float* __restrict__ V,  float* __restrict__ out)
{
    extern __shared__ __align__(16) float sm[];
    float* Ps = sm;                        // [64][132]
    float* Qs = Ps + 64 * 132;             // [64][68]
    float* Vs = Qs + 64 * 68;              // [64][64]
    float* Ws = Vs + 64 * 64;              // [64][132]  j-major: Ws[j][i]

    const int tid = threadIdx.x;
    const int tx = tid & 15, ty = tid >> 4;
    const int bh = blockIdx.y;
    const int i0 = blockIdx.x * 128;

    const float* spb = sp + (size_t)bh * SEQ * HD;
    const float* sqb = sq + (size_t)bh * SEQ * HD;
    const float* Vb  = V  + (size_t)bh * SEQ * HD;

    // resident sp tile, d-major
#pragma unroll
    for (int p = 0; p < 8; p++) {
        int l = tid + p * 256;
        int i = l >> 4, c4 = (l & 15) << 2;
        float4 v = *(const float4*)(spb + (size_t)(i0 + i) * HD + c4);
        Ps[(c4 + 0) * 132 + i] = v.x; Ps[(c4 + 1) * 132 + i] = v.y;
        Ps[(c4 + 2) * 132 + i] = v.z; Ps[(c4 + 3) * 132 + i] = v.w;
    }

    // negated acos^2 series coefficients (packed)
    const u64t K9 = dup2f(-2.0705e-4f);
    const u64t K8 = dup2f(-2.6002e-4f);
    const u64t K7 = dup2f(-6.2160e-4f);
    const u64t K6 = dup2f(-1.52229e-3f);
    const u64t K5 = dup2f(-3.84800e-3f);
    const u64t K4 = dup2f(-1.015873e-2f);
    const u64t K3 = dup2f(-2.8571429e-2f);
    const u64t K2 = dup2f(-8.8888889e-2f);
    const u64t K1 = dup2f(-0.33333333f);
    const u64t K0 = dup2f(-2.0f);
    const u64t CM1 = dup2f(-1.0f);
    const u64t CP1 = dup2f(1.0f);

    u64t o2[4][4];
#pragma unroll
    for (int i = 0; i < 4; i++)
#pragma unroll
        for (int j = 0; j < 4; j++) o2[i][j] = 0ull;
    float den[8] = {};

    for (int j0 = 0; j0 < SEQ; j0 += 64) {
        __syncthreads();   // prior readers of Qs/Vs/Ws done
#pragma unroll
        for (int p = 0; p < 4; p++) {
            int l = tid + p * 256;
            int j = l >> 4, c4 = (l & 15) << 2;
            float4 q = *(const float4*)(sqb + (size_t)(j0 + j) * HD + c4);
            Qs[(c4 + 0) * 68 + j] = q.x; Qs[(c4 + 1) * 68 + j] = q.y;
            Qs[(c4 + 2) * 68 + j] = q.z; Qs[(c4 + 3) * 68 + j] = q.w;
            float4 vv = *(const float4*)(Vb + (size_t)(j0 + j) * HD + c4);
            *(float4*)&Vs[j * 64 + c4] = vv;
        }
        __syncthreads();

        // bc = Ps^T Qs : 4(i2) x 4(j) FFMA2 tile
        u64t bc2[4][4];
#pragma unroll
        for (int i = 0; i < 4; i++)
#pragma unroll
            for (int j = 0; j < 4; j++) bc2[i][j] = 0ull;
#pragma unroll 8
        for (int kk = 0; kk < 64; kk++) {
            longlong2 al0 = *(const longlong2*)&Ps[kk * 132 + ty * 8];
            longlong2 al1 = *(const longlong2*)&Ps[kk * 132 + ty * 8 + 4];
            u64t a2[4] = { (u64t)al0.x, (u64t)al0.y, (u64t)al1.x, (u64t)al1.y };
            float4 bq = *(const float4*)&Qs[kk * 68 + tx * 4];
            u64t bd[4] = { dup2f(bq.x), dup2f(bq.y), dup2f(bq.z), dup2f(bq.w) };
#pragma unroll
            for (int i = 0; i < 4; i++)
#pragma unroll
                for (int j = 0; j < 4; j++)
                    bc2[i][j] = fma2(a2[i], bd[j], bc2[i][j]);
        }

        // transform (packed poly) + store w j-major
#pragma unroll
        for (int j = 0; j < 4; j++) {
            float wf[8];
#pragma unroll
            for (int i2 = 0; i2 < 4; i2++) {
                u64t u2 = fma2(bc2[i2][j], CM1, CP1);   // u = 1 - bc
                u64t g = K9;
                g = fma2(g, u2, K8);
                g = fma2(g, u2, K7);
                g = fma2(g, u2, K6);
                g = fma2(g, u2, K5);
                g = fma2(g, u2, K4);
                g = fma2(g, u2, K3);
                g = fma2(g, u2, K2);
                g = fma2(g, u2, K1);
                g = fma2(g, u2, K0);
                g = mul2(g, u2);                        // g = -acos(1-u)^2
                float2 gf = unpk(g);
                float w0 = __expf(gf.x);
                float w1 = __expf(gf.y);
                den[2 * i2]     += w0;
                den[2 * i2 + 1] += w1;
                wf[2 * i2]     = w0;
                wf[2 * i2 + 1] = w1;
            }
            float* wr = &Ws[(tx * 4 + j) * 132 + ty * 8];
            *(float4*)wr       = *(float4*)&wf[0];
            *(float4*)(wr + 4) = *(float4*)&wf[4];
        }
        __syncthreads();

        // o += w @ V : 4(i2) x 4(d) FFMA2 tile
#pragma unroll 8
        for (int jj = 0; jj < 64; jj++) {
            longlong2 wl0 = *(const longlong2*)&Ws[jj * 132 + ty * 8];
            longlong2 wl1 = *(const longlong2*)&Ws[jj * 132 + ty * 8 + 4];
            u64t w2[4] = { (u64t)wl0.x, (u64t)wl0.y, (u64t)wl1.x, (u64t)wl1.y };
            float4 vq = *(const float4*)&Vs[jj * 64 + tx * 4];
            u64t vd[4] = { dup2f(vq.x), dup2f(vq.y), dup2f(vq.z), dup2f(vq.w) };
#pragma unroll
            for (int i = 0; i < 4; i++)
#pragma unroll
                for (int j = 0; j < 4; j++)
                    o2[i][j] = fma2(w2[i], vd[j], o2[i][j]);
        }
    }

    // reduce den across the 16 tx lanes
#pragma unroll
    for (int i = 0; i < 8; i++) {
#pragma unroll
        for (int off = 1; off < 16; off <<= 1)
            den[i] += __shfl_xor_sync(0xffffffffu, den[i], off);
    }

    const int b = bh >> 3, h = bh & 7;
#pragma unroll
    for (int i2 = 0; i2 < 4; i2++) {
        float2 p[4];
#pragma unroll
        for (int j = 0; j < 4; j++) p[j] = unpk(o2[i2][j]);
#pragma unroll
        for (int e = 0; e < 2; e++) {
            const int i = 2 * i2 + e;
            const float inv = 1.0f / den[i];
            const int srow = i0 + ty * 8 + i;
            float4 v;
            v.x = (e ? p[0].y : p[0].x) * inv;
            v.y = (e ? p[1].y : p[1].x) * inv;
            v.z = (e ? p[2].y : p[2].x) * inv;
            v.w = (e ? p[3].y : p[3].x) * inv;
            *(float4*)&out[((size_t)(b * SEQ + srow) * DIM) + h * HD + tx * 4] = v;
        }
    }
}

// ---------------------------------------------------------------------------
// Output GEMM: out = att @ Wo + bo.  M=4096, K=512, N=1024.  FFMA2 edition.
// ---------------------------------------------------------------------------
__global__ __launch_bounds__(256, 2) void out_gemm(
    const float* __restrict__ A, const float* __restrict__ W,
    const float* __restrict__ bias, float* __restrict__ out)
{
    __shared__ __align__(16) float As[2][16][132];
    __shared__ __align__(16) float Bs[2][16][128];

    const int tid = threadIdx.x;
    const int tx = tid & 15, ty = tid >> 4;
    const int m0 = blockIdx.y * 128;
    const int n0 = blockIdx.x * 128;

    const int ar  = tid >> 2;
    const int ac4 = (tid & 3) << 2;
    const int br  = tid >> 5;
    const int bc4 = (tid & 31) << 2;

    float4 a0, a1, b0, b1;
    {
        a0 = *(const float4*)(A + (size_t)(m0 + ar)      * DIM + ac4);
        a1 = *(const float4*)(A + (size_t)(m0 + ar + 64) * DIM + ac4);
        b0 = *(const float4*)(W + (size_t)(br)     * KIN + n0 + bc4);
        b1 = *(const float4*)(W + (size_t)(br + 8) * KIN + n0 + bc4);
        As[0][ac4+0][ar] = a0.x; As[0][ac4+1][ar] = a0.y;
        As[0][ac4+2][ar] = a0.z; As[0][ac4+3][ar] = a0.w;
        As[0][ac4+0][ar+64] = a1.x; As[0][ac4+1][ar+64] = a1.y;
        As[0][ac4+2][ar+64] = a1.z; As[0][ac4+3][ar+64] = a1.w;
        *(float4*)&Bs[0][br][bc4]     = b0;
        *(float4*)&Bs[0][br + 8][bc4] = b1;
    }
    __syncthreads();

    u64t acc2[4][8];
#pragma unroll
    for (int i = 0; i < 4; i++)
#pragma unroll
        for (int j = 0; j < 8; j++) acc2[i][j] = 0ull;

    const int NIT = DIM / 16;   // 32

    for (int it = 0; it < NIT; ++it) {
        const int cur = it & 1;
        if (it + 1 < NIT) {
            const int kt = (it + 1) * 16;
            a0 = *(const float4*)(A + (size_t)(m0 + ar)      * DIM + kt + ac4);
            a1 = *(const float4*)(A + (size_t)(m0 + ar + 64) * DIM + kt + ac4);
            b0 = *(const float4*)(W + (size_t)(kt + br)     * KIN + n0 + bc4);
            b1 = *(const float4*)(W + (size_t)(kt + br + 8) * KIN + n0 + bc4);
        }
#pragma unroll
        for (int kk = 0; kk < 16; ++kk) {
            longlong2 al0 = *(const longlong2*)&As[cur][kk][ty * 8];
            longlong2 al1 = *(const longlong2*)&As[cur][kk][ty * 8 + 4];
            u64t a2[4] = { (u64t)al0.x, (u64t)al0.y, (u64t)al1.x, (u64t)al1.y };
            float bf[8];
            *(float4*)&bf[0] = *(const float4*)&Bs[cur][kk][tx * 8];
            *(float4*)&bf[4] = *(const float4*)&Bs[cur][kk][tx * 8 + 4];
            u64t bd[8];
#pragma unroll
            for (int j = 0; j < 8; j++) bd[j] = dup2f(bf[j]);
#pragma unroll
            for (int i = 0; i < 4; i++)
#pragma unroll
                for (int j = 0; j < 8; j++)
                    acc2[i][j] = fma2(a2[i], bd[j], acc2[i][j]);
        }
        if (it + 1 < NIT) {
            const int nxt = cur ^ 1;
            As[nxt][ac4+0][ar] = a0.x; As[nxt][ac4+1][ar] = a0.y;
            As[nxt][ac4+2][ar] = a0.z; As[nxt][ac4+3][ar] = a0.w;
            As[nxt][ac4+0][ar+64] = a1.x; As[nxt][ac4+1][ar+64] = a1.y;
            As[nxt][ac4+2][ar+64] = a1.z; As[nxt][ac4+3][ar+64] = a1.w;
            *(float4*)&Bs[nxt][br][bc4]     = b0;
            *(float4*)&Bs[nxt][br + 8][bc4] = b1;
        }
        __syncthreads();
    }

    float bb[8];
#pragma unroll
    for (int j = 0; j < 8; j++) bb[j] = bias[n0 + tx * 8 + j];
#pragma unroll
    for (int i2 = 0; i2 < 4; i2++) {
        float2 p[8];
#pragma unroll
        for (int j = 0; j < 8; j++) p[j] = unpk(acc2[i2][j]);
#pragma unroll
        for (int e = 0; e < 2; e++) {
            const int m = m0 + ty * 8 + 2 * i2 + e;
            float v[8];
#pragma unroll
            for (int j = 0; j < 8; j++) v[j] = (e ? p[j].y : p[j].x) + bb[j];
            float* dst = out + (size_t)m * KIN + n0 + tx * 8;
            float4 v0 = { v[0], v[1], v[2], v[3] };
            float4 v1 = { v[4], v[5], v[6], v[7] };
            *(float4*)dst       = v0;
            *(float4*)(dst + 4) = v1;
        }
    }
}

// ---------------------------------------------------------------------------
extern "C" void kernel_launch(void* const* d_in, const int* in_sizes, int n_in,
                              void* d_out, int out_size)
{
    const float* xr = (const float*)d_in[0];
    const float* xi = (const float*)d_in[1];
    const float* Wq = (const float*)d_in[2];
    const float* bq = (const float*)d_in[3];
    const float* Wk = (const float*)d_in[4];
    const float* bk = (const float*)d_in[5];
    const float* Wv = (const float*)d_in[6];
    const float* bv = (const float*)d_in[7];
    const float* Wo = (const float*)d_in[8];
    const float* bo = (const float*)d_in[9];
    float* out = (float*)d_out;

    float *Qp, *Kp, *Vp, *Ap;
    cudaGetSymbolAddress((void**)&Qp, g_Q);
    cudaGetSymbolAddress((void**)&Kp, g_K);
    cudaGetSymbolAddress((void**)&Vp, g_V);
    cudaGetSymbolAddress((void**)&Ap, g_att);

    dim3 gp(DIM / 128, MTOT / 128);          // (4, 32)
    proj_gemm<true ><<<gp, 256>>>(xr, xi, Wq, bq, Qp);
    proj_gemm<true ><<<gp, 256>>>(xr, xi, Wk, bk, Kp);
    proj_gemm<false><<<gp, 256>>>(xr, xi, Wv, bv, Vp);

    const int asmem = (64 * 132 + 64 * 68 + 64 * 64 + 64 * 132) * (int)sizeof(float); // 101376
    cudaFuncSetAttribute(attn_kernel, cudaFuncAttributeMaxDynamicSharedMemorySize, asmem);
    dim3 ga(SEQ / 128, BATCH * NH);          // (16, 16)
    attn_kernel<<<ga, 256, asmem>>>(Qp, Kp, Vp, Ap);

    dim3 go(KIN / 128, MTOT / 128);          // (8, 32)
    out_gemm<<<go, 256>>>(Ap, Wo, bo, out);
}

// round 5
// speedup vs baseline: 1.1913x; 1.1913x over previous
#include <cuda_runtime.h>
#include <cuda_bf16.h>
#include <math.h>
#include <stdint.h>

#define DIM   512
#define NH    8
#define HD    64
#define SEQ   2048
#define BATCH 2
#define MTOT  (BATCH * SEQ)   // 4096
#define KIN   (2 * DIM)       // 1024

typedef unsigned long long u64t;

// ---- packed f32x2 helpers (SASS FFMA2 path) ----
__device__ __forceinline__ u64t fma2(u64t a, u64t b, u64t c) {
    u64t d; asm("fma.rn.f32x2 %0, %1, %2, %3;" : "=l"(d) : "l"(a), "l"(b), "l"(c));
    return d;
}
__device__ __forceinline__ u64t mul2(u64t a, u64t b) {
    u64t d; asm("mul.rn.f32x2 %0, %1, %2;" : "=l"(d) : "l"(a), "l"(b));
    return d;
}
__device__ __forceinline__ u64t dup2f(float x) {
    u64t r; asm("mov.b64 %0, {%1, %1};" : "=l"(r) : "f"(x));
    return r;
}
__device__ __forceinline__ u64t pk2(float a, float b) {
    u64t r; asm("mov.b64 %0, {%1, %2};" : "=l"(r) : "f"(a), "f"(b));
    return r;
}
__device__ __forceinline__ float2 unpk(u64t v) {
    float lo, hi; asm("mov.b64 {%0, %1}, %2;" : "=f"(lo), "=f"(hi) : "l"(v));
    float2 f; f.x = lo; f.y = hi; return f;
}

// ---- bf16x2 split helpers: x = hi + lo, both bf16 ----
__device__ __forceinline__ void split2(float x, float y, uint32_t& hi, uint32_t& lo) {
    __nv_bfloat162 h;
    h.x = __float2bfloat16(x);
    h.y = __float2bfloat16(y);
    float rx = x - __bfloat162float(h.x);
    float ry = y - __bfloat162float(h.y);
    __nv_bfloat162 l;
    l.x = __float2bfloat16(rx);
    l.y = __float2bfloat16(ry);
    hi = *reinterpret_cast<uint32_t*>(&h);
    lo = *reinterpret_cast<uint32_t*>(&l);
}

// mma.sync m16n8k16 bf16, fp32 accumulate (D==C in place)
__device__ __forceinline__ void mma_bf16(float c[4], const uint32_t a[4],
                                         uint32_t b0, uint32_t b1) {
    asm volatile(
        "mma.sync.aligned.m16n8k16.row.col.f32.bf16.bf16.f32 "
        "{%0,%1,%2,%3}, {%4,%5,%6,%7}, {%8,%9}, {%0,%1,%2,%3};"
        : "+f"(c[0]), "+f"(c[1]), "+f"(c[2]), "+f"(c[3])
        : "r"(a[0]), "r"(a[1]), "r"(a[2]), "r"(a[3]), "r"(b0), "r"(b1));
}

// Scratch
__device__ float g_Q[BATCH * NH * SEQ * HD];
__device__ float g_K[BATCH * NH * SEQ * HD];
__device__ float g_V[BATCH * NH * SEQ * HD];
__device__ float g_att[MTOT * DIM];

// ---------------------------------------------------------------------------
// Projection GEMM (FFMA2, unchanged from R4 — known-good)
// ---------------------------------------------------------------------------
template<bool DO_SM>
__global__ __launch_bounds__(256, 2) void proj_gemm(
    const float* __restrict__ xr, const float* __restrict__ xi,
    const float* __restrict__ W,  const float* __restrict__ bias,
    float* __restrict__ out)
{
    __shared__ __align__(16) float As[2][16][132];
    __shared__ __align__(16) float Bs[2][16][128];

    const int tid = threadIdx.x;
    const int tx = tid & 15, ty = tid >> 4;
    const int m0 = blockIdx.y * 128;
    const int n0 = blockIdx.x * 128;

    const int ar  = tid >> 2;
    const int ac4 = (tid & 3) << 2;
    const int br  = tid >> 5;
    const int bc4 = (tid & 31) << 2;

    float4 a0, a1, b0, b1;
    {
        a0 = *(const float4*)(xr + (size_t)(m0 + ar)      * DIM + ac4);
        a1 = *(const float4*)(xr + (size_t)(m0 + ar + 64) * DIM + ac4);
        b0 = *(const float4*)(W + (size_t)(br)     * DIM + n0 + bc4);
        b1 = *(const float4*)(W + (size_t)(br + 8) * DIM + n0 + bc4);
        As[0][ac4+0][ar] = a0.x; As[0][ac4+1][ar] = a0.y;
        As[0][ac4+2][ar] = a0.z; As[0][ac4+3][ar] = a0.w;
        As[0][ac4+0][ar+64] = a1.x; As[0][ac4+1][ar+64] = a1.y;
        As[0][ac4+2][ar+64] = a1.z; As[0][ac4+3][ar+64] = a1.w;
        *(float4*)&Bs[0][br][bc4]     = b0;
        *(float4*)&Bs[0][br + 8][bc4] = b1;
    }
    __syncthreads();

    u64t acc2[4][8];
#pragma unroll
    for (int i = 0; i < 4; i++)
#pragma unroll
        for (int j = 0; j < 8; j++) acc2[i][j] = 0ull;

    const int NIT = KIN / 16;

    for (int it = 0; it < NIT; ++it) {
        const int cur = it & 1;
        if (it + 1 < NIT) {
            const int kt = (it + 1) * 16;
            const float* base = (kt < DIM) ? xr : xi;
            const int ko = (kt < DIM) ? kt : (kt - DIM);
            a0 = *(const float4*)(base + (size_t)(m0 + ar)      * DIM + ko + ac4);
            a1 = *(const float4*)(base + (size_t)(m0 + ar + 64) * DIM + ko + ac4);
            b0 = *(const float4*)(W + (size_t)(kt + br)     * DIM + n0 + bc4);
            b1 = *(const float4*)(W + (size_t)(kt + br + 8) * DIM + n0 + bc4);
        }
#pragma unroll
        for (int kk = 0; kk < 16; ++kk) {
            longlong2 al0 = *(const longlong2*)&As[cur][kk][ty * 8];
            longlong2 al1 = *(const longlong2*)&As[cur][kk][ty * 8 + 4];
            u64t a2[4] = { (u64t)al0.x, (u64t)al0.y, (u64t)al1.x, (u64t)al1.y };
            float bf[8];
            *(float4*)&bf[0] = *(const float4*)&Bs[cur][kk][tx * 8];
            *(float4*)&bf[4] = *(const float4*)&Bs[cur][kk][tx * 8 + 4];
            u64t bd[8];
#pragma unroll
            for (int j = 0; j < 8; j++) bd[j] = dup2f(bf[j]);
#pragma unroll
            for (int i = 0; i < 4; i++)
#pragma unroll
                for (int j = 0; j < 8; j++)
                    acc2[i][j] = fma2(a2[i], bd[j], acc2[i][j]);
        }
        if (it + 1 < NIT) {
            const int nxt = cur ^ 1;
            As[nxt][ac4+0][ar] = a0.x; As[nxt][ac4+1][ar] = a0.y;
            As[nxt][ac4+2][ar] = a0.z; As[nxt][ac4+3][ar] = a0.w;
            As[nxt][ac4+0][ar+64] = a1.x; As[nxt][ac4+1][ar+64] = a1.y;
            As[nxt][ac4+2][ar+64] = a1.z; As[nxt][ac4+3][ar+64] = a1.w;
            *(float4*)&Bs[nxt][br][bc4]     = b0;
            *(float4*)&Bs[nxt][br + 8][bc4] = b1;
        }
        __syncthreads();
    }

    float bb[8];
#pragma unroll
    for (int j = 0; j < 8; j++) bb[j] = bias[n0 + tx * 8 + j];
    const int h  = (n0 >> 6) + (tx >> 3);
    const int d0 = (tx & 7) * 8;

#pragma unroll
    for (int i2 = 0; i2 < 4; i2++) {
        float2 p[8];
#pragma unroll
        for (int j = 0; j < 8; j++) p[j] = unpk(acc2[i2][j]);
#pragma unroll
        for (int e = 0; e < 2; e++) {
            const int i = 2 * i2 + e;
            const int m = m0 + ty * 8 + i;
            const int b = m >> 11;
            const int s = m & (SEQ - 1);
            float v[8];
#pragma unroll
            for (int j = 0; j < 8; j++) v[j] = (e ? p[j].y : p[j].x) + bb[j];
            if (DO_SM) {
                float mx = v[0];
#pragma unroll
                for (int j = 1; j < 8; j++) mx = fmaxf(mx, v[j]);
#pragma unroll
                for (int off = 1; off < 8; off <<= 1)
                    mx = fmaxf(mx, __shfl_xor_sync(0xffffffffu, mx, off));
                float sum = 0.0f;
#pragma unroll
                for (int j = 0; j < 8; j++) { v[j] = __expf(v[j] - mx); sum += v[j]; }
#pragma unroll
                for (int off = 1; off < 8; off <<= 1)
                    sum += __shfl_xor_sync(0xffffffffu, sum, off);
                const float inv = 1.0f / sum;
#pragma unroll
                for (int j = 0; j < 8; j++) v[j] = sqrtf(v[j] * inv);
            }
            float* dst = out + ((size_t)(b * NH + h) * SEQ + s) * HD + d0;
            float4 v0 = { v[0], v[1], v[2], v[3] };
            float4 v1 = { v[4], v[5], v[6], v[7] };
            *(float4*)dst       = v0;
            *(float4*)(dst + 4) = v1;
        }
    }
}

// ---------------------------------------------------------------------------
// Attention via mma.sync bf16x2-split (3-term: hi*hi + lo*hi + hi*lo).
// Block: 128 threads = 4 warps; warp w owns 16 i-rows of a 64-row i-tile.
// Per 64-wide j-tile:
//   bc (16x64) = sp_i . sq_j   via m16n8k16, sp A-frags register-resident
//   w = exp(-acos(1-u)^2) (poly), split to bf16 pair IN REGISTERS:
//       bc C-frag layout == A-frag layout of the w@V MMA (no smem round trip)
//   o (16x64) += w @ V        via m16n8k16, accumulated in C-frags across j
// sq/V tiles staged in smem in FRAGMENT ORDER -> B-frags are 1 LDS.64 each.
// ---------------------------------------------------------------------------
__global__ __launch_bounds__(128) void attn_tc(
    const float* __restrict__ sp, const float* __restrict__ sq,
    const float* __restrict__ V,  float* __restrict__ out)
{
    // [type(hi/lo)][group(jg or dg)][kstep][lane*2 + reg]
    __shared__ uint32_t Qs[2][8][4][64];
    __shared__ uint32_t Vs[2][8][4][64];

    const int tid  = threadIdx.x;
    const int warp = tid >> 5;
    const int lane = tid & 31;
    const int r    = lane >> 2;    // 0..7
    const int cq   = lane & 3;     // 0..3
    const int bh   = blockIdx.y;
    const int i0   = blockIdx.x * 64;

    const float* spb = sp + (size_t)bh * SEQ * HD;
    const float* sqb = sq + (size_t)bh * SEQ * HD;
    const float* Vb  = V  + (size_t)bh * SEQ * HD;

    // --- preload sp A-frags (row-major m16 x k16 per kstep), bf16x2-split ---
    uint32_t Ahi[4][4], Alo[4][4];
    const int row0 = i0 + warp * 16 + r;
    const int row1 = row0 + 8;
#pragma unroll
    for (int ks = 0; ks < 4; ks++) {
        float2 v00 = *(const float2*)(spb + (size_t)row0 * HD + ks * 16 + 2 * cq);
        float2 v01 = *(const float2*)(spb + (size_t)row0 * HD + ks * 16 + 2 * cq + 8);
        float2 v10 = *(const float2*)(spb + (size_t)row1 * HD + ks * 16 + 2 * cq);
        float2 v11 = *(const float2*)(spb + (size_t)row1 * HD + ks * 16 + 2 * cq + 8);
        split2(v00.x, v00.y, Ahi[ks][0], Alo[ks][0]);   // a0: row r,   cols 2c,2c+1
        split2(v10.x, v10.y, Ahi[ks][1], Alo[ks][1]);   // a1: row r+8, cols 2c,2c+1
        split2(v01.x, v01.y, Ahi[ks][2], Alo[ks][2]);   // a2: row r,   cols 2c+8,+9
        split2(v11.x, v11.y, Ahi[ks][3], Alo[ks][3]);   // a3: row r+8, cols 2c+8,+9
    }

    // negated acos^2 series coefficients (packed f32x2)
    const u64t K9 = dup2f(-2.0705e-4f);
    const u64t K8 = dup2f(-2.6002e-4f);
    const u64t K7 = dup2f(-6.2160e-4f);
    const u64t K6 = dup2f(-1.52229e-3f);
    const u64t K5 = dup2f(-3.84800e-3f);
    const u64t K4 = dup2f(-1.015873e-2f);
    const u64t K3 = dup2f(-2.8571429e-2f);
    const u64t K2 = dup2f(-8.8888889e-2f);
    const u64t K1 = dup2f(-0.33333333f);
    const u64t K0 = dup2f(-2.0f);
    const u64t CM1 = dup2f(-1.0f);
    const u64t CP1 = dup2f(1.0f);

    float o[8][4];
#pragma unroll
    for (int dg = 0; dg < 8; dg++)
#pragma unroll
        for (int e = 0; e < 4; e++) o[dg][e] = 0.0f;
    float den0 = 0.0f, den1 = 0.0f;

    for (int j0 = 0; j0 < SEQ; j0 += 64) {
        __syncthreads();   // prior j-tile's MMA reads of Qs/Vs done

        // --- stage sq tile (64j x 64k) into frag-order: B(k,n=j) ---
        {
            const int j  = tid >> 1;              // 0..63
            const int cb = (tid & 1) * 32;
            const int jg = j >> 3, jl = j & 7;
            const float* src = sqb + (size_t)(j0 + j) * HD + cb;
#pragma unroll
            for (int q = 0; q < 8; q++) {
                float4 v = *(const float4*)(src + 4 * q);
                const int k0 = cb + 4 * q;
                // pair (k0, k0+1)
                {
                    int ks = k0 >> 4, p = (k0 & 15) >> 1;
                    int idx = ((jl << 2) | (p & 3)) * 2 + (p >> 2);
                    uint32_t hi, lo; split2(v.x, v.y, hi, lo);
                    Qs[0][jg][ks][idx] = hi; Qs[1][jg][ks][idx] = lo;
                }
                // pair (k0+2, k0+3)
                {
                    int k2 = k0 + 2;
                    int ks = k2 >> 4, p = (k2 & 15) >> 1;
                    int idx = ((jl << 2) | (p & 3)) * 2 + (p >> 2);
                    uint32_t hi, lo; split2(v.z, v.w, hi, lo);
                    Qs[0][jg][ks][idx] = hi; Qs[1][jg][ks][idx] = lo;
                }
            }
        }
        // --- stage V tile (64j x 64d) into frag-order: B(k=j, n=d) ---
        {
            const int jp = tid >> 2;              // 0..31  (j pair 2jp, 2jp+1)
            const int js = jp >> 3, p = jp & 7;
            const int reg = p >> 2, pc = p & 3;
            const int db = (tid & 3) * 16;
            const float* s0 = Vb + (size_t)(j0 + 2 * jp) * HD;
            const float* s1 = s0 + HD;
#pragma unroll
            for (int q = 0; q < 4; q++) {
                float4 a = *(const float4*)(s0 + db + 4 * q);
                float4 b = *(const float4*)(s1 + db + 4 * q);
                float av[4] = { a.x, a.y, a.z, a.w };
                float bv[4] = { b.x, b.y, b.z, b.w };
#pragma unroll
                for (int e = 0; e < 4; e++) {
                    const int d = db + 4 * q + e;
                    const int dg = d >> 3;
                    const int idx = (((d & 7) << 2) | pc) * 2 + reg;
                    uint32_t hi, lo; split2(av[e], bv[e], hi, lo);
                    Vs[0][dg][js][idx] = hi; Vs[1][dg][js][idx] = lo;
                }
            }
        }
        __syncthreads();

        // --- bc MMAs + transform -> register-resident w A-frags ---
        uint32_t Whi[4][4], Wlo[4][4];
#pragma unroll
        for (int jg = 0; jg < 8; jg++) {
            float acc[4] = { 0.0f, 0.0f, 0.0f, 0.0f };
#pragma unroll
            for (int ks = 0; ks < 4; ks++) {
                uint2 bhi = *(const uint2*)&Qs[0][jg][ks][lane * 2];
                uint2 blo = *(const uint2*)&Qs[1][jg][ks][lane * 2];
                mma_bf16(acc, Ahi[ks], bhi.x, bhi.y);
                mma_bf16(acc, Alo[ks], bhi.x, bhi.y);
                mma_bf16(acc, Ahi[ks], blo.x, blo.y);
            }
            // u = 1 - bc;  g = -acos(1-u)^2 (deg-10 series);  w = exp(g)
            u64t ua = fma2(pk2(acc[0], acc[1]), CM1, CP1);
            u64t ub = fma2(pk2(acc[2], acc[3]), CM1, CP1);
            u64t ga = K9, gb = K9;
            ga = fma2(ga, ua, K8);  gb = fma2(gb, ub, K8);
            ga = fma2(ga, ua, K7);  gb = fma2(gb, ub, K7);
            ga = fma2(ga, ua, K6);  gb = fma2(gb, ub, K6);
            ga = fma2(ga, ua, K5);  gb = fma2(gb, ub, K5);
            ga = fma2(ga, ua, K4);  gb = fma2(gb, ub, K4);
            ga = fma2(ga, ua, K3);  gb = fma2(gb, ub, K3);
            ga = fma2(ga, ua, K2);  gb = fma2(gb, ub, K2);
            ga = fma2(ga, ua, K1);  gb = fma2(gb, ub, K1);
            ga = fma2(ga, ua, K0);  gb = fma2(gb, ub, K0);
            ga = mul2(ga, ua);      gb = mul2(gb, ub);
            float2 gA = unpk(ga), gB = unpk(gb);
            float w0 = __expf(gA.x), w1 = __expf(gA.y);
            float w2 = __expf(gB.x), w3 = __expf(gB.y);
            den0 += w0 + w1;
            den1 += w2 + w3;
            // bc C-frag == A-frag of w@V: jg even -> a0/a1, jg odd -> a2/a3
            const int ks = jg >> 1, up = (jg & 1) << 1;
            split2(w0, w1, Whi[ks][up + 0], Wlo[ks][up + 0]);   // row r
            split2(w2, w3, Whi[ks][up + 1], Wlo[ks][up + 1]);   // row r+8
        }

        // --- o += w @ V ---
#pragma unroll
        for (int dg = 0; dg < 8; dg++) {
#pragma unroll
            for (int js = 0; js < 4; js++) {
                uint2 vhi = *(const uint2*)&Vs[0][dg][js][lane * 2];
                uint2 vlo = *(const uint2*)&Vs[1][dg][js][lane * 2];
                mma_bf16(o[dg], Whi[js], vhi.x, vhi.y);
                mma_bf16(o[dg], Wlo[js], vhi.x, vhi.y);
                mma_bf16(o[dg], Whi[js], vlo.x, vlo.y);
            }
        }
    }

    // --- epilogue: den reduce within quad (lanes share row), divide, store ---
    den0 += __shfl_xor_sync(0xffffffffu, den0, 1);
    den0 += __shfl_xor_sync(0xffffffffu, den0, 2);
    den1 += __shfl_xor_sync(0xffffffffu, den1, 1);
    den1 += __shfl_xor_sync(0xffffffffu, den1, 2);
    const float inv0 = 1.0f / den0;
    const float inv1 = 1.0f / den1;

    const int b = bh >> 3, hh = bh & 7;
    float* out0 = out + (size_t)(b * SEQ + row0) * DIM + hh * HD;
    float* out1 = out + (size_t)(b * SEQ + row1) * DIM + hh * HD;
#pragma unroll
    for (int dg = 0; dg < 8; dg++) {
        float2 t0 = { o[dg][0] * inv0, o[dg][1] * inv0 };
        float2 t1 = { o[dg][2] * inv1, o[dg][3] * inv1 };
        *(float2*)(out0 + dg * 8 + 2 * cq) = t0;
        *(float2*)(out1 + dg * 8 + 2 * cq) = t1;
    }
}

// ---------------------------------------------------------------------------
// Output GEMM (FFMA2, unchanged from R4)
// ---------------------------------------------------------------------------
__global__ __launch_bounds__(256, 2) void out_gemm(
    const float* __restrict__ A, const float* __restrict__ W,
    const float* __restrict__ bias, float* __restrict__ out)
{
    __shared__ __align__(16) float As[2][16][132];
    __shared__ __align__(16) float Bs[2][16][128];

    const int tid = threadIdx.x;
    const int tx = tid & 15, ty = tid >> 4;
    const int m0 = blockIdx.y * 128;
    const int n0 = blockIdx.x * 128;

    const int ar  = tid >> 2;
    const int ac4 = (tid & 3) << 2;
    const int br  = tid >> 5;
    const int bc4 = (tid & 31) << 2;

    float4 a0, a1, b0, b1;
    {
        a0 = *(const float4*)(A + (size_t)(m0 + ar)      * DIM + ac4);
        a1 = *(const float4*)(A + (size_t)(m0 + ar + 64) * DIM + ac4);
        b0 = *(const float4*)(W + (size_t)(br)     * KIN + n0 + bc4);
        b1 = *(const float4*)(W + (size_t)(br + 8) * KIN + n0 + bc4);
        As[0][ac4+0][ar] = a0.x; As[0][ac4+1][ar] = a0.y;
        As[0][ac4+2][ar] = a0.z; As[0][ac4+3][ar] = a0.w;
        As[0][ac4+0][ar+64] = a1.x; As[0][ac4+1][ar+64] = a1.y;
        As[0][ac4+2][ar+64] = a1.z; As[0][ac4+3][ar+64] = a1.w;
        *(float4*)&Bs[0][br][bc4]     = b0;
        *(float4*)&Bs[0][br + 8][bc4] = b1;
    }
    __syncthreads();

    u64t acc2[4][8];
#pragma unroll
    for (int i = 0; i < 4; i++)
#pragma unroll
        for (int j = 0; j < 8; j++) acc2[i][j] = 0ull;

    const int NIT = DIM / 16;

    for (int it = 0; it < NIT; ++it) {
        const int cur = it & 1;
        if (it + 1 < NIT) {
            const int kt = (it + 1) * 16;
            a0 = *(const float4*)(A + (size_t)(m0 + ar)      * DIM + kt + ac4);
            a1 = *(const float4*)(A + (size_t)(m0 + ar + 64) * DIM + kt + ac4);
            b0 = *(const float4*)(W + (size_t)(kt + br)     * KIN + n0 + bc4);
            b1 = *(const float4*)(W + (size_t)(kt + br + 8) * KIN + n0 + bc4);
        }
#pragma unroll
        for (int kk = 0; kk < 16; ++kk) {
            longlong2 al0 = *(const longlong2*)&As[cur][kk][ty * 8];
            longlong2 al1 = *(const longlong2*)&As[cur][kk][ty * 8 + 4];
            u64t a2[4] = { (u64t)al0.x, (u64t)al0.y, (u64t)al1.x, (u64t)al1.y };
            float bf[8];
            *(float4*)&bf[0] = *(const float4*)&Bs[cur][kk][tx * 8];
            *(float4*)&bf[4] = *(const float4*)&Bs[cur][kk][tx * 8 + 4];
            u64t bd[8];
#pragma unroll
            for (int j = 0; j < 8; j++) bd[j] = dup2f(bf[j]);
#pragma unroll
            for (int i = 0; i < 4; i++)
#pragma unroll
                for (int j = 0; j < 8; j++)
                    acc2[i][j] = fma2(a2[i], bd[j], acc2[i][j]);
        }
        if (it + 1 < NIT) {
            const int nxt = cur ^ 1;
            As[nxt][ac4+0][ar] = a0.x; As[nxt][ac4+1][ar] = a0.y;
            As[nxt][ac4+2][ar] = a0.z; As[nxt][ac4+3][ar] = a0.w;
            As[nxt][ac4+0][ar+64] = a1.x; As[nxt][ac4+1][ar+64] = a1.y;
            As[nxt][ac4+2][ar+64] = a1.z; As[nxt][ac4+3][ar+64] = a1.w;
            *(float4*)&Bs[nxt][br][bc4]     = b0;
            *(float4*)&Bs[nxt][br + 8][bc4] = b1;
        }
        __syncthreads();
    }

    float bb[8];
#pragma unroll
    for (int j = 0; j < 8; j++) bb[j] = bias[n0 + tx * 8 + j];
#pragma unroll
    for (int i2 = 0; i2 < 4; i2++) {
        float2 p[8];
#pragma unroll
        for (int j = 0; j < 8; j++) p[j] = unpk(acc2[i2][j]);
#pragma unroll
        for (int e = 0; e < 2; e++) {
            const int m = m0 + ty * 8 + 2 * i2 + e;
            float v[8];
#pragma unroll
            for (int j = 0; j < 8; j++) v[j] = (e ? p[j].y : p[j].x) + bb[j];
            float* dst = out + (size_t)m * KIN + n0 + tx * 8;
            float4 v0 = { v[0], v[1], v[2], v[3] };
            float4 v1 = { v[4], v[5], v[6], v[7] };
            *(float4*)dst       = v0;
            *(float4*)(dst + 4) = v1;
        }
    }
}

// ---------------------------------------------------------------------------
extern "C" void kernel_launch(void* const* d_in, const int* in_sizes, int n_in,
                              void* d_out, int out_size)
{
    const float* xr = (const float*)d_in[0];
    const float* xi = (const float*)d_in[1];
    const float* Wq = (const float*)d_in[2];
    const float* bq = (const float*)d_in[3];
    const float* Wk = (const float*)d_in[4];
    const float* bk = (const float*)d_in[5];
    const float* Wv = (const float*)d_in[6];
    const float* bv = (const float*)d_in[7];
    const float* Wo = (const float*)d_in[8];
    const float* bo = (const float*)d_in[9];
    float* out = (float*)d_out;

    float *Qp, *Kp, *Vp, *Ap;
    cudaGetSymbolAddress((void**)&Qp, g_Q);
    cudaGetSymbolAddress((void**)&Kp, g_K);
    cudaGetSymbolAddress((void**)&Vp, g_V);
    cudaGetSymbolAddress((void**)&Ap, g_att);

    dim3 gp(DIM / 128, MTOT / 128);          // (4, 32)
    proj_gemm<true ><<<gp, 256>>>(xr, xi, Wq, bq, Qp);
    proj_gemm<true ><<<gp, 256>>>(xr, xi, Wk, bk, Kp);
    proj_gemm<false><<<gp, 256>>>(xr, xi, Wv, bv, Vp);

    dim3 ga(SEQ / 64, BATCH * NH);           // (32, 16)
    attn_tc<<<ga, 128>>>(Qp, Kp, Vp, Ap);

    dim3 go(KIN / 128, MTOT / 128);          // (8, 32)
    out_gemm<<<go, 256>>>(Ap, Wo, bo, out);
}

// round 6
// speedup vs baseline: 1.2378x; 1.0391x over previous
#include <cuda_runtime.h>
#include <cuda_bf16.h>
#include <math.h>
#include <stdint.h>

#define DIM   512
#define NH    8
#define HD    64
#define SEQ   2048
#define BATCH 2
#define MTOT  (BATCH * SEQ)   // 4096
#define KIN   (2 * DIM)       // 1024

typedef unsigned long long u64t;

// ---- packed f32x2 helpers ----
__device__ __forceinline__ u64t fma2(u64t a, u64t b, u64t c) {
    u64t d; asm("fma.rn.f32x2 %0, %1, %2, %3;" : "=l"(d) : "l"(a), "l"(b), "l"(c));
    return d;
}
__device__ __forceinline__ u64t mul2(u64t a, u64t b) {
    u64t d; asm("mul.rn.f32x2 %0, %1, %2;" : "=l"(d) : "l"(a), "l"(b));
    return d;
}
__device__ __forceinline__ u64t dup2f(float x) {
    u64t r; asm("mov.b64 %0, {%1, %1};" : "=l"(r) : "f"(x));
    return r;
}
__device__ __forceinline__ u64t pk2(float a, float b) {
    u64t r; asm("mov.b64 %0, {%1, %2};" : "=l"(r) : "f"(a), "f"(b));
    return r;
}
__device__ __forceinline__ float2 unpk(u64t v) {
    float lo, hi; asm("mov.b64 {%0, %1}, %2;" : "=f"(lo), "=f"(hi) : "l"(v));
    float2 f; f.x = lo; f.y = hi; return f;
}

// ---- bf16x2 split: (x,y) -> hi pair + lo pair, x = hi + lo exactly in bf16+bf16 ----
__device__ __forceinline__ void split2(float x, float y, uint32_t& hi, uint32_t& lo) {
    __nv_bfloat162 h;
    h.x = __float2bfloat16(x);
    h.y = __float2bfloat16(y);
    float rx = x - __bfloat162float(h.x);
    float ry = y - __bfloat162float(h.y);
    __nv_bfloat162 l;
    l.x = __float2bfloat16(rx);
    l.y = __float2bfloat16(ry);
    hi = *reinterpret_cast<uint32_t*>(&h);
    lo = *reinterpret_cast<uint32_t*>(&l);
}

// mma.sync m16n8k16 bf16, fp32 accumulate (D==C in place)
__device__ __forceinline__ void mma_bf16(float c[4], const uint32_t a[4],
                                         uint32_t b0, uint32_t b1) {
    asm volatile(
        "mma.sync.aligned.m16n8k16.row.col.f32.bf16.bf16.f32 "
        "{%0,%1,%2,%3}, {%4,%5,%6,%7}, {%8,%9}, {%0,%1,%2,%3};"
        : "+f"(c[0]), "+f"(c[1]), "+f"(c[2]), "+f"(c[3])
        : "r"(a[0]), "r"(a[1]), "r"(a[2]), "r"(a[3]), "r"(b0), "r"(b1));
}
__device__ __forceinline__ void mma_bf16_u4(float c[4], uint4 a,
                                            uint32_t b0, uint32_t b1) {
    uint32_t ar[4] = { a.x, a.y, a.z, a.w };
    mma_bf16(c, ar, b0, b1);
}

// Scratch
__device__ float g_Q[BATCH * NH * SEQ * HD];
__device__ float g_K[BATCH * NH * SEQ * HD];
__device__ float g_V[BATCH * NH * SEQ * HD];
__device__ float g_att[MTOT * DIM];

// ---------------------------------------------------------------------------
// Tensor-core GEMM via bf16x2-split mma.sync (3-term).
// D[M=4096, N] = A[M, KD] @ W[KD, N] + bias.
// Block 256 thr (8 warps), tile 128m x 128n, K staged in 32-wide double-
// buffered chunks IN FRAGMENT ORDER. Warp (wm=warp>>1, wn=warp&1) owns
// 32m x 64n = 2 m-frags x 8 n-groups.
// PROJ: A = concat(A0=xr, A1=xi) (KD=1024), epilogue -> [b,h,s,d] layout with
//       optional fused sqrt(softmax) over head dim (do_sm).
// else: A = A0 row-major (stride KD), plain row-major output (ld = ldout).
// ---------------------------------------------------------------------------
template<int KD, bool PROJ>
__global__ __launch_bounds__(256) void mma_gemm(
    const float* __restrict__ A0, const float* __restrict__ A1,
    const float* __restrict__ W, int ldb,
    const float* __restrict__ bias, float* __restrict__ out,
    int ldout, int do_sm)
{
    // Asm: [buf][hi/lo][mg(8)][ks(2)][128]   (A-frag: uint4 at lane*4)
    // Bsm: [buf][hi/lo][ng(16)][ks(2)][64]   (B-frag: uint2 at lane*2)
    extern __shared__ uint32_t smem_u[];
    uint32_t* Asm = smem_u;            // 2*2*8*2*128 = 8192 u32
    uint32_t* Bsm = smem_u + 8192;     // 2*2*16*2*64 = 8192 u32
#define ASMI(bf, t, mg, ks, ix) Asm[(bf) * 4096 + (t) * 2048 + (mg) * 256 + (ks) * 128 + (ix)]
#define BSMI(bf, t, ng, ks, ix) Bsm[(bf) * 4096 + (t) * 2048 + (ng) * 128 + (ks) * 64 + (ix)]

    const int tid  = threadIdx.x;
    const int warp = tid >> 5;
    const int lane = tid & 31;
    const int wm = warp >> 1, wn = warp & 1;
    const int g  = lane >> 2, tg = lane & 3;
    const int m0 = blockIdx.y * 128;
    const int n0 = blockIdx.x * 128;

    // staging thread mapping
    const int arow = tid >> 1;            // 0..127
    const int akq  = (tid & 1) * 16;      // 0 or 16
    const int amg  = arow >> 4;
    const int alb  = (arow & 7) * 4;
    const int arr  = (arow & 15) >> 3;
    const int bkp  = tid >> 4;            // 0..15 (k pair)
    const int bn8  = (tid & 15) * 8;
    const int btg  = bkp & 3;
    const int breg = (bkp >> 2) & 1;
    const int bks  = bkp >> 3;

    float af[16];
    float br0[8], br1[8];

    // ---- global load of chunk k0 into regs ----
    auto load_chunk = [&](int k0) {
        const float* ab;
        if (PROJ) {
            ab = ((k0 < DIM) ? A0 : A1) + (size_t)(m0 + arow) * DIM + (k0 & (DIM - 1)) + akq;
        } else {
            ab = A0 + (size_t)(m0 + arow) * KD + k0 + akq;
        }
#pragma unroll
        for (int q = 0; q < 4; q++)
            *(float4*)&af[4 * q] = *(const float4*)(ab + 4 * q);
        const float* bb0 = W + (size_t)(k0 + 2 * bkp) * ldb + n0 + bn8;
        const float* bb1 = bb0 + ldb;
        *(float4*)&br0[0] = *(const float4*)(bb0);
        *(float4*)&br0[4] = *(const float4*)(bb0 + 4);
        *(float4*)&br1[0] = *(const float4*)(bb1);
        *(float4*)&br1[4] = *(const float4*)(bb1 + 4);
    };

    // ---- split + store regs into smem buffer bf (frag order) ----
    auto store_chunk = [&](int bf) {
#pragma unroll
        for (int q = 0; q < 4; q++) {
#pragma unroll
            for (int e = 0; e < 4; e += 2) {
                const int k  = akq + 4 * q + e;       // even
                const int kl = k & 31;
                const int ks = kl >> 4;
                const int p  = (kl & 15) >> 1;
                const int idx = (alb + (p & 3)) * 4 + ((p >> 2) * 2 + arr);
                uint32_t hi, lo;
                split2(af[4 * q + e], af[4 * q + e + 1], hi, lo);
                ASMI(bf, 0, amg, ks, idx) = hi;
                ASMI(bf, 1, amg, ks, idx) = lo;
            }
        }
#pragma unroll
        for (int e = 0; e < 8; e++) {
            const int n  = bn8 + e;
            const int ng = n >> 3;
            const int idx = ((n & 7) * 4 + btg) * 2 + breg;
            uint32_t hi, lo;
            split2(br0[e], br1[e], hi, lo);
            BSMI(bf, 0, ng, bks, idx) = hi;
            BSMI(bf, 1, ng, bks, idx) = lo;
        }
    };

    float C[2][8][4];
#pragma unroll
    for (int mg = 0; mg < 2; mg++)
#pragma unroll
        for (int ng = 0; ng < 8; ng++)
#pragma unroll
            for (int e = 0; e < 4; e++) C[mg][ng][e] = 0.0f;

    const int NCH = KD / 32;
    load_chunk(0);
    store_chunk(0);
    __syncthreads();

    for (int ch = 0; ch < NCH; ++ch) {
        const int cur = ch & 1;
        if (ch + 1 < NCH) load_chunk((ch + 1) * 32);
#pragma unroll
        for (int ks = 0; ks < 2; ks++) {
            uint4 ah0 = *(const uint4*)&ASMI(cur, 0, wm * 2 + 0, ks, lane * 4);
            uint4 al0 = *(const uint4*)&ASMI(cur, 1, wm * 2 + 0, ks, lane * 4);
            uint4 ah1 = *(const uint4*)&ASMI(cur, 0, wm * 2 + 1, ks, lane * 4);
            uint4 al1 = *(const uint4*)&ASMI(cur, 1, wm * 2 + 1, ks, lane * 4);
#pragma unroll
            for (int ng = 0; ng < 8; ng++) {
                uint2 bh = *(const uint2*)&BSMI(cur, 0, wn * 8 + ng, ks, lane * 2);
                uint2 bl = *(const uint2*)&BSMI(cur, 1, wn * 8 + ng, ks, lane * 2);
                mma_bf16_u4(C[0][ng], ah0, bh.x, bh.y);
                mma_bf16_u4(C[0][ng], al0, bh.x, bh.y);
                mma_bf16_u4(C[0][ng], ah0, bl.x, bl.y);
                mma_bf16_u4(C[1][ng], ah1, bh.x, bh.y);
                mma_bf16_u4(C[1][ng], al1, bh.x, bh.y);
                mma_bf16_u4(C[1][ng], ah1, bl.x, bl.y);
            }
        }
        if (ch + 1 < NCH) store_chunk(cur ^ 1);
        __syncthreads();
    }

    // ---- epilogue ----
    float bb[8][2];
#pragma unroll
    for (int ng = 0; ng < 8; ng++) {
        const int n = n0 + wn * 64 + ng * 8 + 2 * tg;
        bb[ng][0] = bias[n];
        bb[ng][1] = bias[n + 1];
    }

    if (PROJ) {
        const int h = (n0 + wn * 64) >> 6;
#pragma unroll
        for (int mg = 0; mg < 2; mg++) {
#pragma unroll
            for (int half = 0; half < 2; half++) {
                const int m = m0 + wm * 32 + mg * 16 + g + half * 8;
                const int b = m >> 11;
                const int s = m & (SEQ - 1);
                float v[16];
#pragma unroll
                for (int ng = 0; ng < 8; ng++) {
                    v[2 * ng]     = C[mg][ng][half * 2]     + bb[ng][0];
                    v[2 * ng + 1] = C[mg][ng][half * 2 + 1] + bb[ng][1];
                }
                if (do_sm) {
                    float mx = v[0];
#pragma unroll
                    for (int e = 1; e < 16; e++) mx = fmaxf(mx, v[e]);
                    mx = fmaxf(mx, __shfl_xor_sync(0xffffffffu, mx, 1));
                    mx = fmaxf(mx, __shfl_xor_sync(0xffffffffu, mx, 2));
                    float sum = 0.0f;
#pragma unroll
                    for (int e = 0; e < 16; e++) { v[e] = __expf(v[e] - mx); sum += v[e]; }
                    sum += __shfl_xor_sync(0xffffffffu, sum, 1);
                    sum += __shfl_xor_sync(0xffffffffu, sum, 2);
                    const float inv = 1.0f / sum;
#pragma unroll
                    for (int e = 0; e < 16; e++) v[e] = sqrtf(v[e] * inv);
                }
                float* dst = out + ((size_t)(b * NH + h) * SEQ + s) * HD;
#pragma unroll
                for (int ng = 0; ng < 8; ng++) {
                    float2 t = { v[2 * ng], v[2 * ng + 1] };
                    *(float2*)(dst + ng * 8 + 2 * tg) = t;
                }
            }
        }
    } else {
#pragma unroll
        for (int mg = 0; mg < 2; mg++) {
#pragma unroll
            for (int half = 0; half < 2; half++) {
                const int m = m0 + wm * 32 + mg * 16 + g + half * 8;
                float* dst = out + (size_t)m * ldout + n0 + wn * 64;
#pragma unroll
                for (int ng = 0; ng < 8; ng++) {
                    float2 t = { C[mg][ng][half * 2]     + bb[ng][0],
                                 C[mg][ng][half * 2 + 1] + bb[ng][1] };
                    *(float2*)(dst + ng * 8 + 2 * tg) = t;
                }
            }
        }
    }
#undef ASMI
#undef BSMI
}

// ---------------------------------------------------------------------------
// Attention via mma.sync bf16x2-split (unchanged from R5 — known-good).
// ---------------------------------------------------------------------------
__global__ __launch_bounds__(128) void attn_tc(
    const float* __restrict__ sp, const float* __restrict__ sq,
    const float* __restrict__ V,  float* __restrict__ out)
{
    __shared__ uint32_t Qs[2][8][4][64];
    __shared__ uint32_t Vs[2][8][4][64];

    const int tid  = threadIdx.x;
    const int warp = tid >> 5;
    const int lane = tid & 31;
    const int r    = lane >> 2;
    const int cq   = lane & 3;
    const int bh   = blockIdx.y;
    const int i0   = blockIdx.x * 64;

    const float* spb = sp + (size_t)bh * SEQ * HD;
    const float* sqb = sq + (size_t)bh * SEQ * HD;
    const float* Vb  = V  + (size_t)bh * SEQ * HD;

    uint32_t Ahi[4][4], Alo[4][4];
    const int row0 = i0 + warp * 16 + r;
    const int row1 = row0 + 8;
#pragma unroll
    for (int ks = 0; ks < 4; ks++) {
        float2 v00 = *(const float2*)(spb + (size_t)row0 * HD + ks * 16 + 2 * cq);
        float2 v01 = *(const float2*)(spb + (size_t)row0 * HD + ks * 16 + 2 * cq + 8);
        float2 v10 = *(const float2*)(spb + (size_t)row1 * HD + ks * 16 + 2 * cq);
        float2 v11 = *(const float2*)(spb + (size_t)row1 * HD + ks * 16 + 2 * cq + 8);
        split2(v00.x, v00.y, Ahi[ks][0], Alo[ks][0]);
        split2(v10.x, v10.y, Ahi[ks][1], Alo[ks][1]);
        split2(v01.x, v01.y, Ahi[ks][2], Alo[ks][2]);
        split2(v11.x, v11.y, Ahi[ks][3], Alo[ks][3]);
    }

    const u64t K9 = dup2f(-2.0705e-4f);
    const u64t K8 = dup2f(-2.6002e-4f);
    const u64t K7 = dup2f(-6.2160e-4f);
    const u64t K6 = dup2f(-1.52229e-3f);
    const u64t K5 = dup2f(-3.84800e-3f);
    const u64t K4 = dup2f(-1.015873e-2f);
    const u64t K3 = dup2f(-2.8571429e-2f);
    const u64t K2 = dup2f(-8.8888889e-2f);
    const u64t K1 = dup2f(-0.33333333f);
    const u64t K0 = dup2f(-2.0f);
    const u64t CM1 = dup2f(-1.0f);
    const u64t CP1 = dup2f(1.0f);

    float o[8][4];
#pragma unroll
    for (int dg = 0; dg < 8; dg++)
#pragma unroll
        for (int e = 0; e < 4; e++) o[dg][e] = 0.0f;
    float den0 = 0.0f, den1 = 0.0f;

    for (int j0 = 0; j0 < SEQ; j0 += 64) {
        __syncthreads();
        {
            const int j  = tid >> 1;
            const int cb = (tid & 1) * 32;
            const int jg = j >> 3, jl = j & 7;
            const float* src = sqb + (size_t)(j0 + j) * HD + cb;
#pragma unroll
            for (int q = 0; q < 8; q++) {
                float4 v = *(const float4*)(src + 4 * q);
                const int k0 = cb + 4 * q;
                {
                    int ks = k0 >> 4, p = (k0 & 15) >> 1;
                    int idx = ((jl << 2) | (p & 3)) * 2 + (p >> 2);
                    uint32_t hi, lo; split2(v.x, v.y, hi, lo);
                    Qs[0][jg][ks][idx] = hi; Qs[1][jg][ks][idx] = lo;
                }
                {
                    int k2 = k0 + 2;
                    int ks = k2 >> 4, p = (k2 & 15) >> 1;
                    int idx = ((jl << 2) | (p & 3)) * 2 + (p >> 2);
                    uint32_t hi, lo; split2(v.z, v.w, hi, lo);
                    Qs[0][jg][ks][idx] = hi; Qs[1][jg][ks][idx] = lo;
                }
            }
        }
        {
            const int jp = tid >> 2;
            const int js = jp >> 3, p = jp & 7;
            const int reg = p >> 2, pc = p & 3;
            const int db = (tid & 3) * 16;
            const float* s0 = Vb + (size_t)(j0 + 2 * jp) * HD;
            const float* s1 = s0 + HD;
#pragma unroll
            for (int q = 0; q < 4; q++) {
                float4 a = *(const float4*)(s0 + db + 4 * q);
                float4 b = *(const float4*)(s1 + db + 4 * q);
                float av[4] = { a.x, a.y, a.z, a.w };
                float bv[4] = { b.x, b.y, b.z, b.w };
#pragma unroll
                for (int e = 0; e < 4; e++) {
                    const int d = db + 4 * q + e;
                    const int dg = d >> 3;
                    const int idx = (((d & 7) << 2) | pc) * 2 + reg;
                    uint32_t hi, lo; split2(av[e], bv[e], hi, lo);
                    Vs[0][dg][js][idx] = hi; Vs[1][dg][js][idx] = lo;
                }
            }
        }
        __syncthreads();

        uint32_t Whi[4][4], Wlo[4][4];
#pragma unroll
        for (int jg = 0; jg < 8; jg++) {
            float acc[4] = { 0.0f, 0.0f, 0.0f, 0.0f };
#pragma unroll
            for (int ks = 0; ks < 4; ks++) {
                uint2 bhi = *(const uint2*)&Qs[0][jg][ks][lane * 2];
                uint2 blo = *(const uint2*)&Qs[1][jg][ks][lane * 2];
                mma_bf16(acc, Ahi[ks], bhi.x, bhi.y);
                mma_bf16(acc, Alo[ks], bhi.x, bhi.y);
                mma_bf16(acc, Ahi[ks], blo.x, blo.y);
            }
            u64t ua = fma2(pk2(acc[0], acc[1]), CM1, CP1);
            u64t ub = fma2(pk2(acc[2], acc[3]), CM1, CP1);
            u64t ga = K9, gb = K9;
            ga = fma2(ga, ua, K8);  gb = fma2(gb, ub, K8);
            ga = fma2(ga, ua, K7);  gb = fma2(gb, ub, K7);
            ga = fma2(ga, ua, K6);  gb = fma2(gb, ub, K6);
            ga = fma2(ga, ua, K5);  gb = fma2(gb, ub, K5);
            ga = fma2(ga, ua, K4);  gb = fma2(gb, ub, K4);
            ga = fma2(ga, ua, K3);  gb = fma2(gb, ub, K3);
            ga = fma2(ga, ua, K2);  gb = fma2(gb, ub, K2);
            ga = fma2(ga, ua, K1);  gb = fma2(gb, ub, K1);
            ga = fma2(ga, ua, K0);  gb = fma2(gb, ub, K0);
            ga = mul2(ga, ua);      gb = mul2(gb, ub);
            float2 gA = unpk(ga), gB = unpk(gb);
            float w0 = __expf(gA.x), w1 = __expf(gA.y);
            float w2 = __expf(gB.x), w3 = __expf(gB.y);
            den0 += w0 + w1;
            den1 += w2 + w3;
            const int ks = jg >> 1, up = (jg & 1) << 1;
            split2(w0, w1, Whi[ks][up + 0], Wlo[ks][up + 0]);
            split2(w2, w3, Whi[ks][up + 1], Wlo[ks][up + 1]);
        }

#pragma unroll
        for (int dg = 0; dg < 8; dg++) {
#pragma unroll
            for (int js = 0; js < 4; js++) {
                uint2 vhi = *(const uint2*)&Vs[0][dg][js][lane * 2];
                uint2 vlo = *(const uint2*)&Vs[1][dg][js][lane * 2];
                mma_bf16(o[dg], Whi[js], vhi.x, vhi.y);
                mma_bf16(o[dg], Wlo[js], vhi.x, vhi.y);
                mma_bf16(o[dg], Whi[js], vlo.x, vlo.y);
            }
        }
    }

    den0 += __shfl_xor_sync(0xffffffffu, den0, 1);
    den0 += __shfl_xor_sync(0xffffffffu, den0, 2);
    den1 += __shfl_xor_sync(0xffffffffu, den1, 1);
    den1 += __shfl_xor_sync(0xffffffffu, den1, 2);
    const float inv0 = 1.0f / den0;
    const float inv1 = 1.0f / den1;

    const int b = bh >> 3, hh = bh & 7;
    float* out0 = out + (size_t)(b * SEQ + row0) * DIM + hh * HD;
    float* out1 = out + (size_t)(b * SEQ + row1) * DIM + hh * HD;
#pragma unroll
    for (int dg = 0; dg < 8; dg++) {
        float2 t0 = { o[dg][0] * inv0, o[dg][1] * inv0 };
        float2 t1 = { o[dg][2] * inv1, o[dg][3] * inv1 };
        *(float2*)(out0 + dg * 8 + 2 * cq) = t0;
        *(float2*)(out1 + dg * 8 + 2 * cq) = t1;
    }
}

// ---------------------------------------------------------------------------
extern "C" void kernel_launch(void* const* d_in, const int* in_sizes, int n_in,
                              void* d_out, int out_size)
{
    const float* xr = (const float*)d_in[0];
    const float* xi = (const float*)d_in[1];
    const float* Wq = (const float*)d_in[2];
    const float* bq = (const float*)d_in[3];
    const float* Wk = (const float*)d_in[4];
    const float* bk = (const float*)d_in[5];
    const float* Wv = (const float*)d_in[6];
    const float* bv = (const float*)d_in[7];
    const float* Wo = (const float*)d_in[8];
    const float* bo = (const float*)d_in[9];
    float* out = (float*)d_out;

    float *Qp, *Kp, *Vp, *Ap;
    cudaGetSymbolAddress((void**)&Qp, g_Q);
    cudaGetSymbolAddress((void**)&Kp, g_K);
    cudaGetSymbolAddress((void**)&Vp, g_V);
    cudaGetSymbolAddress((void**)&Ap, g_att);

    const int gsmem = 65536;   // 16K u32 = 64 KB
    cudaFuncSetAttribute(mma_gemm<KIN, true>,
                         cudaFuncAttributeMaxDynamicSharedMemorySize, gsmem);
    cudaFuncSetAttribute(mma_gemm<DIM, false>,
                         cudaFuncAttributeMaxDynamicSharedMemorySize, gsmem);

    dim3 gp(DIM / 128, MTOT / 128);          // (4, 32)
    mma_gemm<KIN, true><<<gp, 256, gsmem>>>(xr, xi, Wq, DIM, bq, Qp, 0, 1);
    mma_gemm<KIN, true><<<gp, 256, gsmem>>>(xr, xi, Wk, DIM, bk, Kp, 0, 1);
    mma_gemm<KIN, true><<<gp, 256, gsmem>>>(xr, xi, Wv, DIM, bv, Vp, 0, 0);

    dim3 ga(SEQ / 64, BATCH * NH);           // (32, 16)
    attn_tc<<<ga, 128>>>(Qp, Kp, Vp, Ap);

    dim3 go(KIN / 128, MTOT / 128);          // (8, 32)
    mma_gemm<DIM, false><<<go, 256, gsmem>>>(Ap, nullptr, Wo, KIN, bo, out, KIN, 0);
}

// round 7
// speedup vs baseline: 1.8417x; 1.4879x over previous
#include <cuda_runtime.h>
#include <cuda_bf16.h>
#include <math.h>
#include <stdint.h>

#define DIM   512
#define NH    8
#define HD    64
#define SEQ   2048
#define BATCH 2
#define MTOT  (BATCH * SEQ)   // 4096
#define KIN   (2 * DIM)       // 1024

typedef unsigned long long u64t;

// ---- packed f32x2 helpers ----
__device__ __forceinline__ u64t fma2(u64t a, u64t b, u64t c) {
    u64t d; asm("fma.rn.f32x2 %0, %1, %2, %3;" : "=l"(d) : "l"(a), "l"(b), "l"(c));
    return d;
}
__device__ __forceinline__ u64t mul2(u64t a, u64t b) {
    u64t d; asm("mul.rn.f32x2 %0, %1, %2;" : "=l"(d) : "l"(a), "l"(b));
    return d;
}
__device__ __forceinline__ u64t dup2f(float x) {
    u64t r; asm("mov.b64 %0, {%1, %1};" : "=l"(r) : "f"(x));
    return r;
}
__device__ __forceinline__ u64t pk2(float a, float b) {
    u64t r; asm("mov.b64 %0, {%1, %2};" : "=l"(r) : "f"(a), "f"(b));
    return r;
}
__device__ __forceinline__ float2 unpk(u64t v) {
    float lo, hi; asm("mov.b64 {%0, %1}, %2;" : "=f"(lo), "=f"(hi) : "l"(v));
    float2 f; f.x = lo; f.y = hi; return f;
}

// ---- bf16x2 split: (x,y) -> hi pair + lo pair ----
__device__ __forceinline__ void split2(float x, float y, uint32_t& hi, uint32_t& lo) {
    __nv_bfloat162 h;
    h.x = __float2bfloat16(x);
    h.y = __float2bfloat16(y);
    float rx = x - __bfloat162float(h.x);
    float ry = y - __bfloat162float(h.y);
    __nv_bfloat162 l;
    l.x = __float2bfloat16(rx);
    l.y = __float2bfloat16(ry);
    hi = *reinterpret_cast<uint32_t*>(&h);
    lo = *reinterpret_cast<uint32_t*>(&l);
}

// mma.sync m16n8k16 bf16, fp32 accumulate (D==C in place)
__device__ __forceinline__ void mma_bf16(float c[4], const uint32_t a[4],
                                         uint32_t b0, uint32_t b1) {
    asm volatile(
        "mma.sync.aligned.m16n8k16.row.col.f32.bf16.bf16.f32 "
        "{%0,%1,%2,%3}, {%4,%5,%6,%7}, {%8,%9}, {%0,%1,%2,%3};"
        : "+f"(c[0]), "+f"(c[1]), "+f"(c[2]), "+f"(c[3])
        : "r"(a[0]), "r"(a[1]), "r"(a[2]), "r"(a[3]), "r"(b0), "r"(b1));
}
__device__ __forceinline__ void mma_bf16_u4(float c[4], uint4 a,
                                            uint32_t b0, uint32_t b1) {
    uint32_t ar[4] = { a.x, a.y, a.z, a.w };
    mma_bf16(c, ar, b0, b1);
}

// Scratch
__device__ float g_Q[BATCH * NH * SEQ * HD];
__device__ float g_K[BATCH * NH * SEQ * HD];
__device__ float g_V[BATCH * NH * SEQ * HD];
__device__ float g_att[MTOT * DIM];

// ---------------------------------------------------------------------------
// Tensor-core GEMM, warp-per-segment conflict-free staging.
// D[M=4096, N] = A[M, KD] @ W[KD, N] + bias. 256 thr, tile 128m x 128n,
// K in 32-wide chunks. Warp (wm=warp>>1, wn=warp&1) computes 32m x 64n.
// Staging: lane l loads exactly the values mma assigns to lane l:
//   A-frag (row-major m16k16): a0=A[g][2t], a1=A[g+8][2t], a2=A[g][2t+8],
//   a3=A[g+8][2t+8]  (g=lane>>2, t=lane&3), pairs (k,k+1).
//   B-frag (col-major k16n8): b0=B[2t..2t+1][g], b1=B[2t+8..2t+9][g].
// Asm[mg][ks][0..127]=hi uint4 @lane*4, [128..255]=lo. Bsm[ng][ks][lane*4]=
// {b0hi,b1hi,b0lo,b1lo}. All STS.128/LDS.128 at lane*4 -> conflict-free.
// ---------------------------------------------------------------------------
template<int KD, bool PROJ>
__global__ __launch_bounds__(256) void mma_gemm(
    const float* __restrict__ A0, const float* __restrict__ A1,
    const float* __restrict__ W, int ldb,
    const float* __restrict__ bias, float* __restrict__ out,
    int ldout, int do_sm)
{
    __shared__ uint32_t Asm[8][2][256];   // 16 KB
    __shared__ uint32_t Bsm[16][2][128];  // 16 KB

    const int tid  = threadIdx.x;
    const int warp = tid >> 5;
    const int lane = tid & 31;
    const int wm = warp >> 1, wn = warp & 1;
    const int g  = lane >> 2, tg = lane & 3;
    const int m0 = blockIdx.y * 128;
    const int n0 = blockIdx.x * 128;
    const int RS = PROJ ? DIM : KD;       // A row stride

    float2 Af[2][4];   // A seg t: {f00(m,k), f10(m+8,k), f01(m,k+8), f11(m+8,k+8)}
    float  Bf[4][4];   // B seg t: {W[k][n], W[k+1][n], W[k+8][n], W[k+9][n]}

    auto load_chunk = [&](int kt) {
        // A segs: (mg = warp, ks = t)
#pragma unroll
        for (int t = 0; t < 2; t++) {
            const int k = kt + t * 16 + 2 * tg;
            const float* ab;
            if (PROJ) {
                ab = ((k < DIM) ? A0 : A1)
                     + (size_t)(m0 + warp * 16 + g) * DIM + (k & (DIM - 1));
            } else {
                ab = A0 + (size_t)(m0 + warp * 16 + g) * KD + k;
            }
            Af[t][0] = *(const float2*)(ab);
            Af[t][1] = *(const float2*)(ab + 8 * RS);
            Af[t][2] = *(const float2*)(ab + 8);
            Af[t][3] = *(const float2*)(ab + 8 * RS + 8);
        }
        // B segs: (ng = warp*2 + (t>>1), ks = t&1)
#pragma unroll
        for (int t = 0; t < 4; t++) {
            const int ng = warp * 2 + (t >> 1), ks = t & 1;
            const int k = kt + ks * 16 + 2 * tg;
            const float* wb = W + (size_t)k * ldb + n0 + ng * 8 + g;
            Bf[t][0] = wb[0];
            Bf[t][1] = wb[ldb];
            Bf[t][2] = wb[8 * ldb];
            Bf[t][3] = wb[9 * ldb];
        }
    };

    auto store_chunk = [&]() {
#pragma unroll
        for (int t = 0; t < 2; t++) {
            uint32_t h[4], l[4];
            split2(Af[t][0].x, Af[t][0].y, h[0], l[0]);
            split2(Af[t][1].x, Af[t][1].y, h[1], l[1]);
            split2(Af[t][2].x, Af[t][2].y, h[2], l[2]);
            split2(Af[t][3].x, Af[t][3].y, h[3], l[3]);
            uint4 ph = { h[0], h[1], h[2], h[3] };
            uint4 pl = { l[0], l[1], l[2], l[3] };
            *(uint4*)&Asm[warp][t][lane * 4]       = ph;
            *(uint4*)&Asm[warp][t][128 + lane * 4] = pl;
        }
#pragma unroll
        for (int t = 0; t < 4; t++) {
            const int ng = warp * 2 + (t >> 1), ks = t & 1;
            uint32_t h0, l0, h1, l1;
            split2(Bf[t][0], Bf[t][1], h0, l0);
            split2(Bf[t][2], Bf[t][3], h1, l1);
            uint4 pk = { h0, h1, l0, l1 };
            *(uint4*)&Bsm[ng][ks][lane * 4] = pk;
        }
    };

    float C[2][8][4];
#pragma unroll
    for (int mg = 0; mg < 2; mg++)
#pragma unroll
        for (int ng = 0; ng < 8; ng++)
#pragma unroll
            for (int e = 0; e < 4; e++) C[mg][ng][e] = 0.0f;

    const int NCH = KD / 32;
    load_chunk(0);
    store_chunk();
    __syncthreads();

    for (int ch = 0; ch < NCH; ++ch) {
        if (ch + 1 < NCH) load_chunk((ch + 1) * 32);   // LDGs overlap MMA below
#pragma unroll
        for (int ks = 0; ks < 2; ks++) {
            uint4 ah0 = *(const uint4*)&Asm[wm * 2 + 0][ks][lane * 4];
            uint4 al0 = *(const uint4*)&Asm[wm * 2 + 0][ks][128 + lane * 4];
            uint4 ah1 = *(const uint4*)&Asm[wm * 2 + 1][ks][lane * 4];
            uint4 al1 = *(const uint4*)&Asm[wm * 2 + 1][ks][128 + lane * 4];
#pragma unroll
            for (int ng = 0; ng < 8; ng++) {
                uint4 b = *(const uint4*)&Bsm[wn * 8 + ng][ks][lane * 4];
                mma_bf16_u4(C[0][ng], ah0, b.x, b.y);
                mma_bf16_u4(C[0][ng], al0, b.x, b.y);
                mma_bf16_u4(C[0][ng], ah0, b.z, b.w);
                mma_bf16_u4(C[1][ng], ah1, b.x, b.y);
                mma_bf16_u4(C[1][ng], al1, b.x, b.y);
                mma_bf16_u4(C[1][ng], ah1, b.z, b.w);
            }
        }
        __syncthreads();
        if (ch + 1 < NCH) {
            store_chunk();
            __syncthreads();
        }
    }

    // ---- epilogue (layout identical to R6 known-good) ----
    float bb[8][2];
#pragma unroll
    for (int ng = 0; ng < 8; ng++) {
        const int n = n0 + wn * 64 + ng * 8 + 2 * tg;
        bb[ng][0] = bias[n];
        bb[ng][1] = bias[n + 1];
    }

    if (PROJ) {
        const int h = (n0 + wn * 64) >> 6;
#pragma unroll
        for (int mg = 0; mg < 2; mg++) {
#pragma unroll
            for (int half = 0; half < 2; half++) {
                const int m = m0 + wm * 32 + mg * 16 + g + half * 8;
                const int b = m >> 11;
                const int s = m & (SEQ - 1);
                float v[16];
#pragma unroll
                for (int ng = 0; ng < 8; ng++) {
                    v[2 * ng]     = C[mg][ng][half * 2]     + bb[ng][0];
                    v[2 * ng + 1] = C[mg][ng][half * 2 + 1] + bb[ng][1];
                }
                if (do_sm) {
                    float mx = v[0];
#pragma unroll
                    for (int e = 1; e < 16; e++) mx = fmaxf(mx, v[e]);
                    mx = fmaxf(mx, __shfl_xor_sync(0xffffffffu, mx, 1));
                    mx = fmaxf(mx, __shfl_xor_sync(0xffffffffu, mx, 2));
                    float sum = 0.0f;
#pragma unroll
                    for (int e = 0; e < 16; e++) { v[e] = __expf(v[e] - mx); sum += v[e]; }
                    sum += __shfl_xor_sync(0xffffffffu, sum, 1);
                    sum += __shfl_xor_sync(0xffffffffu, sum, 2);
                    const float inv = 1.0f / sum;
#pragma unroll
                    for (int e = 0; e < 16; e++) v[e] = sqrtf(v[e] * inv);
                }
                float* dst = out + ((size_t)(b * NH + h) * SEQ + s) * HD;
#pragma unroll
                for (int ng = 0; ng < 8; ng++) {
                    float2 t = { v[2 * ng], v[2 * ng + 1] };
                    *(float2*)(dst + ng * 8 + 2 * tg) = t;
                }
            }
        }
    } else {
#pragma unroll
        for (int mg = 0; mg < 2; mg++) {
#pragma unroll
            for (int half = 0; half < 2; half++) {
                const int m = m0 + wm * 32 + mg * 16 + g + half * 8;
                float* dst = out + (size_t)m * ldout + n0 + wn * 64;
#pragma unroll
                for (int ng = 0; ng < 8; ng++) {
                    float2 t = { C[mg][ng][half * 2]     + bb[ng][0],
                                 C[mg][ng][half * 2 + 1] + bb[ng][1] };
                    *(float2*)(dst + ng * 8 + 2 * tg) = t;
                }
            }
        }
    }
}

// ---------------------------------------------------------------------------
// Attention, warp-per-segment conflict-free staging.
// Qs[jg][ks][lane*4] = {b0hi,b1hi,b0lo,b1lo} for sq B-frags;
// Vs[dg][js][lane*4] = same for V B-frags. Single LDS.128 per frag read.
// ---------------------------------------------------------------------------
__global__ __launch_bounds__(128) void attn_tc(
    const float* __restrict__ sp, const float* __restrict__ sq,
    const float* __restrict__ V,  float* __restrict__ out)
{
    __shared__ uint32_t Qs[8][4][128];   // 16 KB
    __shared__ uint32_t Vs[8][4][128];   // 16 KB

    const int tid  = threadIdx.x;
    const int warp = tid >> 5;
    const int lane = tid & 31;
    const int r    = lane >> 2;
    const int cq   = lane & 3;
    const int bh   = blockIdx.y;
    const int i0   = blockIdx.x * 64;

    const float* spb = sp + (size_t)bh * SEQ * HD;
    const float* sqb = sq + (size_t)bh * SEQ * HD;
    const float* Vb  = V  + (size_t)bh * SEQ * HD;

    // --- preload sp A-frags (register-resident), bf16x2-split ---
    uint32_t Ahi[4][4], Alo[4][4];
    const int row0 = i0 + warp * 16 + r;
    const int row1 = row0 + 8;
#pragma unroll
    for (int ks = 0; ks < 4; ks++) {
        float2 v00 = *(const float2*)(spb + (size_t)row0 * HD + ks * 16 + 2 * cq);
        float2 v01 = *(const float2*)(spb + (size_t)row0 * HD + ks * 16 + 2 * cq + 8);
        float2 v10 = *(const float2*)(spb + (size_t)row1 * HD + ks * 16 + 2 * cq);
        float2 v11 = *(const float2*)(spb + (size_t)row1 * HD + ks * 16 + 2 * cq + 8);
        split2(v00.x, v00.y, Ahi[ks][0], Alo[ks][0]);
        split2(v10.x, v10.y, Ahi[ks][1], Alo[ks][1]);
        split2(v01.x, v01.y, Ahi[ks][2], Alo[ks][2]);
        split2(v11.x, v11.y, Ahi[ks][3], Alo[ks][3]);
    }

    const u64t K9 = dup2f(-2.0705e-4f);
    const u64t K8 = dup2f(-2.6002e-4f);
    const u64t K7 = dup2f(-6.2160e-4f);
    const u64t K6 = dup2f(-1.52229e-3f);
    const u64t K5 = dup2f(-3.84800e-3f);
    const u64t K4 = dup2f(-1.015873e-2f);
    const u64t K3 = dup2f(-2.8571429e-2f);
    const u64t K2 = dup2f(-8.8888889e-2f);
    const u64t K1 = dup2f(-0.33333333f);
    const u64t K0 = dup2f(-2.0f);
    const u64t CM1 = dup2f(-1.0f);
    const u64t CP1 = dup2f(1.0f);

    float o[8][4];
#pragma unroll
    for (int dg = 0; dg < 8; dg++)
#pragma unroll
        for (int e = 0; e < 4; e++) o[dg][e] = 0.0f;
    float den0 = 0.0f, den1 = 0.0f;

    for (int j0 = 0; j0 < SEQ; j0 += 64) {
        __syncthreads();   // prior tile's frag reads done

        // --- stage sq: warp handles segs (jg = warp*2 + (t>>2), ks = t&3) ---
#pragma unroll
        for (int t = 0; t < 8; t++) {
            const int jg = warp * 2 + (t >> 2), ks = t & 3;
            const float* src = sqb + (size_t)(j0 + jg * 8 + r) * HD + ks * 16 + 2 * cq;
            float2 f0 = *(const float2*)(src);
            float2 f1 = *(const float2*)(src + 8);
            uint32_t h0, l0, h1, l1;
            split2(f0.x, f0.y, h0, l0);
            split2(f1.x, f1.y, h1, l1);
            uint4 pk = { h0, h1, l0, l1 };
            *(uint4*)&Qs[jg][ks][lane * 4] = pk;
        }
        // --- stage V: warp handles segs (dg = warp*2 + (t>>2), js = t&3) ---
#pragma unroll
        for (int t = 0; t < 8; t++) {
            const int dg = warp * 2 + (t >> 2), js = t & 3;
            const float* vsrc = Vb + (size_t)(j0 + js * 16 + 2 * cq) * HD + dg * 8 + r;
            float v0 = vsrc[0];
            float v1 = vsrc[HD];
            float v2 = vsrc[8 * HD];
            float v3 = vsrc[9 * HD];
            uint32_t h0, l0, h1, l1;
            split2(v0, v1, h0, l0);
            split2(v2, v3, h1, l1);
            uint4 pk = { h0, h1, l0, l1 };
            *(uint4*)&Vs[dg][js][lane * 4] = pk;
        }
        __syncthreads();

        // --- bc MMAs + transform -> register-resident w A-frags ---
        uint32_t Whi[4][4], Wlo[4][4];
#pragma unroll
        for (int jg = 0; jg < 8; jg++) {
            float acc[4] = { 0.0f, 0.0f, 0.0f, 0.0f };
#pragma unroll
            for (int ks = 0; ks < 4; ks++) {
                uint4 q = *(const uint4*)&Qs[jg][ks][lane * 4];
                mma_bf16(acc, Ahi[ks], q.x, q.y);
                mma_bf16(acc, Alo[ks], q.x, q.y);
                mma_bf16(acc, Ahi[ks], q.z, q.w);
            }
            u64t ua = fma2(pk2(acc[0], acc[1]), CM1, CP1);
            u64t ub = fma2(pk2(acc[2], acc[3]), CM1, CP1);
            u64t ga = K9, gb = K9;
            ga = fma2(ga, ua, K8);  gb = fma2(gb, ub, K8);
            ga = fma2(ga, ua, K7);  gb = fma2(gb, ub, K7);
            ga = fma2(ga, ua, K6);  gb = fma2(gb, ub, K6);
            ga = fma2(ga, ua, K5);  gb = fma2(gb, ub, K5);
            ga = fma2(ga, ua, K4);  gb = fma2(gb, ub, K4);
            ga = fma2(ga, ua, K3);  gb = fma2(gb, ub, K3);
            ga = fma2(ga, ua, K2);  gb = fma2(gb, ub, K2);
            ga = fma2(ga, ua, K1);  gb = fma2(gb, ub, K1);
            ga = fma2(ga, ua, K0);  gb = fma2(gb, ub, K0);
            ga = mul2(ga, ua);      gb = mul2(gb, ub);
            float2 gA = unpk(ga), gB = unpk(gb);
            float w0 = __expf(gA.x), w1 = __expf(gA.y);
            float w2 = __expf(gB.x), w3 = __expf(gB.y);
            den0 += w0 + w1;
            den1 += w2 + w3;
            const int ks = jg >> 1, up = (jg & 1) << 1;
            split2(w0, w1, Whi[ks][up + 0], Wlo[ks][up + 0]);
            split2(w2, w3, Whi[ks][up + 1], Wlo[ks][up + 1]);
        }

        // --- o += w @ V ---
#pragma unroll
        for (int dg = 0; dg < 8; dg++) {
#pragma unroll
            for (int js = 0; js < 4; js++) {
                uint4 v = *(const uint4*)&Vs[dg][js][lane * 4];
                mma_bf16(o[dg], Whi[js], v.x, v.y);
                mma_bf16(o[dg], Wlo[js], v.x, v.y);
                mma_bf16(o[dg], Whi[js], v.z, v.w);
            }
        }
    }

    den0 += __shfl_xor_sync(0xffffffffu, den0, 1);
    den0 += __shfl_xor_sync(0xffffffffu, den0, 2);
    den1 += __shfl_xor_sync(0xffffffffu, den1, 1);
    den1 += __shfl_xor_sync(0xffffffffu, den1, 2);
    const float inv0 = 1.0f / den0;
    const float inv1 = 1.0f / den1;

    const int b = bh >> 3, hh = bh & 7;
    float* out0 = out + (size_t)(b * SEQ + row0) * DIM + hh * HD;
    float* out1 = out + (size_t)(b * SEQ + row1) * DIM + hh * HD;
#pragma unroll
    for (int dg = 0; dg < 8; dg++) {
        float2 t0 = { o[dg][0] * inv0, o[dg][1] * inv0 };
        float2 t1 = { o[dg][2] * inv1, o[dg][3] * inv1 };
        *(float2*)(out0 + dg * 8 + 2 * cq) = t0;
        *(float2*)(out1 + dg * 8 + 2 * cq) = t1;
    }
}

// ---------------------------------------------------------------------------
extern "C" void kernel_launch(void* const* d_in, const int* in_sizes, int n_in,
                              void* d_out, int out_size)
{
    const float* xr = (const float*)d_in[0];
    const float* xi = (const float*)d_in[1];
    const float* Wq = (const float*)d_in[2];
    const float* bq = (const float*)d_in[3];
    const float* Wk = (const float*)d_in[4];
    const float* bk = (const float*)d_in[5];
    const float* Wv = (const float*)d_in[6];
    const float* bv = (const float*)d_in[7];
    const float* Wo = (const float*)d_in[8];
    const float* bo = (const float*)d_in[9];
    float* out = (float*)d_out;

    float *Qp, *Kp, *Vp, *Ap;
    cudaGetSymbolAddress((void**)&Qp, g_Q);
    cudaGetSymbolAddress((void**)&Kp, g_K);
    cudaGetSymbolAddress((void**)&Vp, g_V);
    cudaGetSymbolAddress((void**)&Ap, g_att);

    dim3 gp(DIM / 128, MTOT / 128);          // (4, 32)
    mma_gemm<KIN, true><<<gp, 256>>>(xr, xi, Wq, DIM, bq, Qp, 0, 1);
    mma_gemm<KIN, true><<<gp, 256>>>(xr, xi, Wk, DIM, bk, Kp, 0, 1);
    mma_gemm<KIN, true><<<gp, 256>>>(xr, xi, Wv, DIM, bv, Vp, 0, 0);

    dim3 ga(SEQ / 64, BATCH * NH);           // (32, 16)
    attn_tc<<<ga, 128>>>(Qp, Kp, Vp, Ap);

    dim3 go(KIN / 128, MTOT / 128);          // (8, 32)
    mma_gemm<DIM, false><<<go, 256>>>(Ap, nullptr, Wo, KIN, bo, out, KIN, 0);
}

// round 8
// speedup vs baseline: 1.9828x; 1.0766x over previous
#include <cuda_runtime.h>
#include <cuda_bf16.h>
#include <math.h>
#include <stdint.h>

#define DIM   512
#define NH    8
#define HD    64
#define SEQ   2048
#define BATCH 2
#define MTOT  (BATCH * SEQ)   // 4096
#define KIN   (2 * DIM)       // 1024

typedef unsigned long long u64t;

// ---- packed f32x2 helpers ----
__device__ __forceinline__ u64t fma2(u64t a, u64t b, u64t c) {
    u64t d; asm("fma.rn.f32x2 %0, %1, %2, %3;" : "=l"(d) : "l"(a), "l"(b), "l"(c));
    return d;
}
__device__ __forceinline__ u64t mul2(u64t a, u64t b) {
    u64t d; asm("mul.rn.f32x2 %0, %1, %2;" : "=l"(d) : "l"(a), "l"(b));
    return d;
}
__device__ __forceinline__ u64t dup2f(float x) {
    u64t r; asm("mov.b64 %0, {%1, %1};" : "=l"(r) : "f"(x));
    return r;
}
__device__ __forceinline__ u64t pk2(float a, float b) {
    u64t r; asm("mov.b64 %0, {%1, %2};" : "=l"(r) : "f"(a), "f"(b));
    return r;
}
__device__ __forceinline__ float2 unpk(u64t v) {
    float lo, hi; asm("mov.b64 {%0, %1}, %2;" : "=f"(lo), "=f"(hi) : "l"(v));
    float2 f; f.x = lo; f.y = hi; return f;
}

// ---- bf16x2 split: (x,y) -> hi pair + lo pair ----
__device__ __forceinline__ void split2(float x, float y, uint32_t& hi, uint32_t& lo) {
    __nv_bfloat162 h;
    h.x = __float2bfloat16(x);
    h.y = __float2bfloat16(y);
    float rx = x - __bfloat162float(h.x);
    float ry = y - __bfloat162float(h.y);
    __nv_bfloat162 l;
    l.x = __float2bfloat16(rx);
    l.y = __float2bfloat16(ry);
    hi = *reinterpret_cast<uint32_t*>(&h);
    lo = *reinterpret_cast<uint32_t*>(&l);
}

// mma.sync m16n8k16 bf16, fp32 accumulate (D==C in place)
__device__ __forceinline__ void mma_bf16(float c[4], const uint32_t a[4],
                                         uint32_t b0, uint32_t b1) {
    asm volatile(
        "mma.sync.aligned.m16n8k16.row.col.f32.bf16.bf16.f32 "
        "{%0,%1,%2,%3}, {%4,%5,%6,%7}, {%8,%9}, {%0,%1,%2,%3};"
        : "+f"(c[0]), "+f"(c[1]), "+f"(c[2]), "+f"(c[3])
        : "r"(a[0]), "r"(a[1]), "r"(a[2]), "r"(a[3]), "r"(b0), "r"(b1));
}
__device__ __forceinline__ void mma_bf16_u4(float c[4], uint4 a,
                                            uint32_t b0, uint32_t b1) {
    uint32_t ar[4] = { a.x, a.y, a.z, a.w };
    mma_bf16(c, ar, b0, b1);
}

// Scratch
__device__ float g_Q[BATCH * NH * SEQ * HD];
__device__ float g_K[BATCH * NH * SEQ * HD];
__device__ float g_V[BATCH * NH * SEQ * HD];
__device__ float g_att[MTOT * DIM];

// ---------------------------------------------------------------------------
// Tensor-core GEMM body (identical math/layout to R7 known-good mma_gemm).
// ---------------------------------------------------------------------------
template<int KD, bool PROJ>
__device__ __forceinline__ void gemm_body(
    const float* __restrict__ A0, const float* __restrict__ A1,
    const float* __restrict__ W, int ldb,
    const float* __restrict__ bias, float* __restrict__ out,
    int ldout, int do_sm)
{
    __shared__ uint32_t Asm[8][2][256];   // 16 KB
    __shared__ uint32_t Bsm[16][2][128];  // 16 KB

    const int tid  = threadIdx.x;
    const int warp = tid >> 5;
    const int lane = tid & 31;
    const int wm = warp >> 1, wn = warp & 1;
    const int g  = lane >> 2, tg = lane & 3;
    const int m0 = blockIdx.y * 128;
    const int n0 = blockIdx.x * 128;
    const int RS = PROJ ? DIM : KD;

    float2 Af[2][4];
    float  Bf[4][4];

    auto load_chunk = [&](int kt) {
#pragma unroll
        for (int t = 0; t < 2; t++) {
            const int k = kt + t * 16 + 2 * tg;
            const float* ab;
            if (PROJ) {
                ab = ((k < DIM) ? A0 : A1)
                     + (size_t)(m0 + warp * 16 + g) * DIM + (k & (DIM - 1));
            } else {
                ab = A0 + (size_t)(m0 + warp * 16 + g) * KD + k;
            }
            Af[t][0] = *(const float2*)(ab);
            Af[t][1] = *(const float2*)(ab + 8 * RS);
            Af[t][2] = *(const float2*)(ab + 8);
            Af[t][3] = *(const float2*)(ab + 8 * RS + 8);
        }
#pragma unroll
        for (int t = 0; t < 4; t++) {
            const int ks = t & 1;
            const int k = kt + ks * 16 + 2 * tg;
            const int ng = warp * 2 + (t >> 1);
            const float* wb = W + (size_t)k * ldb + n0 + ng * 8 + g;
            Bf[t][0] = wb[0];
            Bf[t][1] = wb[ldb];
            Bf[t][2] = wb[8 * ldb];
            Bf[t][3] = wb[9 * ldb];
        }
    };

    auto store_chunk = [&]() {
#pragma unroll
        for (int t = 0; t < 2; t++) {
            uint32_t h[4], l[4];
            split2(Af[t][0].x, Af[t][0].y, h[0], l[0]);
            split2(Af[t][1].x, Af[t][1].y, h[1], l[1]);
            split2(Af[t][2].x, Af[t][2].y, h[2], l[2]);
            split2(Af[t][3].x, Af[t][3].y, h[3], l[3]);
            uint4 ph = { h[0], h[1], h[2], h[3] };
            uint4 pl = { l[0], l[1], l[2], l[3] };
            *(uint4*)&Asm[warp][t][lane * 4]       = ph;
            *(uint4*)&Asm[warp][t][128 + lane * 4] = pl;
        }
#pragma unroll
        for (int t = 0; t < 4; t++) {
            const int ng = warp * 2 + (t >> 1), ks = t & 1;
            uint32_t h0, l0, h1, l1;
            split2(Bf[t][0], Bf[t][1], h0, l0);
            split2(Bf[t][2], Bf[t][3], h1, l1);
            uint4 pk = { h0, h1, l0, l1 };
            *(uint4*)&Bsm[ng][ks][lane * 4] = pk;
        }
    };

    float C[2][8][4];
#pragma unroll
    for (int mg = 0; mg < 2; mg++)
#pragma unroll
        for (int ng = 0; ng < 8; ng++)
#pragma unroll
            for (int e = 0; e < 4; e++) C[mg][ng][e] = 0.0f;

    const int NCH = KD / 32;
    load_chunk(0);
    store_chunk();
    __syncthreads();

    for (int ch = 0; ch < NCH; ++ch) {
        if (ch + 1 < NCH) load_chunk((ch + 1) * 32);
#pragma unroll
        for (int ks = 0; ks < 2; ks++) {
            uint4 ah0 = *(const uint4*)&Asm[wm * 2 + 0][ks][lane * 4];
            uint4 al0 = *(const uint4*)&Asm[wm * 2 + 0][ks][128 + lane * 4];
            uint4 ah1 = *(const uint4*)&Asm[wm * 2 + 1][ks][lane * 4];
            uint4 al1 = *(const uint4*)&Asm[wm * 2 + 1][ks][128 + lane * 4];
#pragma unroll
            for (int ng = 0; ng < 8; ng++) {
                uint4 b = *(const uint4*)&Bsm[wn * 8 + ng][ks][lane * 4];
                mma_bf16_u4(C[0][ng], ah0, b.x, b.y);
                mma_bf16_u4(C[0][ng], al0, b.x, b.y);
                mma_bf16_u4(C[0][ng], ah0, b.z, b.w);
                mma_bf16_u4(C[1][ng], ah1, b.x, b.y);
                mma_bf16_u4(C[1][ng], al1, b.x, b.y);
                mma_bf16_u4(C[1][ng], ah1, b.z, b.w);
            }
        }
        __syncthreads();
        if (ch + 1 < NCH) {
            store_chunk();
            __syncthreads();
        }
    }

    float bb[8][2];
#pragma unroll
    for (int ng = 0; ng < 8; ng++) {
        const int n = n0 + wn * 64 + ng * 8 + 2 * tg;
        bb[ng][0] = bias[n];
        bb[ng][1] = bias[n + 1];
    }

    if (PROJ) {
        const int h = (n0 + wn * 64) >> 6;
#pragma unroll
        for (int mg = 0; mg < 2; mg++) {
#pragma unroll
            for (int half = 0; half < 2; half++) {
                const int m = m0 + wm * 32 + mg * 16 + g + half * 8;
                const int b = m >> 11;
                const int s = m & (SEQ - 1);
                float v[16];
#pragma unroll
                for (int ng = 0; ng < 8; ng++) {
                    v[2 * ng]     = C[mg][ng][half * 2]     + bb[ng][0];
                    v[2 * ng + 1] = C[mg][ng][half * 2 + 1] + bb[ng][1];
                }
                if (do_sm) {
                    float mx = v[0];
#pragma unroll
                    for (int e = 1; e < 16; e++) mx = fmaxf(mx, v[e]);
                    mx = fmaxf(mx, __shfl_xor_sync(0xffffffffu, mx, 1));
                    mx = fmaxf(mx, __shfl_xor_sync(0xffffffffu, mx, 2));
                    float sum = 0.0f;
#pragma unroll
                    for (int e = 0; e < 16; e++) { v[e] = __expf(v[e] - mx); sum += v[e]; }
                    sum += __shfl_xor_sync(0xffffffffu, sum, 1);
                    sum += __shfl_xor_sync(0xffffffffu, sum, 2);
                    const float inv = 1.0f / sum;
#pragma unroll
                    for (int e = 0; e < 16; e++) v[e] = sqrtf(v[e] * inv);
                }
                float* dst = out + ((size_t)(b * NH + h) * SEQ + s) * HD;
#pragma unroll
                for (int ng = 0; ng < 8; ng++) {
                    float2 t = { v[2 * ng], v[2 * ng + 1] };
                    *(float2*)(dst + ng * 8 + 2 * tg) = t;
                }
            }
        }
    } else {
#pragma unroll
        for (int mg = 0; mg < 2; mg++) {
#pragma unroll
            for (int half = 0; half < 2; half++) {
                const int m = m0 + wm * 32 + mg * 16 + g + half * 8;
                float* dst = out + (size_t)m * ldout + n0 + wn * 64;
#pragma unroll
                for (int ng = 0; ng < 8; ng++) {
                    float2 t = { C[mg][ng][half * 2]     + bb[ng][0],
                                 C[mg][ng][half * 2 + 1] + bb[ng][1] };
                    *(float2*)(dst + ng * 8 + 2 * tg) = t;
                }
            }
        }
    }
}

// Fused Q/K/V projection: blockIdx.z selects weight/bias/output.
__global__ __launch_bounds__(256) void proj_qkv(
    const float* __restrict__ xr, const float* __restrict__ xi,
    const float* __restrict__ Wq, const float* __restrict__ Wk,
    const float* __restrict__ Wv,
    const float* __restrict__ bq, const float* __restrict__ bk,
    const float* __restrict__ bv,
    float* __restrict__ Q, float* __restrict__ K, float* __restrict__ V)
{
    const int z = blockIdx.z;
    const float* W = (z == 0) ? Wq : (z == 1) ? Wk : Wv;
    const float* b = (z == 0) ? bq : (z == 1) ? bk : bv;
    float* o = (z == 0) ? Q : (z == 1) ? K : V;
    gemm_body<KIN, true>(xr, xi, W, DIM, b, o, 0, z < 2);
}

__global__ __launch_bounds__(256) void out_gemm(
    const float* __restrict__ A, const float* __restrict__ W,
    const float* __restrict__ bias, float* __restrict__ out)
{
    gemm_body<DIM, false>(A, nullptr, W, KIN, bias, out, KIN, 0);
}

// ---------------------------------------------------------------------------
// Attention: 256 threads (8 warps), 128 i-rows/block, pipelined staging.
// Warp w owns i-rows [i0 + 16w, i0 + 16w + 16) and stages Qs[w][*], Vs[w][*].
// Per j-tile: STS(cur regs) -> bar -> LDG(next) -> MMA/transform/MMA -> bar.
// ---------------------------------------------------------------------------
__global__ __launch_bounds__(256) void attn_tc(
    const float* __restrict__ sp, const float* __restrict__ sq,
    const float* __restrict__ V,  float* __restrict__ out)
{
    __shared__ uint32_t Qs[8][4][128];   // 16 KB
    __shared__ uint32_t Vs[8][4][128];   // 16 KB

    const int tid  = threadIdx.x;
    const int warp = tid >> 5;
    const int lane = tid & 31;
    const int r    = lane >> 2;
    const int cq   = lane & 3;
    const int bh   = blockIdx.y;
    const int i0   = blockIdx.x * 128;

    const float* spb = sp + (size_t)bh * SEQ * HD;
    const float* sqb = sq + (size_t)bh * SEQ * HD;
    const float* Vb  = V  + (size_t)bh * SEQ * HD;

    // --- preload sp A-frags (register-resident) ---
    uint32_t Ahi[4][4], Alo[4][4];
    const int row0 = i0 + warp * 16 + r;
    const int row1 = row0 + 8;
#pragma unroll
    for (int ks = 0; ks < 4; ks++) {
        float2 v00 = *(const float2*)(spb + (size_t)row0 * HD + ks * 16 + 2 * cq);
        float2 v01 = *(const float2*)(spb + (size_t)row0 * HD + ks * 16 + 2 * cq + 8);
        float2 v10 = *(const float2*)(spb + (size_t)row1 * HD + ks * 16 + 2 * cq);
        float2 v11 = *(const float2*)(spb + (size_t)row1 * HD + ks * 16 + 2 * cq + 8);
        split2(v00.x, v00.y, Ahi[ks][0], Alo[ks][0]);
        split2(v10.x, v10.y, Ahi[ks][1], Alo[ks][1]);
        split2(v01.x, v01.y, Ahi[ks][2], Alo[ks][2]);
        split2(v11.x, v11.y, Ahi[ks][3], Alo[ks][3]);
    }

    const u64t K9 = dup2f(-2.0705e-4f);
    const u64t K8 = dup2f(-2.6002e-4f);
    const u64t K7 = dup2f(-6.2160e-4f);
    const u64t K6 = dup2f(-1.52229e-3f);
    const u64t K5 = dup2f(-3.84800e-3f);
    const u64t K4 = dup2f(-1.015873e-2f);
    const u64t K3 = dup2f(-2.8571429e-2f);
    const u64t K2 = dup2f(-8.8888889e-2f);
    const u64t K1 = dup2f(-0.33333333f);
    const u64t K0 = dup2f(-2.0f);
    const u64t CM1 = dup2f(-1.0f);
    const u64t CP1 = dup2f(1.0f);

    // staging registers: warp stages sq segs (jg=warp, ks=0..3) and
    // V segs (dg=warp, js=0..3)
    float2 Qf[4][2];   // per ks: {f0 (k..k+1), f1 (k+8..k+9)}
    float  Vf[4][4];   // per js: {V[j][d], V[j+1][d], V[j+8][d], V[j+9][d]}

    auto load_tile = [&](int j0) {
#pragma unroll
        for (int ks = 0; ks < 4; ks++) {
            const float* src = sqb + (size_t)(j0 + warp * 8 + r) * HD + ks * 16 + 2 * cq;
            Qf[ks][0] = *(const float2*)(src);
            Qf[ks][1] = *(const float2*)(src + 8);
        }
#pragma unroll
        for (int js = 0; js < 4; js++) {
            const float* vsrc = Vb + (size_t)(j0 + js * 16 + 2 * cq) * HD + warp * 8 + r;
            Vf[js][0] = vsrc[0];
            Vf[js][1] = vsrc[HD];
            Vf[js][2] = vsrc[8 * HD];
            Vf[js][3] = vsrc[9 * HD];
        }
    };

    auto store_tile = [&]() {
#pragma unroll
        for (int ks = 0; ks < 4; ks++) {
            uint32_t h0, l0, h1, l1;
            split2(Qf[ks][0].x, Qf[ks][0].y, h0, l0);
            split2(Qf[ks][1].x, Qf[ks][1].y, h1, l1);
            uint4 pk = { h0, h1, l0, l1 };
            *(uint4*)&Qs[warp][ks][lane * 4] = pk;
        }
#pragma unroll
        for (int js = 0; js < 4; js++) {
            uint32_t h0, l0, h1, l1;
            split2(Vf[js][0], Vf[js][1], h0, l0);
            split2(Vf[js][2], Vf[js][3], h1, l1);
            uint4 pk = { h0, h1, l0, l1 };
            *(uint4*)&Vs[warp][js][lane * 4] = pk;
        }
    };

    float o[8][4];
#pragma unroll
    for (int dg = 0; dg < 8; dg++)
#pragma unroll
        for (int e = 0; e < 4; e++) o[dg][e] = 0.0f;
    float den0 = 0.0f, den1 = 0.0f;

    load_tile(0);

    const int NT = SEQ / 64;   // 32
    for (int t = 0; t < NT; ++t) {
        store_tile();
        __syncthreads();                       // staging visible
        if (t + 1 < NT) load_tile((t + 1) * 64);   // prefetch hides under MMA

        // --- bc MMAs + transform -> register-resident w A-frags ---
        uint32_t Whi[4][4], Wlo[4][4];
#pragma unroll
        for (int jg = 0; jg < 8; jg++) {
            float acc[4] = { 0.0f, 0.0f, 0.0f, 0.0f };
#pragma unroll
            for (int ks = 0; ks < 4; ks++) {
                uint4 q = *(const uint4*)&Qs[jg][ks][lane * 4];
                mma_bf16(acc, Ahi[ks], q.x, q.y);
                mma_bf16(acc, Alo[ks], q.x, q.y);
                mma_bf16(acc, Ahi[ks], q.z, q.w);
            }
            u64t ua = fma2(pk2(acc[0], acc[1]), CM1, CP1);
            u64t ub = fma2(pk2(acc[2], acc[3]), CM1, CP1);
            u64t ga = K9, gb = K9;
            ga = fma2(ga, ua, K8);  gb = fma2(gb, ub, K8);
            ga = fma2(ga, ua, K7);  gb = fma2(gb, ub, K7);
            ga = fma2(ga, ua, K6);  gb = fma2(gb, ub, K6);
            ga = fma2(ga, ua, K5);  gb = fma2(gb, ub, K5);
            ga = fma2(ga, ua, K4);  gb = fma2(gb, ub, K4);
            ga = fma2(ga, ua, K3);  gb = fma2(gb, ub, K3);
            ga = fma2(ga, ua, K2);  gb = fma2(gb, ub, K2);
            ga = fma2(ga, ua, K1);  gb = fma2(gb, ub, K1);
            ga = fma2(ga, ua, K0);  gb = fma2(gb, ub, K0);
            ga = mul2(ga, ua);      gb = mul2(gb, ub);
            float2 gA = unpk(ga), gB = unpk(gb);
            float w0 = __expf(gA.x), w1 = __expf(gA.y);
            float w2 = __expf(gB.x), w3 = __expf(gB.y);
            den0 += w0 + w1;
            den1 += w2 + w3;
            const int ks = jg >> 1, up = (jg & 1) << 1;
            split2(w0, w1, Whi[ks][up + 0], Wlo[ks][up + 0]);
            split2(w2, w3, Whi[ks][up + 1], Wlo[ks][up + 1]);
        }

        // --- o += w @ V ---
#pragma unroll
        for (int dg = 0; dg < 8; dg++) {
#pragma unroll
            for (int js = 0; js < 4; js++) {
                uint4 v = *(const uint4*)&Vs[dg][js][lane * 4];
                mma_bf16(o[dg], Whi[js], v.x, v.y);
                mma_bf16(o[dg], Wlo[js], v.x, v.y);
                mma_bf16(o[dg], Whi[js], v.z, v.w);
            }
        }
        __syncthreads();                       // frag reads done before next store
    }

    den0 += __shfl_xor_sync(0xffffffffu, den0, 1);
    den0 += __shfl_xor_sync(0xffffffffu, den0, 2);
    den1 += __shfl_xor_sync(0xffffffffu, den1, 1);
    den1 += __shfl_xor_sync(0xffffffffu, den1, 2);
    const float inv0 = 1.0f / den0;
    const float inv1 = 1.0f / den1;

    const int b = bh >> 3, hh = bh & 7;
    float* out0 = out + (size_t)(b * SEQ + row0) * DIM + hh * HD;
    float* out1 = out + (size_t)(b * SEQ + row1) * DIM + hh * HD;
#pragma unroll
    for (int dg = 0; dg < 8; dg++) {
        float2 t0 = { o[dg][0] * inv0, o[dg][1] * inv0 };
        float2 t1 = { o[dg][2] * inv1, o[dg][3] * inv1 };
        *(float2*)(out0 + dg * 8 + 2 * cq) = t0;
        *(float2*)(out1 + dg * 8 + 2 * cq) = t1;
    }
}

// ---------------------------------------------------------------------------
extern "C" void kernel_launch(void* const* d_in, const int* in_sizes, int n_in,
                              void* d_out, int out_size)
{
    const float* xr = (const float*)d_in[0];
    const float* xi = (const float*)d_in[1];
    const float* Wq = (const float*)d_in[2];
    const float* bq = (const float*)d_in[3];
    const float* Wk = (const float*)d_in[4];
    const float* bk = (const float*)d_in[5];
    const float* Wv = (const float*)d_in[6];
    const float* bv = (const float*)d_in[7];
    const float* Wo = (const float*)d_in[8];
    const float* bo = (const float*)d_in[9];
    float* out = (float*)d_out;

    float *Qp, *Kp, *Vp, *Ap;
    cudaGetSymbolAddress((void**)&Qp, g_Q);
    cudaGetSymbolAddress((void**)&Kp, g_K);
    cudaGetSymbolAddress((void**)&Vp, g_V);
    cudaGetSymbolAddress((void**)&Ap, g_att);

    dim3 gp(DIM / 128, MTOT / 128, 3);       // (4, 32, 3) = 384 blocks
    proj_qkv<<<gp, 256>>>(xr, xi, Wq, Wk, Wv, bq, bk, bv, Qp, Kp, Vp);

    dim3 ga(SEQ / 128, BATCH * NH);          // (16, 16) = 256 blocks
    attn_tc<<<ga, 256>>>(Qp, Kp, Vp, Ap);

    dim3 go(KIN / 128, MTOT / 128);          // (8, 32)
    out_gemm<<<go, 256>>>(Ap, Wo, bo, out);
}

// round 9
// speedup vs baseline: 2.0581x; 1.0380x over previous
#include <cuda_runtime.h>
#include <cuda_bf16.h>
#include <math.h>
#include <stdint.h>

#define DIM   512
#define NH    8
#define HD    64
#define SEQ   2048
#define BATCH 2
#define MTOT  (BATCH * SEQ)   // 4096
#define KIN   (2 * DIM)       // 1024

typedef unsigned long long u64t;

// ---- packed f32x2 helpers ----
__device__ __forceinline__ u64t fma2(u64t a, u64t b, u64t c) {
    u64t d; asm("fma.rn.f32x2 %0, %1, %2, %3;" : "=l"(d) : "l"(a), "l"(b), "l"(c));
    return d;
}
__device__ __forceinline__ u64t mul2(u64t a, u64t b) {
    u64t d; asm("mul.rn.f32x2 %0, %1, %2;" : "=l"(d) : "l"(a), "l"(b));
    return d;
}
__device__ __forceinline__ u64t dup2f(float x) {
    u64t r; asm("mov.b64 %0, {%1, %1};" : "=l"(r) : "f"(x));
    return r;
}
__device__ __forceinline__ u64t pk2(float a, float b) {
    u64t r; asm("mov.b64 %0, {%1, %2};" : "=l"(r) : "f"(a), "f"(b));
    return r;
}
__device__ __forceinline__ float2 unpk(u64t v) {
    float lo, hi; asm("mov.b64 {%0, %1}, %2;" : "=f"(lo), "=f"(hi) : "l"(v));
    float2 f; f.x = lo; f.y = hi; return f;
}

// ---- bf16x2 split: (x,y) -> hi pair + lo pair ----
__device__ __forceinline__ void split2(float x, float y, uint32_t& hi, uint32_t& lo) {
    __nv_bfloat162 h;
    h.x = __float2bfloat16(x);
    h.y = __float2bfloat16(y);
    float rx = x - __bfloat162float(h.x);
    float ry = y - __bfloat162float(h.y);
    __nv_bfloat162 l;
    l.x = __float2bfloat16(rx);
    l.y = __float2bfloat16(ry);
    hi = *reinterpret_cast<uint32_t*>(&h);
    lo = *reinterpret_cast<uint32_t*>(&l);
}

// mma.sync m16n8k16 bf16, fp32 accumulate (D==C in place)
__device__ __forceinline__ void mma_bf16(float c[4], const uint32_t a[4],
                                         uint32_t b0, uint32_t b1) {
    asm volatile(
        "mma.sync.aligned.m16n8k16.row.col.f32.bf16.bf16.f32 "
        "{%0,%1,%2,%3}, {%4,%5,%6,%7}, {%8,%9}, {%0,%1,%2,%3};"
        : "+f"(c[0]), "+f"(c[1]), "+f"(c[2]), "+f"(c[3])
        : "r"(a[0]), "r"(a[1]), "r"(a[2]), "r"(a[3]), "r"(b0), "r"(b1));
}
__device__ __forceinline__ void mma_bf16_u4(float c[4], uint4 a,
                                            uint32_t b0, uint32_t b1) {
    uint32_t ar[4] = { a.x, a.y, a.z, a.w };
    mma_bf16(c, ar, b0, b1);
}

// Scratch
__device__ float g_Q[BATCH * NH * SEQ * HD];
__device__ float g_K[BATCH * NH * SEQ * HD];
__device__ float g_V[BATCH * NH * SEQ * HD];
__device__ float g_att[MTOT * DIM];

// ---------------------------------------------------------------------------
// Tensor-core GEMM body, double-buffered smem, ONE barrier per K-chunk.
// Dynamic smem 64 KB: Asm[2][8][2][256] then Bsm[2][16][2][128].
// ---------------------------------------------------------------------------
template<int KD, bool PROJ>
__device__ __forceinline__ void gemm_body(
    const float* __restrict__ A0, const float* __restrict__ A1,
    const float* __restrict__ W, int ldb,
    const float* __restrict__ bias, float* __restrict__ out,
    int ldout, int do_sm)
{
    extern __shared__ uint32_t sm[];
    uint32_t* AsmB = sm;            // [2][8][2][256]  (buf stride 4096)
    uint32_t* BsmB = sm + 8192;     // [2][16][2][128] (buf stride 4096)

    const int tid  = threadIdx.x;
    const int warp = tid >> 5;
    const int lane = tid & 31;
    const int wm = warp >> 1, wn = warp & 1;
    const int g  = lane >> 2, tg = lane & 3;
    const int m0 = blockIdx.y * 128;
    const int n0 = blockIdx.x * 128;
    const int RS = PROJ ? DIM : KD;

    float2 Af[2][4];
    float  Bf[4][4];

    auto load_chunk = [&](int kt) {
#pragma unroll
        for (int t = 0; t < 2; t++) {
            const int k = kt + t * 16 + 2 * tg;
            const float* ab;
            if (PROJ) {
                ab = ((k < DIM) ? A0 : A1)
                     + (size_t)(m0 + warp * 16 + g) * DIM + (k & (DIM - 1));
            } else {
                ab = A0 + (size_t)(m0 + warp * 16 + g) * KD + k;
            }
            Af[t][0] = *(const float2*)(ab);
            Af[t][1] = *(const float2*)(ab + 8 * RS);
            Af[t][2] = *(const float2*)(ab + 8);
            Af[t][3] = *(const float2*)(ab + 8 * RS + 8);
        }
#pragma unroll
        for (int t = 0; t < 4; t++) {
            const int ks = t & 1;
            const int k = kt + ks * 16 + 2 * tg;
            const int ng = warp * 2 + (t >> 1);
            const float* wb = W + (size_t)k * ldb + n0 + ng * 8 + g;
            Bf[t][0] = wb[0];
            Bf[t][1] = wb[ldb];
            Bf[t][2] = wb[8 * ldb];
            Bf[t][3] = wb[9 * ldb];
        }
    };

    auto store_chunk = [&](int bf) {
        uint32_t* A = AsmB + bf * 4096;
        uint32_t* B = BsmB + bf * 4096;
#pragma unroll
        for (int t = 0; t < 2; t++) {
            uint32_t h[4], l[4];
            split2(Af[t][0].x, Af[t][0].y, h[0], l[0]);
            split2(Af[t][1].x, Af[t][1].y, h[1], l[1]);
            split2(Af[t][2].x, Af[t][2].y, h[2], l[2]);
            split2(Af[t][3].x, Af[t][3].y, h[3], l[3]);
            uint4 ph = { h[0], h[1], h[2], h[3] };
            uint4 pl = { l[0], l[1], l[2], l[3] };
            *(uint4*)&A[warp * 512 + t * 256 + lane * 4]       = ph;
            *(uint4*)&A[warp * 512 + t * 256 + 128 + lane * 4] = pl;
        }
#pragma unroll
        for (int t = 0; t < 4; t++) {
            const int ng = warp * 2 + (t >> 1), ks = t & 1;
            uint32_t h0, l0, h1, l1;
            split2(Bf[t][0], Bf[t][1], h0, l0);
            split2(Bf[t][2], Bf[t][3], h1, l1);
            uint4 pk = { h0, h1, l0, l1 };
            *(uint4*)&B[ng * 256 + ks * 128 + lane * 4] = pk;
        }
    };

    float C[2][8][4];
#pragma unroll
    for (int mg = 0; mg < 2; mg++)
#pragma unroll
        for (int ng = 0; ng < 8; ng++)
#pragma unroll
            for (int e = 0; e < 4; e++) C[mg][ng][e] = 0.0f;

    const int NCH = KD / 32;
    load_chunk(0);
    store_chunk(0);
    __syncthreads();

    for (int ch = 0; ch < NCH; ++ch) {
        const int cur = ch & 1;
        if (ch + 1 < NCH) load_chunk((ch + 1) * 32);
        const uint32_t* A = AsmB + cur * 4096;
        const uint32_t* B = BsmB + cur * 4096;
#pragma unroll
        for (int ks = 0; ks < 2; ks++) {
            uint4 ah0 = *(const uint4*)&A[(wm * 2 + 0) * 512 + ks * 256 + lane * 4];
            uint4 al0 = *(const uint4*)&A[(wm * 2 + 0) * 512 + ks * 256 + 128 + lane * 4];
            uint4 ah1 = *(const uint4*)&A[(wm * 2 + 1) * 512 + ks * 256 + lane * 4];
            uint4 al1 = *(const uint4*)&A[(wm * 2 + 1) * 512 + ks * 256 + 128 + lane * 4];
#pragma unroll
            for (int ng = 0; ng < 8; ng++) {
                uint4 b = *(const uint4*)&B[(wn * 8 + ng) * 256 + ks * 128 + lane * 4];
                mma_bf16_u4(C[0][ng], ah0, b.x, b.y);
                mma_bf16_u4(C[0][ng], al0, b.x, b.y);
                mma_bf16_u4(C[0][ng], ah0, b.z, b.w);
                mma_bf16_u4(C[1][ng], ah1, b.x, b.y);
                mma_bf16_u4(C[1][ng], al1, b.x, b.y);
                mma_bf16_u4(C[1][ng], ah1, b.z, b.w);
            }
        }
        if (ch + 1 < NCH) store_chunk(cur ^ 1);   // other buffer: no hazard
        __syncthreads();
    }

    float bb[8][2];
#pragma unroll
    for (int ng = 0; ng < 8; ng++) {
        const int n = n0 + wn * 64 + ng * 8 + 2 * tg;
        bb[ng][0] = bias[n];
        bb[ng][1] = bias[n + 1];
    }

    if (PROJ) {
        const int h = (n0 + wn * 64) >> 6;
#pragma unroll
        for (int mg = 0; mg < 2; mg++) {
#pragma unroll
            for (int half = 0; half < 2; half++) {
                const int m = m0 + wm * 32 + mg * 16 + g + half * 8;
                const int b = m >> 11;
                const int s = m & (SEQ - 1);
                float v[16];
#pragma unroll
                for (int ng = 0; ng < 8; ng++) {
                    v[2 * ng]     = C[mg][ng][half * 2]     + bb[ng][0];
                    v[2 * ng + 1] = C[mg][ng][half * 2 + 1] + bb[ng][1];
                }
                if (do_sm) {
                    float mx = v[0];
#pragma unroll
                    for (int e = 1; e < 16; e++) mx = fmaxf(mx, v[e]);
                    mx = fmaxf(mx, __shfl_xor_sync(0xffffffffu, mx, 1));
                    mx = fmaxf(mx, __shfl_xor_sync(0xffffffffu, mx, 2));
                    float sum = 0.0f;
#pragma unroll
                    for (int e = 0; e < 16; e++) { v[e] = __expf(v[e] - mx); sum += v[e]; }
                    sum += __shfl_xor_sync(0xffffffffu, sum, 1);
                    sum += __shfl_xor_sync(0xffffffffu, sum, 2);
                    const float inv = 1.0f / sum;
#pragma unroll
                    for (int e = 0; e < 16; e++) v[e] = sqrtf(v[e] * inv);
                }
                float* dst = out + ((size_t)(b * NH + h) * SEQ + s) * HD;
#pragma unroll
                for (int ng = 0; ng < 8; ng++) {
                    float2 t = { v[2 * ng], v[2 * ng + 1] };
                    *(float2*)(dst + ng * 8 + 2 * tg) = t;
                }
            }
        }
    } else {
#pragma unroll
        for (int mg = 0; mg < 2; mg++) {
#pragma unroll
            for (int half = 0; half < 2; half++) {
                const int m = m0 + wm * 32 + mg * 16 + g + half * 8;
                float* dst = out + (size_t)m * ldout + n0 + wn * 64;
#pragma unroll
                for (int ng = 0; ng < 8; ng++) {
                    float2 t = { C[mg][ng][half * 2]     + bb[ng][0],
                                 C[mg][ng][half * 2 + 1] + bb[ng][1] };
                    *(float2*)(dst + ng * 8 + 2 * tg) = t;
                }
            }
        }
    }
}

// Fused Q/K/V projection: blockIdx.z selects weight/bias/output.
__global__ __launch_bounds__(256) void proj_qkv(
    const float* __restrict__ xr, const float* __restrict__ xi,
    const float* __restrict__ Wq, const float* __restrict__ Wk,
    const float* __restrict__ Wv,
    const float* __restrict__ bq, const float* __restrict__ bk,
    const float* __restrict__ bv,
    float* __restrict__ Q, float* __restrict__ K, float* __restrict__ V)
{
    const int z = blockIdx.z;
    const float* W = (z == 0) ? Wq : (z == 1) ? Wk : Wv;
    const float* b = (z == 0) ? bq : (z == 1) ? bk : bv;
    float* o = (z == 0) ? Q : (z == 1) ? K : V;
    gemm_body<KIN, true>(xr, xi, W, DIM, b, o, 0, z < 2);
}

__global__ __launch_bounds__(256) void out_gemm(
    const float* __restrict__ A, const float* __restrict__ W,
    const float* __restrict__ bias, float* __restrict__ out)
{
    gemm_body<DIM, false>(A, nullptr, W, KIN, bias, out, KIN, 0);
}

// ---------------------------------------------------------------------------
// Attention: 256 threads, 128 i-rows/block, double-buffered staging,
// ONE barrier per j-tile. Dynamic smem 64 KB:
//   Qs[2][8][4][128] then Vs[2][8][4][128] (buf stride 4096 u32 each).
// ---------------------------------------------------------------------------
__global__ __launch_bounds__(256) void attn_tc(
    const float* __restrict__ sp, const float* __restrict__ sq,
    const float* __restrict__ V,  float* __restrict__ out)
{
    extern __shared__ uint32_t sm[];
    uint32_t* QsB = sm;            // [2][8][4][128]
    uint32_t* VsB = sm + 8192;     // [2][8][4][128]

    const int tid  = threadIdx.x;
    const int warp = tid >> 5;
    const int lane = tid & 31;
    const int r    = lane >> 2;
    const int cq   = lane & 3;
    const int bh   = blockIdx.y;
    const int i0   = blockIdx.x * 128;

    const float* spb = sp + (size_t)bh * SEQ * HD;
    const float* sqb = sq + (size_t)bh * SEQ * HD;
    const float* Vb  = V  + (size_t)bh * SEQ * HD;

    // --- preload sp A-frags (register-resident) ---
    uint32_t Ahi[4][4], Alo[4][4];
    const int row0 = i0 + warp * 16 + r;
    const int row1 = row0 + 8;
#pragma unroll
    for (int ks = 0; ks < 4; ks++) {
        float2 v00 = *(const float2*)(spb + (size_t)row0 * HD + ks * 16 + 2 * cq);
        float2 v01 = *(const float2*)(spb + (size_t)row0 * HD + ks * 16 + 2 * cq + 8);
        float2 v10 = *(const float2*)(spb + (size_t)row1 * HD + ks * 16 + 2 * cq);
        float2 v11 = *(const float2*)(spb + (size_t)row1 * HD + ks * 16 + 2 * cq + 8);
        split2(v00.x, v00.y, Ahi[ks][0], Alo[ks][0]);
        split2(v10.x, v10.y, Ahi[ks][1], Alo[ks][1]);
        split2(v01.x, v01.y, Ahi[ks][2], Alo[ks][2]);
        split2(v11.x, v11.y, Ahi[ks][3], Alo[ks][3]);
    }

    const u64t K9 = dup2f(-2.0705e-4f);
    const u64t K8 = dup2f(-2.6002e-4f);
    const u64t K7 = dup2f(-6.2160e-4f);
    const u64t K6 = dup2f(-1.52229e-3f);
    const u64t K5 = dup2f(-3.84800e-3f);
    const u64t K4 = dup2f(-1.015873e-2f);
    const u64t K3 = dup2f(-2.8571429e-2f);
    const u64t K2 = dup2f(-8.8888889e-2f);
    const u64t K1 = dup2f(-0.33333333f);
    const u64t K0 = dup2f(-2.0f);
    const u64t CM1 = dup2f(-1.0f);
    const u64t CP1 = dup2f(1.0f);

    float2 Qf[4][2];
    float  Vf[4][4];

    auto load_tile = [&](int j0) {
#pragma unroll
        for (int ks = 0; ks < 4; ks++) {
            const float* src = sqb + (size_t)(j0 + warp * 8 + r) * HD + ks * 16 + 2 * cq;
            Qf[ks][0] = *(const float2*)(src);
            Qf[ks][1] = *(const float2*)(src + 8);
        }
#pragma unroll
        for (int js = 0; js < 4; js++) {
            const float* vsrc = Vb + (size_t)(j0 + js * 16 + 2 * cq) * HD + warp * 8 + r;
            Vf[js][0] = vsrc[0];
            Vf[js][1] = vsrc[HD];
            Vf[js][2] = vsrc[8 * HD];
            Vf[js][3] = vsrc[9 * HD];
        }
    };

    auto store_tile = [&](int bf) {
        uint32_t* Q = QsB + bf * 4096;
        uint32_t* Vv = VsB + bf * 4096;
#pragma unroll
        for (int ks = 0; ks < 4; ks++) {
            uint32_t h0, l0, h1, l1;
            split2(Qf[ks][0].x, Qf[ks][0].y, h0, l0);
            split2(Qf[ks][1].x, Qf[ks][1].y, h1, l1);
            uint4 pk = { h0, h1, l0, l1 };
            *(uint4*)&Q[warp * 512 + ks * 128 + lane * 4] = pk;
        }
#pragma unroll
        for (int js = 0; js < 4; js++) {
            uint32_t h0, l0, h1, l1;
            split2(Vf[js][0], Vf[js][1], h0, l0);
            split2(Vf[js][2], Vf[js][3], h1, l1);
            uint4 pk = { h0, h1, l0, l1 };
            *(uint4*)&Vv[warp * 512 + js * 128 + lane * 4] = pk;
        }
    };

    float o[8][4];
#pragma unroll
    for (int dg = 0; dg < 8; dg++)
#pragma unroll
        for (int e = 0; e < 4; e++) o[dg][e] = 0.0f;
    float den0 = 0.0f, den1 = 0.0f;

    load_tile(0);
    store_tile(0);
    __syncthreads();

    const int NT = SEQ / 64;   // 32
    for (int t = 0; t < NT; ++t) {
        const int cur = t & 1;
        if (t + 1 < NT) load_tile((t + 1) * 64);
        const uint32_t* Q = QsB + cur * 4096;
        const uint32_t* Vv = VsB + cur * 4096;

        // --- bc MMAs + transform -> register-resident w A-frags ---
        uint32_t Whi[4][4], Wlo[4][4];
#pragma unroll
        for (int jg = 0; jg < 8; jg++) {
            float acc[4] = { 0.0f, 0.0f, 0.0f, 0.0f };
#pragma unroll
            for (int ks = 0; ks < 4; ks++) {
                uint4 q = *(const uint4*)&Q[jg * 512 + ks * 128 + lane * 4];
                mma_bf16(acc, Ahi[ks], q.x, q.y);
                mma_bf16(acc, Alo[ks], q.x, q.y);
                mma_bf16(acc, Ahi[ks], q.z, q.w);
            }
            u64t ua = fma2(pk2(acc[0], acc[1]), CM1, CP1);
            u64t ub = fma2(pk2(acc[2], acc[3]), CM1, CP1);
            u64t ga = K9, gb = K9;
            ga = fma2(ga, ua, K8);  gb = fma2(gb, ub, K8);
            ga = fma2(ga, ua, K7);  gb = fma2(gb, ub, K7);
            ga = fma2(ga, ua, K6);  gb = fma2(gb, ub, K6);
            ga = fma2(ga, ua, K5);  gb = fma2(gb, ub, K5);
            ga = fma2(ga, ua, K4);  gb = fma2(gb, ub, K4);
            ga = fma2(ga, ua, K3);  gb = fma2(gb, ub, K3);
            ga = fma2(ga, ua, K2);  gb = fma2(gb, ub, K2);
            ga = fma2(ga, ua, K1);  gb = fma2(gb, ub, K1);
            ga = fma2(ga, ua, K0);  gb = fma2(gb, ub, K0);
            ga = mul2(ga, ua);      gb = mul2(gb, ub);
            float2 gA = unpk(ga), gB = unpk(gb);
            float w0 = __expf(gA.x), w1 = __expf(gA.y);
            float w2 = __expf(gB.x), w3 = __expf(gB.y);
            den0 += w0 + w1;
            den1 += w2 + w3;
            const int ks = jg >> 1, up = (jg & 1) << 1;
            split2(w0, w1, Whi[ks][up + 0], Wlo[ks][up + 0]);
            split2(w2, w3, Whi[ks][up + 1], Wlo[ks][up + 1]);
        }

        // --- o += w @ V ---
#pragma unroll
        for (int dg = 0; dg < 8; dg++) {
#pragma unroll
            for (int js = 0; js < 4; js++) {
                uint4 v = *(const uint4*)&Vv[dg * 512 + js * 128 + lane * 4];
                mma_bf16(o[dg], Whi[js], v.x, v.y);
                mma_bf16(o[dg], Wlo[js], v.x, v.y);
                mma_bf16(o[dg], Whi[js], v.z, v.w);
            }
        }

        if (t + 1 < NT) store_tile(cur ^ 1);   // other buffer: no hazard
        __syncthreads();
    }

    den0 += __shfl_xor_sync(0xffffffffu, den0, 1);
    den0 += __shfl_xor_sync(0xffffffffu, den0, 2);
    den1 += __shfl_xor_sync(0xffffffffu, den1, 1);
    den1 += __shfl_xor_sync(0xffffffffu, den1, 2);
    const float inv0 = 1.0f / den0;
    const float inv1 = 1.0f / den1;

    const int b = bh >> 3, hh = bh & 7;
    float* out0 = out + (size_t)(b * SEQ + row0) * DIM + hh * HD;
    float* out1 = out + (size_t)(b * SEQ + row1) * DIM + hh * HD;
#pragma unroll
    for (int dg = 0; dg < 8; dg++) {
        float2 t0 = { o[dg][0] * inv0, o[dg][1] * inv0 };
        float2 t1 = { o[dg][2] * inv1, o[dg][3] * inv1 };
        *(float2*)(out0 + dg * 8 + 2 * cq) = t0;
        *(float2*)(out1 + dg * 8 + 2 * cq) = t1;
    }
}

// ---------------------------------------------------------------------------
extern "C" void kernel_launch(void* const* d_in, const int* in_sizes, int n_in,
                              void* d_out, int out_size)
{
    const float* xr = (const float*)d_in[0];
    const float* xi = (const float*)d_in[1];
    const float* Wq = (const float*)d_in[2];
    const float* bq = (const float*)d_in[3];
    const float* Wk = (const float*)d_in[4];
    const float* bk = (const float*)d_in[5];
    const float* Wv = (const float*)d_in[6];
    const float* bv = (const float*)d_in[7];
    const float* Wo = (const float*)d_in[8];
    const float* bo = (const float*)d_in[9];
    float* out = (float*)d_out;

    float *Qp, *Kp, *Vp, *Ap;
    cudaGetSymbolAddress((void**)&Qp, g_Q);
    cudaGetSymbolAddress((void**)&Kp, g_K);
    cudaGetSymbolAddress((void**)&Vp, g_V);
    cudaGetSymbolAddress((void**)&Ap, g_att);

    const int smem = 65536;
    cudaFuncSetAttribute(proj_qkv, cudaFuncAttributeMaxDynamicSharedMemorySize, smem);
    cudaFuncSetAttribute(out_gemm, cudaFuncAttributeMaxDynamicSharedMemorySize, smem);
    cudaFuncSetAttribute(attn_tc,  cudaFuncAttributeMaxDynamicSharedMemorySize, smem);

    dim3 gp(DIM / 128, MTOT / 128, 3);       // (4, 32, 3) = 384 blocks
    proj_qkv<<<gp, 256, smem>>>(xr, xi, Wq, Wk, Wv, bq, bk, bv, Qp, Kp, Vp);

    dim3 ga(SEQ / 128, BATCH * NH);          // (16, 16) = 256 blocks
    attn_tc<<<ga, 256, smem>>>(Qp, Kp, Vp, Ap);

    dim3 go(KIN / 128, MTOT / 128);          // (8, 32)
    out_gemm<<<go, 256, smem>>>(Ap, Wo, bo, out);
}

// round 10
// speedup vs baseline: 2.5260x; 1.2273x over previous
#include <cuda_runtime.h>
#include <cuda_bf16.h>
#include <math.h>
#include <stdint.h>

#define DIM   512
#define NH    8
#define HD    64
#define SEQ   2048
#define BATCH 2
#define MTOT  (BATCH * SEQ)   // 4096
#define KIN   (2 * DIM)       // 1024

typedef unsigned long long u64t;

// ---- packed f32x2 helpers ----
__device__ __forceinline__ u64t fma2(u64t a, u64t b, u64t c) {
    u64t d; asm("fma.rn.f32x2 %0, %1, %2, %3;" : "=l"(d) : "l"(a), "l"(b), "l"(c));
    return d;
}
__device__ __forceinline__ u64t mul2(u64t a, u64t b) {
    u64t d; asm("mul.rn.f32x2 %0, %1, %2;" : "=l"(d) : "l"(a), "l"(b));
    return d;
}
__device__ __forceinline__ u64t dup2f(float x) {
    u64t r; asm("mov.b64 %0, {%1, %1};" : "=l"(r) : "f"(x));
    return r;
}
__device__ __forceinline__ u64t pk2(float a, float b) {
    u64t r; asm("mov.b64 %0, {%1, %2};" : "=l"(r) : "f"(a), "f"(b));
    return r;
}
__device__ __forceinline__ float2 unpk(u64t v) {
    float lo, hi; asm("mov.b64 {%0, %1}, %2;" : "=f"(lo), "=f"(hi) : "l"(v));
    float2 f; f.x = lo; f.y = hi; return f;
}

// ---- bf16x2 split: (x,y) -> hi pair + lo pair ----
__device__ __forceinline__ void split2(float x, float y, uint32_t& hi, uint32_t& lo) {
    __nv_bfloat162 h;
    h.x = __float2bfloat16(x);
    h.y = __float2bfloat16(y);
    float rx = x - __bfloat162float(h.x);
    float ry = y - __bfloat162float(h.y);
    __nv_bfloat162 l;
    l.x = __float2bfloat16(rx);
    l.y = __float2bfloat16(ry);
    hi = *reinterpret_cast<uint32_t*>(&h);
    lo = *reinterpret_cast<uint32_t*>(&l);
}

// mma.sync m16n8k16 bf16, fp32 accumulate (D==C in place)
__device__ __forceinline__ void mma_bf16(float c[4], const uint32_t a[4],
                                         uint32_t b0, uint32_t b1) {
    asm volatile(
        "mma.sync.aligned.m16n8k16.row.col.f32.bf16.bf16.f32 "
        "{%0,%1,%2,%3}, {%4,%5,%6,%7}, {%8,%9}, {%0,%1,%2,%3};"
        : "+f"(c[0]), "+f"(c[1]), "+f"(c[2]), "+f"(c[3])
        : "r"(a[0]), "r"(a[1]), "r"(a[2]), "r"(a[3]), "r"(b0), "r"(b1));
}
__device__ __forceinline__ void mma_bf16_u4(float c[4], uint4 a,
                                            uint32_t b0, uint32_t b1) {
    uint32_t ar[4] = { a.x, a.y, a.z, a.w };
    mma_bf16(c, ar, b0, b1);
}

// ---------------------------------------------------------------------------
// Pre-split fragment-order global buffers
// ---------------------------------------------------------------------------
__device__ uint32_t g_XA[256 * 64 * 2 * 128];         // x A-frags  [mg][kg][hl][128]
__device__ uint32_t g_WqF[64 * 64 * 128];             // W B-frags [ng][kg][128]
__device__ uint32_t g_WkF[64 * 64 * 128];
__device__ uint32_t g_WvF[64 * 64 * 128];
__device__ uint32_t g_WoF[128 * 32 * 128];
__device__ uint32_t g_QA[16 * 128 * 4 * 2 * 128];     // Q A-frags [bh][sg][ks][hl][128]
__device__ uint32_t g_KF[16 * 32 * 8 * 4 * 128];      // K B-frags [bh][jt][jg][ks][128]
__device__ uint32_t g_VF[16 * 32 * 8 * 4 * 128];      // V B-frags [bh][jt][dg][js][128]
__device__ float    g_V [16 * SEQ * HD];              // V fp32 (repacked to g_VF)
__device__ uint32_t g_AF[256 * 32 * 2 * 128];         // att A-frags [mgg][ksg][hl][128]

// ---------------------------------------------------------------------------
// Prep: x -> A-frag split.  grid(32, 64), 256 thr. warp w: mg = bx*8+w, kg = by.
// ---------------------------------------------------------------------------
__global__ __launch_bounds__(256) void prep_xa(
    const float* __restrict__ xr, const float* __restrict__ xi)
{
    const int lane = threadIdx.x & 31;
    const int warp = threadIdx.x >> 5;
    const int g = lane >> 2, tg = lane & 3;
    const int mg = blockIdx.x * 8 + warp;
    const int kg = blockIdx.y;
    const int m = mg * 16 + g;
    const int k = kg * 16 + 2 * tg;
    const float* base = (k < DIM) ? xr : xi;
    const int kk = k & (DIM - 1);
    float2 f00 = *(const float2*)(base + (size_t)m * DIM + kk);
    float2 f01 = *(const float2*)(base + (size_t)m * DIM + kk + 8);
    float2 f10 = *(const float2*)(base + (size_t)(m + 8) * DIM + kk);
    float2 f11 = *(const float2*)(base + (size_t)(m + 8) * DIM + kk + 8);
    uint32_t h[4], l[4];
    split2(f00.x, f00.y, h[0], l[0]);
    split2(f10.x, f10.y, h[1], l[1]);
    split2(f01.x, f01.y, h[2], l[2]);
    split2(f11.x, f11.y, h[3], l[3]);
    uint32_t* dst = g_XA + ((size_t)(mg * 64 + kg) * 2) * 128 + lane * 4;
    *(uint4*)dst         = make_uint4(h[0], h[1], h[2], h[3]);
    *(uint4*)(dst + 128) = make_uint4(l[0], l[1], l[2], l[3]);
}

// ---------------------------------------------------------------------------
// Prep: W -> B-frag split.  grid(N/8, K/16/8), 256 thr. warp w: ks = by*8+w.
// ---------------------------------------------------------------------------
__global__ __launch_bounds__(256) void prep_w(
    const float* __restrict__ W, int N, int KGC, uint32_t* __restrict__ WF)
{
    const int lane = threadIdx.x & 31;
    const int warp = threadIdx.x >> 5;
    const int g = lane >> 2, tg = lane & 3;
    const int ng = blockIdx.x;
    const int ks = blockIdx.y * 8 + warp;
    const int k = ks * 16 + 2 * tg;
    const int n = ng * 8 + g;
    float b0a = W[(size_t)k * N + n];
    float b0b = W[(size_t)(k + 1) * N + n];
    float b1a = W[(size_t)(k + 8) * N + n];
    float b1b = W[(size_t)(k + 9) * N + n];
    uint32_t h0, l0, h1, l1;
    split2(b0a, b0b, h0, l0);
    split2(b1a, b1b, h1, l1);
    *(uint4*)(WF + (size_t)(ng * KGC + ks) * 128 + lane * 4) = make_uint4(h0, h1, l0, l1);
}

// ---------------------------------------------------------------------------
// Repack V fp32 -> B-frag split.  grid(32 jt, 16 bh), 256 thr; warp = dg.
// ---------------------------------------------------------------------------
__global__ __launch_bounds__(256) void repack_v()
{
    const int lane = threadIdx.x & 31;
    const int dg = threadIdx.x >> 5;
    const int r = lane >> 2, cq = lane & 3;
    const int jt = blockIdx.x, bh = blockIdx.y;
    const float* Vb = g_V + (size_t)bh * SEQ * HD;
    const int j0 = jt * 64;
#pragma unroll
    for (int js = 0; js < 4; js++) {
        const float* vsrc = Vb + (size_t)(j0 + js * 16 + 2 * cq) * HD + dg * 8 + r;
        float v0 = vsrc[0];
        float v1 = vsrc[HD];
        float v2 = vsrc[8 * HD];
        float v3 = vsrc[9 * HD];
        uint32_t h0, l0, h1, l1;
        split2(v0, v1, h0, l0);
        split2(v2, v3, h1, l1);
        *(uint4*)(g_VF + ((size_t)((bh * 32 + jt) * 8 + dg) * 4 + js) * 128 + lane * 4)
            = make_uint4(h0, h1, l0, l1);
    }
}

// ---------------------------------------------------------------------------
// GEMM core: 256 thr, 128m x 128n tile, K in 32-chunks, double-buffered,
// staging = contiguous copies of pre-split frags. Result in C[2][8][4].
// ---------------------------------------------------------------------------
template<int KGC>
__device__ __forceinline__ void gemm_core(
    const uint32_t* __restrict__ XA, const uint32_t* __restrict__ WF,
    float C[2][8][4])
{
    extern __shared__ uint32_t sm[];
    uint32_t* AsmB = sm;            // [2][8][2][256]
    uint32_t* BsmB = sm + 8192;     // [2][16][2][128]

    const int tid  = threadIdx.x;
    const int warp = tid >> 5;
    const int lane = tid & 31;
    const int wm = warp >> 1, wn = warp & 1;
    const int m0 = blockIdx.y * 128;
    const int n0 = blockIdx.x * 128;
    const int mgA = (m0 >> 4) + warp;
    const int ngB = (n0 >> 3);

    uint4 ah[2], al[2], bt[4];

    auto load_chunk = [&](int kt) {
        const int kg0 = kt >> 4;
#pragma unroll
        for (int t = 0; t < 2; t++) {
            const uint32_t* src = XA + ((size_t)(mgA * KGC + kg0 + t) * 2) * 128 + lane * 4;
            ah[t] = *(const uint4*)src;
            al[t] = *(const uint4*)(src + 128);
        }
#pragma unroll
        for (int t = 0; t < 4; t++) {
            const int ng = ngB + warp * 2 + (t >> 1);
            const int kg = kg0 + (t & 1);
            bt[t] = *(const uint4*)(WF + (size_t)(ng * KGC + kg) * 128 + lane * 4);
        }
    };

    auto store_chunk = [&](int bf) {
        uint32_t* A = AsmB + bf * 4096;
        uint32_t* B = BsmB + bf * 4096;
#pragma unroll
        for (int t = 0; t < 2; t++) {
            *(uint4*)&A[warp * 512 + t * 256 + lane * 4]       = ah[t];
            *(uint4*)&A[warp * 512 + t * 256 + 128 + lane * 4] = al[t];
        }
#pragma unroll
        for (int t = 0; t < 4; t++) {
            const int ng = warp * 2 + (t >> 1), ks = t & 1;
            *(uint4*)&B[ng * 256 + ks * 128 + lane * 4] = bt[t];
        }
    };

#pragma unroll
    for (int mg = 0; mg < 2; mg++)
#pragma unroll
        for (int ng = 0; ng < 8; ng++)
#pragma unroll
            for (int e = 0; e < 4; e++) C[mg][ng][e] = 0.0f;

    const int NCH = KGC / 2;
    load_chunk(0);
    store_chunk(0);
    __syncthreads();

    for (int ch = 0; ch < NCH; ++ch) {
        const int cur = ch & 1;
        if (ch + 1 < NCH) load_chunk((ch + 1) * 32);
        const uint32_t* A = AsmB + cur * 4096;
        const uint32_t* B = BsmB + cur * 4096;
#pragma unroll
        for (int ks = 0; ks < 2; ks++) {
            uint4 a0h = *(const uint4*)&A[(wm * 2 + 0) * 512 + ks * 256 + lane * 4];
            uint4 a0l = *(const uint4*)&A[(wm * 2 + 0) * 512 + ks * 256 + 128 + lane * 4];
            uint4 a1h = *(const uint4*)&A[(wm * 2 + 1) * 512 + ks * 256 + lane * 4];
            uint4 a1l = *(const uint4*)&A[(wm * 2 + 1) * 512 + ks * 256 + 128 + lane * 4];
#pragma unroll
            for (int ng = 0; ng < 8; ng++) {
                uint4 b = *(const uint4*)&B[(wn * 8 + ng) * 256 + ks * 128 + lane * 4];
                mma_bf16_u4(C[0][ng], a0h, b.x, b.y);
                mma_bf16_u4(C[0][ng], a0l, b.x, b.y);
                mma_bf16_u4(C[0][ng], a0h, b.z, b.w);
                mma_bf16_u4(C[1][ng], a1h, b.x, b.y);
                mma_bf16_u4(C[1][ng], a1l, b.x, b.y);
                mma_bf16_u4(C[1][ng], a1h, b.z, b.w);
            }
        }
        if (ch + 1 < NCH) store_chunk(cur ^ 1);
        __syncthreads();
    }
}

// ---------------------------------------------------------------------------
// Fused Q/K/V projection. z=0: Q -> A-frag split (g_QA); z=1: K -> B-frag
// split (g_KF); z=2: V -> fp32 (g_V). Softmax-sqrt fused for z<2.
// ---------------------------------------------------------------------------
__global__ __launch_bounds__(256) void proj_qkv(
    const float* __restrict__ bq, const float* __restrict__ bk,
    const float* __restrict__ bv)
{
    const int z = blockIdx.z;
    const uint32_t* WF = (z == 0) ? g_WqF : (z == 1) ? g_WkF : g_WvF;
    const float* bias = (z == 0) ? bq : (z == 1) ? bk : bv;

    float C[2][8][4];
    gemm_core<64>(g_XA, WF, C);

    const int tid  = threadIdx.x;
    const int warp = tid >> 5;
    const int lane = tid & 31;
    const int wm = warp >> 1, wn = warp & 1;
    const int g = lane >> 2, tg = lane & 3;
    const int m0 = blockIdx.y * 128;
    const int n0 = blockIdx.x * 128;
    const int h = (n0 + wn * 64) >> 6;

    float bb[8][2];
#pragma unroll
    for (int ng = 0; ng < 8; ng++) {
        const int n = n0 + wn * 64 + ng * 8 + 2 * tg;
        bb[ng][0] = bias[n];
        bb[ng][1] = bias[n + 1];
    }

#pragma unroll
    for (int mg = 0; mg < 2; mg++) {
        const int mtile = m0 + wm * 32 + mg * 16;
        const int b = mtile >> 11;
        const int stile = mtile & (SEQ - 1);
        const int bh = b * NH + h;
        float v[2][16];
#pragma unroll
        for (int half = 0; half < 2; half++) {
#pragma unroll
            for (int ng = 0; ng < 8; ng++) {
                v[half][2 * ng]     = C[mg][ng][half * 2]     + bb[ng][0];
                v[half][2 * ng + 1] = C[mg][ng][half * 2 + 1] + bb[ng][1];
            }
            if (z < 2) {
                float mx = v[half][0];
#pragma unroll
                for (int e = 1; e < 16; e++) mx = fmaxf(mx, v[half][e]);
                mx = fmaxf(mx, __shfl_xor_sync(0xffffffffu, mx, 1));
                mx = fmaxf(mx, __shfl_xor_sync(0xffffffffu, mx, 2));
                float sum = 0.0f;
#pragma unroll
                for (int e = 0; e < 16; e++) { v[half][e] = __expf(v[half][e] - mx); sum += v[half][e]; }
                sum += __shfl_xor_sync(0xffffffffu, sum, 1);
                sum += __shfl_xor_sync(0xffffffffu, sum, 2);
                const float inv = 1.0f / sum;
#pragma unroll
                for (int e = 0; e < 16; e++) v[half][e] = sqrtf(v[half][e] * inv);
            }
        }

        if (z == 0) {
            // Q: A-frag split, lane-preserving
            const int sg = stile >> 4;
#pragma unroll
            for (int ks = 0; ks < 4; ks++) {
                uint32_t h4[4], l4[4];
                split2(v[0][4 * ks],     v[0][4 * ks + 1], h4[0], l4[0]);   // a0: row g
                split2(v[1][4 * ks],     v[1][4 * ks + 1], h4[1], l4[1]);   // a1: row g+8
                split2(v[0][4 * ks + 2], v[0][4 * ks + 3], h4[2], l4[2]);   // a2
                split2(v[1][4 * ks + 2], v[1][4 * ks + 3], h4[3], l4[3]);   // a3
                uint32_t* dst = g_QA + (((size_t)(bh * 128 + sg) * 4 + ks) * 2) * 128 + lane * 4;
                *(uint4*)dst         = make_uint4(h4[0], h4[1], h4[2], h4[3]);
                *(uint4*)(dst + 128) = make_uint4(l4[0], l4[1], l4[2], l4[3]);
            }
        } else if (z == 1) {
            // K: B-frag split, per-row scatter
#pragma unroll
            for (int half = 0; half < 2; half++) {
                const int s = stile + g + half * 8;
                const int jt = s >> 6, jg = (s >> 3) & 7;
                const int lp = (s & 7) * 4 + tg;
#pragma unroll
                for (int ks = 0; ks < 4; ks++) {
                    uint32_t h0, l0, h1, l1;
                    split2(v[half][4 * ks],     v[half][4 * ks + 1], h0, l0);
                    split2(v[half][4 * ks + 2], v[half][4 * ks + 3], h1, l1);
                    *(uint4*)(g_KF + (((size_t)((bh * 32 + jt) * 8 + jg) * 4 + ks)) * 128 + lp * 4)
                        = make_uint4(h0, h1, l0, l1);
                }
            }
        } else {
            // V: fp32
#pragma unroll
            for (int half = 0; half < 2; half++) {
                const int s = stile + g + half * 8;
                float* dst = g_V + ((size_t)bh * SEQ + s) * HD;
#pragma unroll
                for (int ng = 0; ng < 8; ng++) {
                    float2 t = { v[half][2 * ng], v[half][2 * ng + 1] };
                    *(float2*)(dst + ng * 8 + 2 * tg) = t;
                }
            }
        }
    }
}

// ---------------------------------------------------------------------------
// Output GEMM: reads pre-split att frags (g_AF) and WoF; writes fp32 out.
// ---------------------------------------------------------------------------
__global__ __launch_bounds__(256) void out_gemm(
    const float* __restrict__ bias, float* __restrict__ out)
{
    float C[2][8][4];
    gemm_core<32>(g_AF, g_WoF, C);

    const int tid  = threadIdx.x;
    const int warp = tid >> 5;
    const int lane = tid & 31;
    const int wm = warp >> 1, wn = warp & 1;
    const int g = lane >> 2, tg = lane & 3;
    const int m0 = blockIdx.y * 128;
    const int n0 = blockIdx.x * 128;

    float bb[8][2];
#pragma unroll
    for (int ng = 0; ng < 8; ng++) {
        const int n = n0 + wn * 64 + ng * 8 + 2 * tg;
        bb[ng][0] = bias[n];
        bb[ng][1] = bias[n + 1];
    }
#pragma unroll
    for (int mg = 0; mg < 2; mg++) {
#pragma unroll
        for (int half = 0; half < 2; half++) {
            const int m = m0 + wm * 32 + mg * 16 + g + half * 8;
            float* dst = out + (size_t)m * KIN + n0 + wn * 64;
#pragma unroll
            for (int ng = 0; ng < 8; ng++) {
                float2 t = { C[mg][ng][half * 2]     + bb[ng][0],
                             C[mg][ng][half * 2 + 1] + bb[ng][1] };
                *(float2*)(dst + ng * 8 + 2 * tg) = t;
            }
        }
    }
}

// ---------------------------------------------------------------------------
// Attention: 256 thr, 128 i-rows/block, staging = contiguous copies from
// pre-split KF/VF; epilogue writes att in A-frag split form (g_AF).
// ---------------------------------------------------------------------------
__global__ __launch_bounds__(256) void attn_tc()
{
    extern __shared__ uint32_t sm[];
    uint32_t* QsB = sm;            // [2][8][4][128]
    uint32_t* VsB = sm + 8192;

    const int tid  = threadIdx.x;
    const int warp = tid >> 5;
    const int lane = tid & 31;
    const int bh   = blockIdx.y;
    const int i0   = blockIdx.x * 128;

    // --- preload sp A-frags from g_QA ---
    uint4 AhiV[4], AloV[4];
    const int sg = (i0 >> 4) + warp;
#pragma unroll
    for (int ks = 0; ks < 4; ks++) {
        const uint32_t* src = g_QA + (((size_t)(bh * 128 + sg) * 4 + ks) * 2) * 128 + lane * 4;
        AhiV[ks] = *(const uint4*)src;
        AloV[ks] = *(const uint4*)(src + 128);
    }

    const u64t K9 = dup2f(-2.0705e-4f);
    const u64t K8 = dup2f(-2.6002e-4f);
    const u64t K7 = dup2f(-6.2160e-4f);
    const u64t K6 = dup2f(-1.52229e-3f);
    const u64t K5 = dup2f(-3.84800e-3f);
    const u64t K4 = dup2f(-1.015873e-2f);
    const u64t K3 = dup2f(-2.8571429e-2f);
    const u64t K2 = dup2f(-8.8888889e-2f);
    const u64t K1 = dup2f(-0.33333333f);
    const u64t K0 = dup2f(-2.0f);
    const u64t CM1 = dup2f(-1.0f);
    const u64t CP1 = dup2f(1.0f);

    uint4 Qt[4], Vt[4];
    auto load_tile = [&](int jt) {
        const uint32_t* qs = g_KF + ((size_t)((bh * 32 + jt) * 8 + warp) * 4) * 128 + lane * 4;
        const uint32_t* vs = g_VF + ((size_t)((bh * 32 + jt) * 8 + warp) * 4) * 128 + lane * 4;
#pragma unroll
        for (int ks = 0; ks < 4; ks++) {
            Qt[ks] = *(const uint4*)(qs + ks * 128);
            Vt[ks] = *(const uint4*)(vs + ks * 128);
        }
    };
    auto store_tile = [&](int bf) {
        uint32_t* Q = QsB + bf * 4096;
        uint32_t* Vv = VsB + bf * 4096;
#pragma unroll
        for (int ks = 0; ks < 4; ks++) {
            *(uint4*)&Q[warp * 512 + ks * 128 + lane * 4]  = Qt[ks];
            *(uint4*)&Vv[warp * 512 + ks * 128 + lane * 4] = Vt[ks];
        }
    };

    float o[8][4];
#pragma unroll
    for (int dg = 0; dg < 8; dg++)
#pragma unroll
        for (int e = 0; e < 4; e++) o[dg][e] = 0.0f;
    float den0 = 0.0f, den1 = 0.0f;

    load_tile(0);
    store_tile(0);
    __syncthreads();

    const int NT = SEQ / 64;   // 32
    for (int t = 0; t < NT; ++t) {
        const int cur = t & 1;
        if (t + 1 < NT) load_tile(t + 1);
        const uint32_t* Q = QsB + cur * 4096;
        const uint32_t* Vv = VsB + cur * 4096;

        uint32_t Whi[4][4], Wlo[4][4];
#pragma unroll
        for (int jg = 0; jg < 8; jg++) {
            float acc[4] = { 0.0f, 0.0f, 0.0f, 0.0f };
#pragma unroll
            for (int ks = 0; ks < 4; ks++) {
                uint4 q = *(const uint4*)&Q[jg * 512 + ks * 128 + lane * 4];
                mma_bf16_u4(acc, AhiV[ks], q.x, q.y);
                mma_bf16_u4(acc, AloV[ks], q.x, q.y);
                mma_bf16_u4(acc, AhiV[ks], q.z, q.w);
            }
            u64t ua = fma2(pk2(acc[0], acc[1]), CM1, CP1);
            u64t ub = fma2(pk2(acc[2], acc[3]), CM1, CP1);
            u64t ga = K9, gb = K9;
            ga = fma2(ga, ua, K8);  gb = fma2(gb, ub, K8);
            ga = fma2(ga, ua, K7);  gb = fma2(gb, ub, K7);
            ga = fma2(ga, ua, K6);  gb = fma2(gb, ub, K6);
            ga = fma2(ga, ua, K5);  gb = fma2(gb, ub, K5);
            ga = fma2(ga, ua, K4);  gb = fma2(gb, ub, K4);
            ga = fma2(ga, ua, K3);  gb = fma2(gb, ub, K3);
            ga = fma2(ga, ua, K2);  gb = fma2(gb, ub, K2);
            ga = fma2(ga, ua, K1);  gb = fma2(gb, ub, K1);
            ga = fma2(ga, ua, K0);  gb = fma2(gb, ub, K0);
            ga = mul2(ga, ua);      gb = mul2(gb, ub);
            float2 gA = unpk(ga), gB = unpk(gb);
            float w0 = __expf(gA.x), w1 = __expf(gA.y);
            float w2 = __expf(gB.x), w3 = __expf(gB.y);
            den0 += w0 + w1;
            den1 += w2 + w3;
            const int ks = jg >> 1, up = (jg & 1) << 1;
            split2(w0, w1, Whi[ks][up + 0], Wlo[ks][up + 0]);
            split2(w2, w3, Whi[ks][up + 1], Wlo[ks][up + 1]);
        }

#pragma unroll
        for (int dg = 0; dg < 8; dg++) {
#pragma unroll
            for (int js = 0; js < 4; js++) {
                uint4 v = *(const uint4*)&Vv[dg * 512 + js * 128 + lane * 4];
                mma_bf16(o[dg], Whi[js], v.x, v.y);
                mma_bf16(o[dg], Wlo[js], v.x, v.y);
                mma_bf16(o[dg], Whi[js], v.z, v.w);
            }
        }

        if (t + 1 < NT) store_tile(cur ^ 1);
        __syncthreads();
    }

    den0 += __shfl_xor_sync(0xffffffffu, den0, 1);
    den0 += __shfl_xor_sync(0xffffffffu, den0, 2);
    den1 += __shfl_xor_sync(0xffffffffu, den1, 1);
    den1 += __shfl_xor_sync(0xffffffffu, den1, 2);
    const float inv0 = 1.0f / den0;
    const float inv1 = 1.0f / den1;

    // epilogue: att in A-frag split form (C-frag layout == A-frag layout)
    const int b = bh >> 3, hh = bh & 7;
    const int mgg = b * 128 + (i0 >> 4) + warp;
#pragma unroll
    for (int k = 0; k < 4; k++) {
        uint32_t h4[4], l4[4];
        split2(o[2 * k][0] * inv0,     o[2 * k][1] * inv0,     h4[0], l4[0]);  // a0
        split2(o[2 * k][2] * inv1,     o[2 * k][3] * inv1,     h4[1], l4[1]);  // a1
        split2(o[2 * k + 1][0] * inv0, o[2 * k + 1][1] * inv0, h4[2], l4[2]);  // a2
        split2(o[2 * k + 1][2] * inv1, o[2 * k + 1][3] * inv1, h4[3], l4[3]);  // a3
        const int ksg = hh * 4 + k;
        uint32_t* dst = g_AF + ((size_t)(mgg * 32 + ksg) * 2) * 128 + lane * 4;
        *(uint4*)dst         = make_uint4(h4[0], h4[1], h4[2], h4[3]);
        *(uint4*)(dst + 128) = make_uint4(l4[0], l4[1], l4[2], l4[3]);
    }
}

// ---------------------------------------------------------------------------
extern "C" void kernel_launch(void* const* d_in, const int* in_sizes, int n_in,
                              void* d_out, int out_size)
{
    const float* xr = (const float*)d_in[0];
    const float* xi = (const float*)d_in[1];
    const float* Wq = (const float*)d_in[2];
    const float* bq = (const float*)d_in[3];
    const float* Wk = (const float*)d_in[4];
    const float* bk = (const float*)d_in[5];
    const float* Wv = (const float*)d_in[6];
    const float* bv = (const float*)d_in[7];
    const float* Wo = (const float*)d_in[8];
    const float* bo = (const float*)d_in[9];
    float* out = (float*)d_out;

    uint32_t *WqF, *WkF, *WvF, *WoF;
    cudaGetSymbolAddress((void**)&WqF, g_WqF);
    cudaGetSymbolAddress((void**)&WkF, g_WkF);
    cudaGetSymbolAddress((void**)&WvF, g_WvF);
    cudaGetSymbolAddress((void**)&WoF, g_WoF);

    const int smem = 65536;
    cudaFuncSetAttribute(proj_qkv, cudaFuncAttributeMaxDynamicSharedMemorySize, smem);
    cudaFuncSetAttribute(out_gemm, cudaFuncAttributeMaxDynamicSharedMemorySize, smem);
    cudaFuncSetAttribute(attn_tc,  cudaFuncAttributeMaxDynamicSharedMemorySize, smem);

    prep_xa<<<dim3(32, 64), 256>>>(xr, xi);
    prep_w<<<dim3(64, 8), 256>>>(Wq, DIM, 64, WqF);
    prep_w<<<dim3(64, 8), 256>>>(Wk, DIM, 64, WkF);
    prep_w<<<dim3(64, 8), 256>>>(Wv, DIM, 64, WvF);
    prep_w<<<dim3(128, 4), 256>>>(Wo, KIN, 32, WoF);

    dim3 gp(DIM / 128, MTOT / 128, 3);       // (4, 32, 3)
    proj_qkv<<<gp, 256, smem>>>(bq, bk, bv);

    repack_v<<<dim3(32, 16), 256>>>();

    dim3 ga(SEQ / 128, BATCH * NH);          // (16, 16)
    attn_tc<<<ga, 256, smem>>>();

    dim3 go(KIN / 128, MTOT / 128);          // (8, 32)
    out_gemm<<<go, 256, smem>>>(bo, out);
}

// round 12
// speedup vs baseline: 2.8433x; 1.1256x over previous
#include <cuda_runtime.h>
#include <cuda_bf16.h>
#include <math.h>
#include <stdint.h>

#define DIM   512
#define NH    8
#define HD    64
#define SEQ   2048
#define BATCH 2
#define MTOT  (BATCH * SEQ)   // 4096
#define KIN   (2 * DIM)       // 1024

typedef unsigned long long u64t;

// ---- packed f32x2 helpers ----
__device__ __forceinline__ u64t fma2(u64t a, u64t b, u64t c) {
    u64t d; asm("fma.rn.f32x2 %0, %1, %2, %3;" : "=l"(d) : "l"(a), "l"(b), "l"(c));
    return d;
}
__device__ __forceinline__ u64t mul2(u64t a, u64t b) {
    u64t d; asm("mul.rn.f32x2 %0, %1, %2;" : "=l"(d) : "l"(a), "l"(b));
    return d;
}
__device__ __forceinline__ u64t dup2f(float x) {
    u64t r; asm("mov.b64 %0, {%1, %1};" : "=l"(r) : "f"(x));
    return r;
}
__device__ __forceinline__ u64t pk2(float a, float b) {
    u64t r; asm("mov.b64 %0, {%1, %2};" : "=l"(r) : "f"(a), "f"(b));
    return r;
}
__device__ __forceinline__ float2 unpk(u64t v) {
    float lo, hi; asm("mov.b64 {%0, %1}, %2;" : "=f"(lo), "=f"(hi) : "l"(v));
    float2 f; f.x = lo; f.y = hi; return f;
}

// ---- bf16x2 split ----
__device__ __forceinline__ void split2(float x, float y, uint32_t& hi, uint32_t& lo) {
    __nv_bfloat162 h;
    h.x = __float2bfloat16(x);
    h.y = __float2bfloat16(y);
    float rx = x - __bfloat162float(h.x);
    float ry = y - __bfloat162float(h.y);
    __nv_bfloat162 l;
    l.x = __float2bfloat16(rx);
    l.y = __float2bfloat16(ry);
    hi = *reinterpret_cast<uint32_t*>(&h);
    lo = *reinterpret_cast<uint32_t*>(&l);
}

// ---- mma.sync m16n8k16 bf16 ----
__device__ __forceinline__ void mma_bf16(float c[4], const uint32_t a[4],
                                         uint32_t b0, uint32_t b1) {
    asm volatile(
        "mma.sync.aligned.m16n8k16.row.col.f32.bf16.bf16.f32 "
        "{%0,%1,%2,%3}, {%4,%5,%6,%7}, {%8,%9}, {%0,%1,%2,%3};"
        : "+f"(c[0]), "+f"(c[1]), "+f"(c[2]), "+f"(c[3])
        : "r"(a[0]), "r"(a[1]), "r"(a[2]), "r"(a[3]), "r"(b0), "r"(b1));
}
__device__ __forceinline__ void mma_bf16_u4(float c[4], uint4 a,
                                            uint32_t b0, uint32_t b1) {
    uint32_t ar[4] = { a.x, a.y, a.z, a.w };
    mma_bf16(c, ar, b0, b1);
}

// ---- cp.async 16B ----
__device__ __forceinline__ void cp16(void* smem_dst, const void* gsrc) {
    uint32_t s = (uint32_t)__cvta_generic_to_shared(smem_dst);
    asm volatile("cp.async.cg.shared.global [%0], [%1], 16;" :: "r"(s), "l"(gsrc));
}
#define CP_COMMIT() asm volatile("cp.async.commit_group;")
#define CP_WAIT0()  asm volatile("cp.async.wait_group 0;" ::: "memory")

// ---------------------------------------------------------------------------
// Pre-split fragment-order global buffers
// ---------------------------------------------------------------------------
__device__ uint32_t g_XA[256 * 64 * 2 * 128];
__device__ uint32_t g_WqF[64 * 64 * 128];
__device__ uint32_t g_WkF[64 * 64 * 128];
__device__ uint32_t g_WvF[64 * 64 * 128];
__device__ uint32_t g_WoF[128 * 32 * 128];
__device__ uint32_t g_QA[16 * 128 * 4 * 2 * 128];
__device__ uint32_t g_KF[16 * 32 * 8 * 4 * 128];
__device__ uint32_t g_VF[16 * 32 * 8 * 4 * 128];
__device__ float    g_V [16 * SEQ * HD];
__device__ uint32_t g_AF[256 * 32 * 2 * 128];

// ---------------------------------------------------------------------------
// Prep: x -> A-frag split.  grid(32, 64), 256 thr.
// ---------------------------------------------------------------------------
__global__ __launch_bounds__(256) void prep_xa(
    const float* __restrict__ xr, const float* __restrict__ xi)
{
    const int lane = threadIdx.x & 31;
    const int warp = threadIdx.x >> 5;
    const int g = lane >> 2, tg = lane & 3;
    const int mg = blockIdx.x * 8 + warp;
    const int kg = blockIdx.y;
    const int m = mg * 16 + g;
    const int k = kg * 16 + 2 * tg;
    const float* base = (k < DIM) ? xr : xi;
    const int kk = k & (DIM - 1);
    float2 f00 = *(const float2*)(base + (size_t)m * DIM + kk);
    float2 f01 = *(const float2*)(base + (size_t)m * DIM + kk + 8);
    float2 f10 = *(const float2*)(base + (size_t)(m + 8) * DIM + kk);
    float2 f11 = *(const float2*)(base + (size_t)(m + 8) * DIM + kk + 8);
    uint32_t h[4], l[4];
    split2(f00.x, f00.y, h[0], l[0]);
    split2(f10.x, f10.y, h[1], l[1]);
    split2(f01.x, f01.y, h[2], l[2]);
    split2(f11.x, f11.y, h[3], l[3]);
    uint32_t* dst = g_XA + ((size_t)(mg * 64 + kg) * 2) * 128 + lane * 4;
    *(uint4*)dst         = make_uint4(h[0], h[1], h[2], h[3]);
    *(uint4*)(dst + 128) = make_uint4(l[0], l[1], l[2], l[3]);
}

// ---------------------------------------------------------------------------
// Prep: all four W -> B-frag split in one launch. grid(64, 8, 4), 256 thr.
// ---------------------------------------------------------------------------
__global__ __launch_bounds__(256) void prep_w_all(
    const float* __restrict__ Wq, const float* __restrict__ Wk,
    const float* __restrict__ Wv, const float* __restrict__ Wo)
{
    const int lane = threadIdx.x & 31;
    const int warp = threadIdx.x >> 5;
    const int g = lane >> 2, tg = lane & 3;
    const int z = blockIdx.z;

    int ng, ks, N, KGC;
    const float* W;
    uint32_t* WF;
    if (z < 3) {
        ng = blockIdx.x;
        ks = blockIdx.y * 8 + warp;
        N = DIM; KGC = 64;
        W  = (z == 0) ? Wq : (z == 1) ? Wk : Wv;
        WF = (z == 0) ? g_WqF : (z == 1) ? g_WkF : g_WvF;
    } else {
        const int id = blockIdx.y * 64 + blockIdx.x;   // 0..511
        ng = id >> 2;
        ks = (id & 3) * 8 + warp;
        N = KIN; KGC = 32;
        W = Wo; WF = g_WoF;
    }

    const int k = ks * 16 + 2 * tg;
    const int n = ng * 8 + g;
    float b0a = W[(size_t)k * N + n];
    float b0b = W[(size_t)(k + 1) * N + n];
    float b1a = W[(size_t)(k + 8) * N + n];
    float b1b = W[(size_t)(k + 9) * N + n];
    uint32_t h0, l0, h1, l1;
    split2(b0a, b0b, h0, l0);
    split2(b1a, b1b, h1, l1);
    *(uint4*)(WF + (size_t)(ng * KGC + ks) * 128 + lane * 4) = make_uint4(h0, h1, l0, l1);
}

// ---------------------------------------------------------------------------
// Repack V fp32 -> B-frag split.  grid(32 jt, 16 bh), 256 thr.
// ---------------------------------------------------------------------------
__global__ __launch_bounds__(256) void repack_v()
{
    const int lane = threadIdx.x & 31;
    const int dg = threadIdx.x >> 5;
    const int r = lane >> 2, cq = lane & 3;
    const int jt = blockIdx.x, bh = blockIdx.y;
    const float* Vb = g_V + (size_t)bh * SEQ * HD;
    const int j0 = jt * 64;
#pragma unroll
    for (int js = 0; js < 4; js++) {
        const float* vsrc = Vb + (size_t)(j0 + js * 16 + 2 * cq) * HD + dg * 8 + r;
        float v0 = vsrc[0];
        float v1 = vsrc[HD];
        float v2 = vsrc[8 * HD];
        float v3 = vsrc[9 * HD];
        uint32_t h0, l0, h1, l1;
        split2(v0, v1, h0, l0);
        split2(v2, v3, h1, l1);
        *(uint4*)(g_VF + ((size_t)((bh * 32 + jt) * 8 + dg) * 4 + js) * 128 + lane * 4)
            = make_uint4(h0, h1, l0, l1);
    }
}

// ---------------------------------------------------------------------------
// GEMM core: cp.async staging, double-buffered, one barrier per K-chunk.
// Dynamic smem 64 KB total.
// ---------------------------------------------------------------------------
template<int KGC>
__device__ __forceinline__ void gemm_core(
    const uint32_t* __restrict__ XA, const uint32_t* __restrict__ WF,
    float C[2][8][4])
{
    extern __shared__ uint32_t sm[];
    uint32_t* AsmB = sm;            // [2][8][2][256] = 8192 u32
    uint32_t* BsmB = sm + 8192;     // [2][16][2][128] = 8192 u32

    const int tid  = threadIdx.x;
    const int warp = tid >> 5;
    const int lane = tid & 31;
    const int wm = warp >> 1, wn = warp & 1;
    const int m0 = blockIdx.y * 128;
    const int n0 = blockIdx.x * 128;
    const int mgA = (m0 >> 4) + warp;
    const int ngB = (n0 >> 3);

    auto copy_chunk = [&](int kg0, int bf) {
        uint32_t* A = AsmB + bf * 4096;
        uint32_t* B = BsmB + bf * 4096;
#pragma unroll
        for (int t = 0; t < 2; t++) {
            const uint32_t* src = XA + ((size_t)(mgA * KGC + kg0 + t) * 2) * 128 + lane * 4;
            cp16(&A[warp * 512 + t * 256 + lane * 4], src);
            cp16(&A[warp * 512 + t * 256 + 128 + lane * 4], src + 128);
        }
#pragma unroll
        for (int t = 0; t < 4; t++) {
            const int ngl = warp * 2 + (t >> 1), ks = t & 1;
            cp16(&B[ngl * 256 + ks * 128 + lane * 4],
                 WF + (size_t)((ngB + ngl) * KGC + kg0 + ks) * 128 + lane * 4);
        }
        CP_COMMIT();
    };

#pragma unroll
    for (int mg = 0; mg < 2; mg++)
#pragma unroll
        for (int ng = 0; ng < 8; ng++)
#pragma unroll
            for (int e = 0; e < 4; e++) C[mg][ng][e] = 0.0f;

    const int NCH = KGC / 2;
    copy_chunk(0, 0);
    CP_WAIT0();
    __syncthreads();

    for (int ch = 0; ch < NCH; ++ch) {
        const int cur = ch & 1;
        if (ch + 1 < NCH) copy_chunk((ch + 1) * 2, cur ^ 1);
        const uint32_t* A = AsmB + cur * 4096;
        const uint32_t* B = BsmB + cur * 4096;
#pragma unroll
        for (int ks = 0; ks < 2; ks++) {
            uint4 a0h = *(const uint4*)&A[(wm * 2 + 0) * 512 + ks * 256 + lane * 4];
            uint4 a0l = *(const uint4*)&A[(wm * 2 + 0) * 512 + ks * 256 + 128 + lane * 4];
            uint4 a1h = *(const uint4*)&A[(wm * 2 + 1) * 512 + ks * 256 + lane * 4];
            uint4 a1l = *(const uint4*)&A[(wm * 2 + 1) * 512 + ks * 256 + 128 + lane * 4];
#pragma unroll
            for (int ng = 0; ng < 8; ng++) {
                uint4 b = *(const uint4*)&B[(wn * 8 + ng) * 256 + ks * 128 + lane * 4];
                mma_bf16_u4(C[0][ng], a0h, b.x, b.y);
                mma_bf16_u4(C[0][ng], a0l, b.x, b.y);
                mma_bf16_u4(C[0][ng], a0h, b.z, b.w);
                mma_bf16_u4(C[1][ng], a1h, b.x, b.y);
                mma_bf16_u4(C[1][ng], a1l, b.x, b.y);
                mma_bf16_u4(C[1][ng], a1h, b.z, b.w);
            }
        }
        CP_WAIT0();
        __syncthreads();
    }
}

// ---------------------------------------------------------------------------
// Fused Q/K/V projection (epilogues identical to R10 known-good).
// ---------------------------------------------------------------------------
__global__ __launch_bounds__(256, 2) void proj_qkv(
    const float* __restrict__ bq, const float* __restrict__ bk,
    const float* __restrict__ bv)
{
    const int z = blockIdx.z;
    const uint32_t* WF = (z == 0) ? g_WqF : (z == 1) ? g_WkF : g_WvF;
    const float* bias = (z == 0) ? bq : (z == 1) ? bk : bv;

    float C[2][8][4];
    gemm_core<64>(g_XA, WF, C);

    const int tid  = threadIdx.x;
    const int warp = tid >> 5;
    const int lane = tid & 31;
    const int wm = warp >> 1, wn = warp & 1;
    const int g = lane >> 2, tg = lane & 3;
    const int m0 = blockIdx.y * 128;
    const int n0 = blockIdx.x * 128;
    const int h = (n0 + wn * 64) >> 6;

    float bb[8][2];
#pragma unroll
    for (int ng = 0; ng < 8; ng++) {
        const int n = n0 + wn * 64 + ng * 8 + 2 * tg;
        bb[ng][0] = bias[n];
        bb[ng][1] = bias[n + 1];
    }

#pragma unroll
    for (int mg = 0; mg < 2; mg++) {
        const int mtile = m0 + wm * 32 + mg * 16;
        const int b = mtile >> 11;
        const int stile = mtile & (SEQ - 1);
        const int bh = b * NH + h;
        float v[2][16];
#pragma unroll
        for (int half = 0; half < 2; half++) {
#pragma unroll
            for (int ng = 0; ng < 8; ng++) {
                v[half][2 * ng]     = C[mg][ng][half * 2]     + bb[ng][0];
                v[half][2 * ng + 1] = C[mg][ng][half * 2 + 1] + bb[ng][1];
            }
            if (z < 2) {
                float mx = v[half][0];
#pragma unroll
                for (int e = 1; e < 16; e++) mx = fmaxf(mx, v[half][e]);
                mx = fmaxf(mx, __shfl_xor_sync(0xffffffffu, mx, 1));
                mx = fmaxf(mx, __shfl_xor_sync(0xffffffffu, mx, 2));
                float sum = 0.0f;
#pragma unroll
                for (int e = 0; e < 16; e++) { v[half][e] = __expf(v[half][e] - mx); sum += v[half][e]; }
                sum += __shfl_xor_sync(0xffffffffu, sum, 1);
                sum += __shfl_xor_sync(0xffffffffu, sum, 2);
                const float inv = 1.0f / sum;
#pragma unroll
                for (int e = 0; e < 16; e++) v[half][e] = sqrtf(v[half][e] * inv);
            }
        }

        if (z == 0) {
            const int sg = stile >> 4;
#pragma unroll
            for (int ks = 0; ks < 4; ks++) {
                uint32_t h4[4], l4[4];
                split2(v[0][4 * ks],     v[0][4 * ks + 1], h4[0], l4[0]);
                split2(v[1][4 * ks],     v[1][4 * ks + 1], h4[1], l4[1]);
                split2(v[0][4 * ks + 2], v[0][4 * ks + 3], h4[2], l4[2]);
                split2(v[1][4 * ks + 2], v[1][4 * ks + 3], h4[3], l4[3]);
                uint32_t* dst = g_QA + (((size_t)(bh * 128 + sg) * 4 + ks) * 2) * 128 + lane * 4;
                *(uint4*)dst         = make_uint4(h4[0], h4[1], h4[2], h4[3]);
                *(uint4*)(dst + 128) = make_uint4(l4[0], l4[1], l4[2], l4[3]);
            }
        } else if (z == 1) {
#pragma unroll
            for (int half = 0; half < 2; half++) {
                const int s = stile + g + half * 8;
                const int jt = s >> 6, jg = (s >> 3) & 7;
                const int lp = (s & 7) * 4 + tg;
#pragma unroll
                for (int ks = 0; ks < 4; ks++) {
                    uint32_t h0, l0, h1, l1;
                    split2(v[half][4 * ks],     v[half][4 * ks + 1], h0, l0);
                    split2(v[half][4 * ks + 2], v[half][4 * ks + 3], h1, l1);
                    *(uint4*)(g_KF + (((size_t)((bh * 32 + jt) * 8 + jg) * 4 + ks)) * 128 + lp * 4)
                        = make_uint4(h0, h1, l0, l1);
                }
            }
        } else {
#pragma unroll
            for (int half = 0; half < 2; half++) {
                const int s = stile + g + half * 8;
                float* dst = g_V + ((size_t)bh * SEQ + s) * HD;
#pragma unroll
                for (int ng = 0; ng < 8; ng++) {
                    float2 t = { v[half][2 * ng], v[half][2 * ng + 1] };
                    *(float2*)(dst + ng * 8 + 2 * tg) = t;
                }
            }
        }
    }
}

// ---------------------------------------------------------------------------
__global__ __launch_bounds__(256, 2) void out_gemm(
    const float* __restrict__ bias, float* __restrict__ out)
{
    float C[2][8][4];
    gemm_core<32>(g_AF, g_WoF, C);

    const int tid  = threadIdx.x;
    const int warp = tid >> 5;
    const int lane = tid & 31;
    const int wm = warp >> 1, wn = warp & 1;
    const int g = lane >> 2, tg = lane & 3;
    const int m0 = blockIdx.y * 128;
    const int n0 = blockIdx.x * 128;

    float bb[8][2];
#pragma unroll
    for (int ng = 0; ng < 8; ng++) {
        const int n = n0 + wn * 64 + ng * 8 + 2 * tg;
        bb[ng][0] = bias[n];
        bb[ng][1] = bias[n + 1];
    }
#pragma unroll
    for (int mg = 0; mg < 2; mg++) {
#pragma unroll
        for (int half = 0; half < 2; half++) {
            const int m = m0 + wm * 32 + mg * 16 + g + half * 8;
            float* dst = out + (size_t)m * KIN + n0 + wn * 64;
#pragma unroll
            for (int ng = 0; ng < 8; ng++) {
                float2 t = { C[mg][ng][half * 2]     + bb[ng][0],
                             C[mg][ng][half * 2 + 1] + bb[ng][1] };
                *(float2*)(dst + ng * 8 + 2 * tg) = t;
            }
        }
    }
}

// ---------------------------------------------------------------------------
// Attention: cp.async staging, double-buffered, one barrier per j-tile.
// Dynamic smem 64 KB.
// ---------------------------------------------------------------------------
__global__ __launch_bounds__(256, 2) void attn_tc()
{
    extern __shared__ uint32_t sm[];
    uint32_t* QsB = sm;            // [2][8][4][128] = 8192 u32
    uint32_t* VsB = sm + 8192;

    const int tid  = threadIdx.x;
    const int warp = tid >> 5;
    const int lane = tid & 31;
    const int bh   = blockIdx.y;
    const int i0   = blockIdx.x * 128;

    uint4 AhiV[4], AloV[4];
    const int sg = (i0 >> 4) + warp;
#pragma unroll
    for (int ks = 0; ks < 4; ks++) {
        const uint32_t* src = g_QA + (((size_t)(bh * 128 + sg) * 4 + ks) * 2) * 128 + lane * 4;
        AhiV[ks] = *(const uint4*)src;
        AloV[ks] = *(const uint4*)(src + 128);
    }

    const u64t K9 = dup2f(-2.0705e-4f);
    const u64t K8 = dup2f(-2.6002e-4f);
    const u64t K7 = dup2f(-6.2160e-4f);
    const u64t K6 = dup2f(-1.52229e-3f);
    const u64t K5 = dup2f(-3.84800e-3f);
    const u64t K4 = dup2f(-1.015873e-2f);
    const u64t K3 = dup2f(-2.8571429e-2f);
    const u64t K2 = dup2f(-8.8888889e-2f);
    const u64t K1 = dup2f(-0.33333333f);
    const u64t K0 = dup2f(-2.0f);
    const u64t CM1 = dup2f(-1.0f);
    const u64t CP1 = dup2f(1.0f);

    auto copy_tile = [&](int jt, int bf) {
        uint32_t* Q = QsB + bf * 4096;
        uint32_t* Vv = VsB + bf * 4096;
        const uint32_t* qs = g_KF + ((size_t)((bh * 32 + jt) * 8 + warp) * 4) * 128 + lane * 4;
        const uint32_t* vs = g_VF + ((size_t)((bh * 32 + jt) * 8 + warp) * 4) * 128 + lane * 4;
#pragma unroll
        for (int ks = 0; ks < 4; ks++) {
            cp16(&Q[warp * 512 + ks * 128 + lane * 4],  qs + ks * 128);
            cp16(&Vv[warp * 512 + ks * 128 + lane * 4], vs + ks * 128);
        }
        CP_COMMIT();
    };

    float o[8][4];
#pragma unroll
    for (int dg = 0; dg < 8; dg++)
#pragma unroll
        for (int e = 0; e < 4; e++) o[dg][e] = 0.0f;
    float den0 = 0.0f, den1 = 0.0f;

    copy_tile(0, 0);
    CP_WAIT0();
    __syncthreads();

    const int NT = SEQ / 64;   // 32
    for (int t = 0; t < NT; ++t) {
        const int cur = t & 1;
        if (t + 1 < NT) copy_tile(t + 1, cur ^ 1);
        const uint32_t* Q = QsB + cur * 4096;
        const uint32_t* Vv = VsB + cur * 4096;

        uint32_t Whi[4][4], Wlo[4][4];
#pragma unroll
        for (int jg = 0; jg < 8; jg++) {
            float acc[4] = { 0.0f, 0.0f, 0.0f, 0.0f };
#pragma unroll
            for (int ks = 0; ks < 4; ks++) {
                uint4 q = *(const uint4*)&Q[jg * 512 + ks * 128 + lane * 4];
                mma_bf16_u4(acc, AhiV[ks], q.x, q.y);
                mma_bf16_u4(acc, AloV[ks], q.x, q.y);
                mma_bf16_u4(acc, AhiV[ks], q.z, q.w);
            }
            u64t ua = fma2(pk2(acc[0], acc[1]), CM1, CP1);
            u64t ub = fma2(pk2(acc[2], acc[3]), CM1, CP1);
            u64t ga = K9, gb = K9;
            ga = fma2(ga, ua, K8);  gb = fma2(gb, ub, K8);
            ga = fma2(ga, ua, K7);  gb = fma2(gb, ub, K7);
            ga = fma2(ga, ua, K6);  gb = fma2(gb, ub, K6);
            ga = fma2(ga, ua, K5);  gb = fma2(gb, ub, K5);
            ga = fma2(ga, ua, K4);  gb = fma2(gb, ub, K4);
            ga = fma2(ga, ua, K3);  gb = fma2(gb, ub, K3);
            ga = fma2(ga, ua, K2);  gb = fma2(gb, ub, K2);
            ga = fma2(ga, ua, K1);  gb = fma2(gb, ub, K1);
            ga = fma2(ga, ua, K0);  gb = fma2(gb, ub, K0);
            ga = mul2(ga, ua);      gb = mul2(gb, ub);
            float2 gA = unpk(ga), gB = unpk(gb);
            float w0 = __expf(gA.x), w1 = __expf(gA.y);
            float w2 = __expf(gB.x), w3 = __expf(gB.y);
            den0 += w0 + w1;
            den1 += w2 + w3;
            const int ks = jg >> 1, up = (jg & 1) << 1;
            split2(w0, w1, Whi[ks][up + 0], Wlo[ks][up + 0]);
            split2(w2, w3, Whi[ks][up + 1], Wlo[ks][up + 1]);
        }

#pragma unroll
        for (int dg = 0; dg < 8; dg++) {
#pragma unroll
            for (int js = 0; js < 4; js++) {
                uint4 v = *(const uint4*)&Vv[dg * 512 + js * 128 + lane * 4];
                mma_bf16(o[dg], Whi[js], v.x, v.y);
                mma_bf16(o[dg], Wlo[js], v.x, v.y);
                mma_bf16(o[dg], Whi[js], v.z, v.w);
            }
        }

        CP_WAIT0();
        __syncthreads();
    }

    den0 += __shfl_xor_sync(0xffffffffu, den0, 1);
    den0 += __shfl_xor_sync(0xffffffffu, den0, 2);
    den1 += __shfl_xor_sync(0xffffffffu, den1, 1);
    den1 += __shfl_xor_sync(0xffffffffu, den1, 2);
    const float inv0 = 1.0f / den0;
    const float inv1 = 1.0f / den1;

    const int b = bh >> 3, hh = bh & 7;
    const int mgg = b * 128 + (i0 >> 4) + warp;
#pragma unroll
    for (int k = 0; k < 4; k++) {
        uint32_t h4[4], l4[4];
        split2(o[2 * k][0] * inv0,     o[2 * k][1] * inv0,     h4[0], l4[0]);
        split2(o[2 * k][2] * inv1,     o[2 * k][3] * inv1,     h4[1], l4[1]);
        split2(o[2 * k + 1][0] * inv0, o[2 * k + 1][1] * inv0, h4[2], l4[2]);
        split2(o[2 * k + 1][2] * inv1, o[2 * k + 1][3] * inv1, h4[3], l4[3]);
        const int ksg = hh * 4 + k;
        uint32_t* dst = g_AF + ((size_t)(mgg * 32 + ksg) * 2) * 128 + lane * 4;
        *(uint4*)dst         = make_uint4(h4[0], h4[1], h4[2], h4[3]);
        *(uint4*)(dst + 128) = make_uint4(l4[0], l4[1], l4[2], l4[3]);
    }
}

// ---------------------------------------------------------------------------
extern "C" void kernel_launch(void* const* d_in, const int* in_sizes, int n_in,
                              void* d_out, int out_size)
{
    const float* xr = (const float*)d_in[0];
    const float* xi = (const float*)d_in[1];
    const float* Wq = (const float*)d_in[2];
    const float* bq = (const float*)d_in[3];
    const float* Wk = (const float*)d_in[4];
    const float* bk = (const float*)d_in[5];
    const float* Wv = (const float*)d_in[6];
    const float* bv = (const float*)d_in[7];
    const float* Wo = (const float*)d_in[8];
    const float* bo = (const float*)d_in[9];
    float* out = (float*)d_out;

    const int smem = 65536;   // matches kernels' 64 KB footprint (R11 bug: was 32768)
    cudaFuncSetAttribute(proj_qkv, cudaFuncAttributeMaxDynamicSharedMemorySize, smem);
    cudaFuncSetAttribute(out_gemm, cudaFuncAttributeMaxDynamicSharedMemorySize, smem);
    cudaFuncSetAttribute(attn_tc,  cudaFuncAttributeMaxDynamicSharedMemorySize, smem);

    prep_xa<<<dim3(32, 64), 256>>>(xr, xi);
    prep_w_all<<<dim3(64, 8, 4), 256>>>(Wq, Wk, Wv, Wo);

    dim3 gp(DIM / 128, MTOT / 128, 3);       // (4, 32, 3)
    proj_qkv<<<gp, 256, smem>>>(bq, bk, bv);

    repack_v<<<dim3(32, 16), 256>>>();

    dim3 ga(SEQ / 128, BATCH * NH);          // (16, 16)
    attn_tc<<<ga, 256, smem>>>();

    dim3 go(KIN / 128, MTOT / 128);          // (8, 32)
    out_gemm<<<go, 256, smem>>>(bo, out);
}

// round 13
// speedup vs baseline: 2.8490x; 1.0020x over previous
#include <cuda_runtime.h>
#include <cuda_bf16.h>
#include <math.h>
#include <stdint.h>

#define DIM   512
#define NH    8
#define HD    64
#define SEQ   2048
#define BATCH 2
#define MTOT  (BATCH * SEQ)   // 4096
#define KIN   (2 * DIM)       // 1024

typedef unsigned long long u64t;

// ---- packed f32x2 helpers ----
__device__ __forceinline__ u64t fma2(u64t a, u64t b, u64t c) {
    u64t d; asm("fma.rn.f32x2 %0, %1, %2, %3;" : "=l"(d) : "l"(a), "l"(b), "l"(c));
    return d;
}
__device__ __forceinline__ u64t mul2(u64t a, u64t b) {
    u64t d; asm("mul.rn.f32x2 %0, %1, %2;" : "=l"(d) : "l"(a), "l"(b));
    return d;
}
__device__ __forceinline__ u64t dup2f(float x) {
    u64t r; asm("mov.b64 %0, {%1, %1};" : "=l"(r) : "f"(x));
    return r;
}
__device__ __forceinline__ u64t pk2(float a, float b) {
    u64t r; asm("mov.b64 %0, {%1, %2};" : "=l"(r) : "f"(a), "f"(b));
    return r;
}
__device__ __forceinline__ float2 unpk(u64t v) {
    float lo, hi; asm("mov.b64 {%0, %1}, %2;" : "=f"(lo), "=f"(hi) : "l"(v));
    float2 f; f.x = lo; f.y = hi; return f;
}

// ---- bf16x2 split, bit-trick version (6 instr). hi = {bf16(y)|bf16(x)},
// residuals via <<16 / mask reconstruction (bf16 -> f32 is exact). Rounding
// (.rn) identical to __float2bfloat16 -> results bit-identical to R12. ----
__device__ __forceinline__ void split2(float x, float y, uint32_t& hi, uint32_t& lo) {
    uint32_t h;
    asm("cvt.rn.bf16x2.f32 %0, %1, %2;" : "=r"(h) : "f"(y), "f"(x));
    float hx = __uint_as_float(h << 16);
    float hy = __uint_as_float(h & 0xffff0000u);
    float rx = x - hx;
    float ry = y - hy;
    asm("cvt.rn.bf16x2.f32 %0, %1, %2;" : "=r"(lo) : "f"(ry), "f"(rx));
    hi = h;
}

// ---- mma.sync m16n8k16 bf16 ----
__device__ __forceinline__ void mma_bf16(float c[4], const uint32_t a[4],
                                         uint32_t b0, uint32_t b1) {
    asm volatile(
        "mma.sync.aligned.m16n8k16.row.col.f32.bf16.bf16.f32 "
        "{%0,%1,%2,%3}, {%4,%5,%6,%7}, {%8,%9}, {%0,%1,%2,%3};"
        : "+f"(c[0]), "+f"(c[1]), "+f"(c[2]), "+f"(c[3])
        : "r"(a[0]), "r"(a[1]), "r"(a[2]), "r"(a[3]), "r"(b0), "r"(b1));
}
__device__ __forceinline__ void mma_bf16_u4(float c[4], uint4 a,
                                            uint32_t b0, uint32_t b1) {
    uint32_t ar[4] = { a.x, a.y, a.z, a.w };
    mma_bf16(c, ar, b0, b1);
}

// ---- cp.async 16B ----
__device__ __forceinline__ void cp16(void* smem_dst, const void* gsrc) {
    uint32_t s = (uint32_t)__cvta_generic_to_shared(smem_dst);
    asm volatile("cp.async.cg.shared.global [%0], [%1], 16;" :: "r"(s), "l"(gsrc));
}
#define CP_COMMIT() asm volatile("cp.async.commit_group;")
#define CP_WAIT0()  asm volatile("cp.async.wait_group 0;" ::: "memory")
#define CP_WAIT1()  asm volatile("cp.async.wait_group 1;" ::: "memory")

// ---------------------------------------------------------------------------
// Pre-split fragment-order global buffers
// ---------------------------------------------------------------------------
__device__ uint32_t g_XA[256 * 64 * 2 * 128];
__device__ uint32_t g_WqF[64 * 64 * 128];
__device__ uint32_t g_WkF[64 * 64 * 128];
__device__ uint32_t g_WvF[64 * 64 * 128];
__device__ uint32_t g_WoF[128 * 32 * 128];
__device__ uint32_t g_QA[16 * 128 * 4 * 2 * 128];
__device__ uint32_t g_KF[16 * 32 * 8 * 4 * 128];
__device__ uint32_t g_VF[16 * 32 * 8 * 4 * 128];
__device__ float    g_V [16 * SEQ * HD];
__device__ uint32_t g_AF[256 * 32 * 2 * 128];

// ---------------------------------------------------------------------------
// Prep: x -> A-frag split.  grid(32, 64), 256 thr.
// ---------------------------------------------------------------------------
__global__ __launch_bounds__(256) void prep_xa(
    const float* __restrict__ xr, const float* __restrict__ xi)
{
    const int lane = threadIdx.x & 31;
    const int warp = threadIdx.x >> 5;
    const int g = lane >> 2, tg = lane & 3;
    const int mg = blockIdx.x * 8 + warp;
    const int kg = blockIdx.y;
    const int m = mg * 16 + g;
    const int k = kg * 16 + 2 * tg;
    const float* base = (k < DIM) ? xr : xi;
    const int kk = k & (DIM - 1);
    float2 f00 = *(const float2*)(base + (size_t)m * DIM + kk);
    float2 f01 = *(const float2*)(base + (size_t)m * DIM + kk + 8);
    float2 f10 = *(const float2*)(base + (size_t)(m + 8) * DIM + kk);
    float2 f11 = *(const float2*)(base + (size_t)(m + 8) * DIM + kk + 8);
    uint32_t h[4], l[4];
    split2(f00.x, f00.y, h[0], l[0]);
    split2(f10.x, f10.y, h[1], l[1]);
    split2(f01.x, f01.y, h[2], l[2]);
    split2(f11.x, f11.y, h[3], l[3]);
    uint32_t* dst = g_XA + ((size_t)(mg * 64 + kg) * 2) * 128 + lane * 4;
    *(uint4*)dst         = make_uint4(h[0], h[1], h[2], h[3]);
    *(uint4*)(dst + 128) = make_uint4(l[0], l[1], l[2], l[3]);
}

// ---------------------------------------------------------------------------
// Prep: all four W -> B-frag split. grid(64, 8, 4), 256 thr.
// ---------------------------------------------------------------------------
__global__ __launch_bounds__(256) void prep_w_all(
    const float* __restrict__ Wq, const float* __restrict__ Wk,
    const float* __restrict__ Wv, const float* __restrict__ Wo)
{
    const int lane = threadIdx.x & 31;
    const int warp = threadIdx.x >> 5;
    const int g = lane >> 2, tg = lane & 3;
    const int z = blockIdx.z;

    int ng, ks, N, KGC;
    const float* W;
    uint32_t* WF;
    if (z < 3) {
        ng = blockIdx.x;
        ks = blockIdx.y * 8 + warp;
        N = DIM; KGC = 64;
        W  = (z == 0) ? Wq : (z == 1) ? Wk : Wv;
        WF = (z == 0) ? g_WqF : (z == 1) ? g_WkF : g_WvF;
    } else {
        const int id = blockIdx.y * 64 + blockIdx.x;
        ng = id >> 2;
        ks = (id & 3) * 8 + warp;
        N = KIN; KGC = 32;
        W = Wo; WF = g_WoF;
    }

    const int k = ks * 16 + 2 * tg;
    const int n = ng * 8 + g;
    float b0a = W[(size_t)k * N + n];
    float b0b = W[(size_t)(k + 1) * N + n];
    float b1a = W[(size_t)(k + 8) * N + n];
    float b1b = W[(size_t)(k + 9) * N + n];
    uint32_t h0, l0, h1, l1;
    split2(b0a, b0b, h0, l0);
    split2(b1a, b1b, h1, l1);
    *(uint4*)(WF + (size_t)(ng * KGC + ks) * 128 + lane * 4) = make_uint4(h0, h1, l0, l1);
}

// ---------------------------------------------------------------------------
// Repack V fp32 -> B-frag split.  grid(32 jt, 16 bh), 256 thr.
// ---------------------------------------------------------------------------
__global__ __launch_bounds__(256) void repack_v()
{
    const int lane = threadIdx.x & 31;
    const int dg = threadIdx.x >> 5;
    const int r = lane >> 2, cq = lane & 3;
    const int jt = blockIdx.x, bh = blockIdx.y;
    const float* Vb = g_V + (size_t)bh * SEQ * HD;
    const int j0 = jt * 64;
#pragma unroll
    for (int js = 0; js < 4; js++) {
        const float* vsrc = Vb + (size_t)(j0 + js * 16 + 2 * cq) * HD + dg * 8 + r;
        float v0 = vsrc[0];
        float v1 = vsrc[HD];
        float v2 = vsrc[8 * HD];
        float v3 = vsrc[9 * HD];
        uint32_t h0, l0, h1, l1;
        split2(v0, v1, h0, l0);
        split2(v2, v3, h1, l1);
        *(uint4*)(g_VF + ((size_t)((bh * 32 + jt) * 8 + dg) * 4 + js) * 128 + lane * 4)
            = make_uint4(h0, h1, l0, l1);
    }
}

// ---------------------------------------------------------------------------
// GEMM core: 3-stage cp.async pipeline (two copies in flight), one barrier
// per 32-wide K-chunk. Dynamic smem 96 KB.
// ---------------------------------------------------------------------------
template<int KGC>
__device__ __forceinline__ void gemm_core(
    const uint32_t* __restrict__ XA, const uint32_t* __restrict__ WF,
    float C[2][8][4])
{
    extern __shared__ uint32_t sm[];
    uint32_t* AsmB = sm;             // [3][8][2][256] = 12288 u32
    uint32_t* BsmB = sm + 12288;     // [3][16][2][128] = 12288 u32

    const int tid  = threadIdx.x;
    const int warp = tid >> 5;
    const int lane = tid & 31;
    const int wm = warp >> 1, wn = warp & 1;
    const int m0 = blockIdx.y * 128;
    const int n0 = blockIdx.x * 128;
    const int mgA = (m0 >> 4) + warp;
    const int ngB = (n0 >> 3);

    auto copy_chunk = [&](int ch, int bf) {
        const int kg0 = ch * 2;
        uint32_t* A = AsmB + bf * 4096;
        uint32_t* B = BsmB + bf * 4096;
#pragma unroll
        for (int t = 0; t < 2; t++) {
            const uint32_t* src = XA + ((size_t)(mgA * KGC + kg0 + t) * 2) * 128 + lane * 4;
            cp16(&A[warp * 512 + t * 256 + lane * 4], src);
            cp16(&A[warp * 512 + t * 256 + 128 + lane * 4], src + 128);
        }
#pragma unroll
        for (int t = 0; t < 4; t++) {
            const int ngl = warp * 2 + (t >> 1), ks = t & 1;
            cp16(&B[ngl * 256 + ks * 128 + lane * 4],
                 WF + (size_t)((ngB + ngl) * KGC + kg0 + ks) * 128 + lane * 4);
        }
        CP_COMMIT();
    };

#pragma unroll
    for (int mg = 0; mg < 2; mg++)
#pragma unroll
        for (int ng = 0; ng < 8; ng++)
#pragma unroll
            for (int e = 0; e < 4; e++) C[mg][ng][e] = 0.0f;

    const int NCH = KGC / 2;
    copy_chunk(0, 0);
    copy_chunk(1, 1);

    for (int ch = 0; ch < NCH; ++ch) {
        const int cur = ch % 3;
        if (ch + 1 < NCH) { CP_WAIT1(); } else { CP_WAIT0(); }
        __syncthreads();
        const uint32_t* A = AsmB + cur * 4096;
        const uint32_t* B = BsmB + cur * 4096;
#pragma unroll
        for (int ks = 0; ks < 2; ks++) {
            uint4 a0h = *(const uint4*)&A[(wm * 2 + 0) * 512 + ks * 256 + lane * 4];
            uint4 a0l = *(const uint4*)&A[(wm * 2 + 0) * 512 + ks * 256 + 128 + lane * 4];
            uint4 a1h = *(const uint4*)&A[(wm * 2 + 1) * 512 + ks * 256 + lane * 4];
            uint4 a1l = *(const uint4*)&A[(wm * 2 + 1) * 512 + ks * 256 + 128 + lane * 4];
#pragma unroll
            for (int ng = 0; ng < 8; ng++) {
                uint4 b = *(const uint4*)&B[(wn * 8 + ng) * 256 + ks * 128 + lane * 4];
                mma_bf16_u4(C[0][ng], a0h, b.x, b.y);
                mma_bf16_u4(C[0][ng], a0l, b.x, b.y);
                mma_bf16_u4(C[0][ng], a0h, b.z, b.w);
                mma_bf16_u4(C[1][ng], a1h, b.x, b.y);
                mma_bf16_u4(C[1][ng], a1l, b.x, b.y);
                mma_bf16_u4(C[1][ng], a1h, b.z, b.w);
            }
        }
        if (ch + 2 < NCH) copy_chunk(ch + 2, (ch + 2) % 3);
    }
}

// ---------------------------------------------------------------------------
// Fused Q/K/V projection (epilogues identical to R12 known-good).
// ---------------------------------------------------------------------------
__global__ __launch_bounds__(256, 2) void proj_qkv(
    const float* __restrict__ bq, const float* __restrict__ bk,
    const float* __restrict__ bv)
{
    const int z = blockIdx.z;
    const uint32_t* WF = (z == 0) ? g_WqF : (z == 1) ? g_WkF : g_WvF;
    const float* bias = (z == 0) ? bq : (z == 1) ? bk : bv;

    float C[2][8][4];
    gemm_core<64>(g_XA, WF, C);

    const int tid  = threadIdx.x;
    const int warp = tid >> 5;
    const int lane = tid & 31;
    const int wm = warp >> 1, wn = warp & 1;
    const int g = lane >> 2, tg = lane & 3;
    const int m0 = blockIdx.y * 128;
    const int n0 = blockIdx.x * 128;
    const int h = (n0 + wn * 64) >> 6;

    float bb[8][2];
#pragma unroll
    for (int ng = 0; ng < 8; ng++) {
        const int n = n0 + wn * 64 + ng * 8 + 2 * tg;
        bb[ng][0] = bias[n];
        bb[ng][1] = bias[n + 1];
    }

#pragma unroll
    for (int mg = 0; mg < 2; mg++) {
        const int mtile = m0 + wm * 32 + mg * 16;
        const int b = mtile >> 11;
        const int stile = mtile & (SEQ - 1);
        const int bh = b * NH + h;
        float v[2][16];
#pragma unroll
        for (int half = 0; half < 2; half++) {
#pragma unroll
            for (int ng = 0; ng < 8; ng++) {
                v[half][2 * ng]     = C[mg][ng][half * 2]     + bb[ng][0];
                v[half][2 * ng + 1] = C[mg][ng][half * 2 + 1] + bb[ng][1];
            }
            if (z < 2) {
                float mx = v[half][0];
#pragma unroll
                for (int e = 1; e < 16; e++) mx = fmaxf(mx, v[half][e]);
                mx = fmaxf(mx, __shfl_xor_sync(0xffffffffu, mx, 1));
                mx = fmaxf(mx, __shfl_xor_sync(0xffffffffu, mx, 2));
                float sum = 0.0f;
#pragma unroll
                for (int e = 0; e < 16; e++) { v[half][e] = __expf(v[half][e] - mx); sum += v[half][e]; }
                sum += __shfl_xor_sync(0xffffffffu, sum, 1);
                sum += __shfl_xor_sync(0xffffffffu, sum, 2);
                const float inv = 1.0f / sum;
#pragma unroll
                for (int e = 0; e < 16; e++) v[half][e] = sqrtf(v[half][e] * inv);
            }
        }

        if (z == 0) {
            const int sg = stile >> 4;
#pragma unroll
            for (int ks = 0; ks < 4; ks++) {
                uint32_t h4[4], l4[4];
                split2(v[0][4 * ks],     v[0][4 * ks + 1], h4[0], l4[0]);
                split2(v[1][4 * ks],     v[1][4 * ks + 1], h4[1], l4[1]);
                split2(v[0][4 * ks + 2], v[0][4 * ks + 3], h4[2], l4[2]);
                split2(v[1][4 * ks + 2], v[1][4 * ks + 3], h4[3], l4[3]);
                uint32_t* dst = g_QA + (((size_t)(bh * 128 + sg) * 4 + ks) * 2) * 128 + lane * 4;
                *(uint4*)dst         = make_uint4(h4[0], h4[1], h4[2], h4[3]);
                *(uint4*)(dst + 128) = make_uint4(l4[0], l4[1], l4[2], l4[3]);
            }
        } else if (z == 1) {
#pragma unroll
            for (int half = 0; half < 2; half++) {
                const int s = stile + g + half * 8;
                const int jt = s >> 6, jg = (s >> 3) & 7;
                const int lp = (s & 7) * 4 + tg;
#pragma unroll
                for (int ks = 0; ks < 4; ks++) {
                    uint32_t h0, l0, h1, l1;
                    split2(v[half][4 * ks],     v[half][4 * ks + 1], h0, l0);
                    split2(v[half][4 * ks + 2], v[half][4 * ks + 3], h1, l1);
                    *(uint4*)(g_KF + (((size_t)((bh * 32 + jt) * 8 + jg) * 4 + ks)) * 128 + lp * 4)
                        = make_uint4(h0, h1, l0, l1);
                }
            }
        } else {
#pragma unroll
            for (int half = 0; half < 2; half++) {
                const int s = stile + g + half * 8;
                float* dst = g_V + ((size_t)bh * SEQ + s) * HD;
#pragma unroll
                for (int ng = 0; ng < 8; ng++) {
                    float2 t = { v[half][2 * ng], v[half][2 * ng + 1] };
                    *(float2*)(dst + ng * 8 + 2 * tg) = t;
                }
            }
        }
    }
}

// ---------------------------------------------------------------------------
__global__ __launch_bounds__(256, 2) void out_gemm(
    const float* __restrict__ bias, float* __restrict__ out)
{
    float C[2][8][4];
    gemm_core<32>(g_AF, g_WoF, C);

    const int tid  = threadIdx.x;
    const int warp = tid >> 5;
    const int lane = tid & 31;
    const int wm = warp >> 1, wn = warp & 1;
    const int g = lane >> 2, tg = lane & 3;
    const int m0 = blockIdx.y * 128;
    const int n0 = blockIdx.x * 128;

    float bb[8][2];
#pragma unroll
    for (int ng = 0; ng < 8; ng++) {
        const int n = n0 + wn * 64 + ng * 8 + 2 * tg;
        bb[ng][0] = bias[n];
        bb[ng][1] = bias[n + 1];
    }
#pragma unroll
    for (int mg = 0; mg < 2; mg++) {
#pragma unroll
        for (int half = 0; half < 2; half++) {
            const int m = m0 + wm * 32 + mg * 16 + g + half * 8;
            float* dst = out + (size_t)m * KIN + n0 + wn * 64;
#pragma unroll
            for (int ng = 0; ng < 8; ng++) {
                float2 t = { C[mg][ng][half * 2]     + bb[ng][0],
                             C[mg][ng][half * 2 + 1] + bb[ng][1] };
                *(float2*)(dst + ng * 8 + 2 * tg) = t;
            }
        }
    }
}

// ---------------------------------------------------------------------------
// Attention: 3-stage cp.async pipeline, transform interleaved with w@V per
// ks-group (same per-accumulator order -> bit-identical). Smem 96 KB.
// ---------------------------------------------------------------------------
__global__ __launch_bounds__(256, 2) void attn_tc()
{
    extern __shared__ uint32_t sm[];
    uint32_t* QsB = sm;             // [3][8][4][128]
    uint32_t* VsB = sm + 12288;

    const int tid  = threadIdx.x;
    const int warp = tid >> 5;
    const int lane = tid & 31;
    const int bh   = blockIdx.y;
    const int i0   = blockIdx.x * 128;

    uint4 AhiV[4], AloV[4];
    const int sg = (i0 >> 4) + warp;
#pragma unroll
    for (int ks = 0; ks < 4; ks++) {
        const uint32_t* src = g_QA + (((size_t)(bh * 128 + sg) * 4 + ks) * 2) * 128 + lane * 4;
        AhiV[ks] = *(const uint4*)src;
        AloV[ks] = *(const uint4*)(src + 128);
    }

    const u64t K9 = dup2f(-2.0705e-4f);
    const u64t K8 = dup2f(-2.6002e-4f);
    const u64t K7 = dup2f(-6.2160e-4f);
    const u64t K6 = dup2f(-1.52229e-3f);
    const u64t K5 = dup2f(-3.84800e-3f);
    const u64t K4 = dup2f(-1.015873e-2f);
    const u64t K3 = dup2f(-2.8571429e-2f);
    const u64t K2 = dup2f(-8.8888889e-2f);
    const u64t K1 = dup2f(-0.33333333f);
    const u64t K0 = dup2f(-2.0f);
    const u64t CM1 = dup2f(-1.0f);
    const u64t CP1 = dup2f(1.0f);

    auto copy_tile = [&](int jt, int bf) {
        uint32_t* Q = QsB + bf * 4096;
        uint32_t* Vv = VsB + bf * 4096;
        const uint32_t* qs = g_KF + ((size_t)((bh * 32 + jt) * 8 + warp) * 4) * 128 + lane * 4;
        const uint32_t* vs = g_VF + ((size_t)((bh * 32 + jt) * 8 + warp) * 4) * 128 + lane * 4;
#pragma unroll
        for (int ks = 0; ks < 4; ks++) {
            cp16(&Q[warp * 512 + ks * 128 + lane * 4],  qs + ks * 128);
            cp16(&Vv[warp * 512 + ks * 128 + lane * 4], vs + ks * 128);
        }
        CP_COMMIT();
    };

    float o[8][4];
#pragma unroll
    for (int dg = 0; dg < 8; dg++)
#pragma unroll
        for (int e = 0; e < 4; e++) o[dg][e] = 0.0f;
    float den0 = 0.0f, den1 = 0.0f;

    copy_tile(0, 0);
    copy_tile(1, 1);

    const int NT = SEQ / 64;   // 32
    for (int t = 0; t < NT; ++t) {
        const int cur = t % 3;
        if (t + 1 < NT) { CP_WAIT1(); } else { CP_WAIT0(); }
        __syncthreads();
        const uint32_t* Q = QsB + cur * 4096;
        const uint32_t* Vv = VsB + cur * 4096;

#pragma unroll
        for (int ks2 = 0; ks2 < 4; ks2++) {
            uint32_t Whi4[4], Wlo4[4];
#pragma unroll
            for (int e = 0; e < 2; e++) {
                const int jg = 2 * ks2 + e;
                float acc[4] = { 0.0f, 0.0f, 0.0f, 0.0f };
#pragma unroll
                for (int ks = 0; ks < 4; ks++) {
                    uint4 q = *(const uint4*)&Q[jg * 512 + ks * 128 + lane * 4];
                    mma_bf16_u4(acc, AhiV[ks], q.x, q.y);
                    mma_bf16_u4(acc, AloV[ks], q.x, q.y);
                    mma_bf16_u4(acc, AhiV[ks], q.z, q.w);
                }
                u64t ua = fma2(pk2(acc[0], acc[1]), CM1, CP1);
                u64t ub = fma2(pk2(acc[2], acc[3]), CM1, CP1);
                u64t ga = K9, gb = K9;
                ga = fma2(ga, ua, K8);  gb = fma2(gb, ub, K8);
                ga = fma2(ga, ua, K7);  gb = fma2(gb, ub, K7);
                ga = fma2(ga, ua, K6);  gb = fma2(gb, ub, K6);
                ga = fma2(ga, ua, K5);  gb = fma2(gb, ub, K5);
                ga = fma2(ga, ua, K4);  gb = fma2(gb, ub, K4);
                ga = fma2(ga, ua, K3);  gb = fma2(gb, ub, K3);
                ga = fma2(ga, ua, K2);  gb = fma2(gb, ub, K2);
                ga = fma2(ga, ua, K1);  gb = fma2(gb, ub, K1);
                ga = fma2(ga, ua, K0);  gb = fma2(gb, ub, K0);
                ga = mul2(ga, ua);      gb = mul2(gb, ub);
                float2 gA = unpk(ga), gB = unpk(gb);
                float w0 = __expf(gA.x), w1 = __expf(gA.y);
                float w2 = __expf(gB.x), w3 = __expf(gB.y);
                den0 += w0 + w1;
                den1 += w2 + w3;
                split2(w0, w1, Whi4[2 * e + 0], Wlo4[2 * e + 0]);
                split2(w2, w3, Whi4[2 * e + 1], Wlo4[2 * e + 1]);
            }
            // w @ V for js = ks2 (interleaves with next ks2's transform)
#pragma unroll
            for (int dg = 0; dg < 8; dg++) {
                uint4 v = *(const uint4*)&Vv[dg * 512 + ks2 * 128 + lane * 4];
                mma_bf16(o[dg], Whi4, v.x, v.y);
                mma_bf16(o[dg], Wlo4, v.x, v.y);
                mma_bf16(o[dg], Whi4, v.z, v.w);
            }
        }

        if (t + 2 < NT) copy_tile(t + 2, (t + 2) % 3);
    }

    den0 += __shfl_xor_sync(0xffffffffu, den0, 1);
    den0 += __shfl_xor_sync(0xffffffffu, den0, 2);
    den1 += __shfl_xor_sync(0xffffffffu, den1, 1);
    den1 += __shfl_xor_sync(0xffffffffu, den1, 2);
    const float inv0 = 1.0f / den0;
    const float inv1 = 1.0f / den1;

    const int b = bh >> 3, hh = bh & 7;
    const int mgg = b * 128 + (i0 >> 4) + warp;
#pragma unroll
    for (int k = 0; k < 4; k++) {
        uint32_t h4[4], l4[4];
        split2(o[2 * k][0] * inv0,     o[2 * k][1] * inv0,     h4[0], l4[0]);
        split2(o[2 * k][2] * inv1,     o[2 * k][3] * inv1,     h4[1], l4[1]);
        split2(o[2 * k + 1][0] * inv0, o[2 * k + 1][1] * inv0, h4[2], l4[2]);
        split2(o[2 * k + 1][2] * inv1, o[2 * k + 1][3] * inv1, h4[3], l4[3]);
        const int ksg = hh * 4 + k;
        uint32_t* dst = g_AF + ((size_t)(mgg * 32 + ksg) * 2) * 128 + lane * 4;
        *(uint4*)dst         = make_uint4(h4[0], h4[1], h4[2], h4[3]);
        *(uint4*)(dst + 128) = make_uint4(l4[0], l4[1], l4[2], l4[3]);
    }
}

// ---------------------------------------------------------------------------
extern "C" void kernel_launch(void* const* d_in, const int* in_sizes, int n_in,
                              void* d_out, int out_size)
{
    const float* xr = (const float*)d_in[0];
    const float* xi = (const float*)d_in[1];
    const float* Wq = (const float*)d_in[2];
    const float* bq = (const float*)d_in[3];
    const float* Wk = (const float*)d_in[4];
    const float* bk = (const float*)d_in[5];
    const float* Wv = (const float*)d_in[6];
    const float* bv = (const float*)d_in[7];
    const float* Wo = (const float*)d_in[8];
    const float* bo = (const float*)d_in[9];
    float* out = (float*)d_out;

    const int smem = 98304;   // 3-stage: 2 x 48 KB
    cudaFuncSetAttribute(proj_qkv, cudaFuncAttributeMaxDynamicSharedMemorySize, smem);
    cudaFuncSetAttribute(out_gemm, cudaFuncAttributeMaxDynamicSharedMemorySize, smem);
    cudaFuncSetAttribute(attn_tc,  cudaFuncAttributeMaxDynamicSharedMemorySize, smem);

    prep_xa<<<dim3(32, 64), 256>>>(xr, xi);
    prep_w_all<<<dim3(64, 8, 4), 256>>>(Wq, Wk, Wv, Wo);

    dim3 gp(DIM / 128, MTOT / 128, 3);       // (4, 32, 3)
    proj_qkv<<<gp, 256, smem>>>(bq, bk, bv);

    repack_v<<<dim3(32, 16), 256>>>();

    dim3 ga(SEQ / 128, BATCH * NH);          // (16, 16)
    attn_tc<<<ga, 256, smem>>>();

    dim3 go(KIN / 128, MTOT / 128);          // (8, 32)
    out_gemm<<<go, 256, smem>>>(bo, out);
}

// round 14
// speedup vs baseline: 2.9421x; 1.0327x over previous
#include <cuda_runtime.h>
#include <cuda_bf16.h>
#include <math.h>
#include <stdint.h>

#define DIM   512
#define NH    8
#define HD    64
#define SEQ   2048
#define BATCH 2
#define MTOT  (BATCH * SEQ)   // 4096
#define KIN   (2 * DIM)       // 1024

typedef unsigned long long u64t;

// ---- packed f32x2 helpers ----
__device__ __forceinline__ u64t fma2(u64t a, u64t b, u64t c) {
    u64t d; asm("fma.rn.f32x2 %0, %1, %2, %3;" : "=l"(d) : "l"(a), "l"(b), "l"(c));
    return d;
}
__device__ __forceinline__ u64t mul2(u64t a, u64t b) {
    u64t d; asm("mul.rn.f32x2 %0, %1, %2;" : "=l"(d) : "l"(a), "l"(b));
    return d;
}
__device__ __forceinline__ u64t dup2f(float x) {
    u64t r; asm("mov.b64 %0, {%1, %1};" : "=l"(r) : "f"(x));
    return r;
}
__device__ __forceinline__ u64t pk2(float a, float b) {
    u64t r; asm("mov.b64 %0, {%1, %2};" : "=l"(r) : "f"(a), "f"(b));
    return r;
}
__device__ __forceinline__ float2 unpk(u64t v) {
    float lo, hi; asm("mov.b64 {%0, %1}, %2;" : "=f"(lo), "=f"(hi) : "l"(v));
    float2 f; f.x = lo; f.y = hi; return f;
}

// ---- bf16x2 split (bit-trick, rounding identical to __float2bfloat16) ----
__device__ __forceinline__ void split2(float x, float y, uint32_t& hi, uint32_t& lo) {
    uint32_t h;
    asm("cvt.rn.bf16x2.f32 %0, %1, %2;" : "=r"(h) : "f"(y), "f"(x));
    float hx = __uint_as_float(h << 16);
    float hy = __uint_as_float(h & 0xffff0000u);
    float rx = x - hx;
    float ry = y - hy;
    asm("cvt.rn.bf16x2.f32 %0, %1, %2;" : "=r"(lo) : "f"(ry), "f"(rx));
    hi = h;
}

// ---- mma.sync m16n8k16 bf16 ----
__device__ __forceinline__ void mma_bf16(float c[4], const uint32_t a[4],
                                         uint32_t b0, uint32_t b1) {
    asm volatile(
        "mma.sync.aligned.m16n8k16.row.col.f32.bf16.bf16.f32 "
        "{%0,%1,%2,%3}, {%4,%5,%6,%7}, {%8,%9}, {%0,%1,%2,%3};"
        : "+f"(c[0]), "+f"(c[1]), "+f"(c[2]), "+f"(c[3])
        : "r"(a[0]), "r"(a[1]), "r"(a[2]), "r"(a[3]), "r"(b0), "r"(b1));
}
__device__ __forceinline__ void mma_bf16_u4(float c[4], uint4 a,
                                            uint32_t b0, uint32_t b1) {
    uint32_t ar[4] = { a.x, a.y, a.z, a.w };
    mma_bf16(c, ar, b0, b1);
}

// ---- cp.async 16B ----
__device__ __forceinline__ void cp16(void* smem_dst, const void* gsrc) {
    uint32_t s = (uint32_t)__cvta_generic_to_shared(smem_dst);
    asm volatile("cp.async.cg.shared.global [%0], [%1], 16;" :: "r"(s), "l"(gsrc));
}
#define CP_COMMIT() asm volatile("cp.async.commit_group;")
#define CP_WAIT0()  asm volatile("cp.async.wait_group 0;" ::: "memory")
#define CP_WAIT1()  asm volatile("cp.async.wait_group 1;" ::: "memory")

// ---------------------------------------------------------------------------
// Pre-split fragment-order global buffers
// ---------------------------------------------------------------------------
__device__ uint32_t g_XA[256 * 64 * 2 * 128];
__device__ uint32_t g_WqF[64 * 64 * 128];
__device__ uint32_t g_WkF[64 * 64 * 128];
__device__ uint32_t g_WvF[64 * 64 * 128];
__device__ uint32_t g_WoF[128 * 32 * 128];
__device__ uint32_t g_QA[16 * 128 * 4 * 2 * 128];
__device__ uint32_t g_KF[16 * 32 * 8 * 4 * 128];
__device__ uint32_t g_VF[16 * 32 * 8 * 4 * 128];
__device__ float    g_V [16 * SEQ * HD];
__device__ uint32_t g_AF[256 * 32 * 2 * 128];

// ---------------------------------------------------------------------------
// Prep: x -> A-frag split.  grid(32, 64), 256 thr.
// ---------------------------------------------------------------------------
__global__ __launch_bounds__(256) void prep_xa(
    const float* __restrict__ xr, const float* __restrict__ xi)
{
    const int lane = threadIdx.x & 31;
    const int warp = threadIdx.x >> 5;
    const int g = lane >> 2, tg = lane & 3;
    const int mg = blockIdx.x * 8 + warp;
    const int kg = blockIdx.y;
    const int m = mg * 16 + g;
    const int k = kg * 16 + 2 * tg;
    const float* base = (k < DIM) ? xr : xi;
    const int kk = k & (DIM - 1);
    float2 f00 = *(const float2*)(base + (size_t)m * DIM + kk);
    float2 f01 = *(const float2*)(base + (size_t)m * DIM + kk + 8);
    float2 f10 = *(const float2*)(base + (size_t)(m + 8) * DIM + kk);
    float2 f11 = *(const float2*)(base + (size_t)(m + 8) * DIM + kk + 8);
    uint32_t h[4], l[4];
    split2(f00.x, f00.y, h[0], l[0]);
    split2(f10.x, f10.y, h[1], l[1]);
    split2(f01.x, f01.y, h[2], l[2]);
    split2(f11.x, f11.y, h[3], l[3]);
    uint32_t* dst = g_XA + ((size_t)(mg * 64 + kg) * 2) * 128 + lane * 4;
    *(uint4*)dst         = make_uint4(h[0], h[1], h[2], h[3]);
    *(uint4*)(dst + 128) = make_uint4(l[0], l[1], l[2], l[3]);
}

// ---------------------------------------------------------------------------
// Prep: all four W -> B-frag split. grid(64, 8, 4), 256 thr.
// ---------------------------------------------------------------------------
__global__ __launch_bounds__(256) void prep_w_all(
    const float* __restrict__ Wq, const float* __restrict__ Wk,
    const float* __restrict__ Wv, const float* __restrict__ Wo)
{
    const int lane = threadIdx.x & 31;
    const int warp = threadIdx.x >> 5;
    const int g = lane >> 2, tg = lane & 3;
    const int z = blockIdx.z;

    int ng, ks, N, KGC;
    const float* W;
    uint32_t* WF;
    if (z < 3) {
        ng = blockIdx.x;
        ks = blockIdx.y * 8 + warp;
        N = DIM; KGC = 64;
        W  = (z == 0) ? Wq : (z == 1) ? Wk : Wv;
        WF = (z == 0) ? g_WqF : (z == 1) ? g_WkF : g_WvF;
    } else {
        const int id = blockIdx.y * 64 + blockIdx.x;
        ng = id >> 2;
        ks = (id & 3) * 8 + warp;
        N = KIN; KGC = 32;
        W = Wo; WF = g_WoF;
    }

    const int k = ks * 16 + 2 * tg;
    const int n = ng * 8 + g;
    float b0a = W[(size_t)k * N + n];
    float b0b = W[(size_t)(k + 1) * N + n];
    float b1a = W[(size_t)(k + 8) * N + n];
    float b1b = W[(size_t)(k + 9) * N + n];
    uint32_t h0, l0, h1, l1;
    split2(b0a, b0b, h0, l0);
    split2(b1a, b1b, h1, l1);
    *(uint4*)(WF + (size_t)(ng * KGC + ks) * 128 + lane * 4) = make_uint4(h0, h1, l0, l1);
}

// ---------------------------------------------------------------------------
// Repack V fp32 -> B-frag split.  grid(32 jt, 16 bh), 256 thr.
// ---------------------------------------------------------------------------
__global__ __launch_bounds__(256) void repack_v()
{
    const int lane = threadIdx.x & 31;
    const int dg = threadIdx.x >> 5;
    const int r = lane >> 2, cq = lane & 3;
    const int jt = blockIdx.x, bh = blockIdx.y;
    const float* Vb = g_V + (size_t)bh * SEQ * HD;
    const int j0 = jt * 64;
#pragma unroll
    for (int js = 0; js < 4; js++) {
        const float* vsrc = Vb + (size_t)(j0 + js * 16 + 2 * cq) * HD + dg * 8 + r;
        float v0 = vsrc[0];
        float v1 = vsrc[HD];
        float v2 = vsrc[8 * HD];
        float v3 = vsrc[9 * HD];
        uint32_t h0, l0, h1, l1;
        split2(v0, v1, h0, l0);
        split2(v2, v3, h1, l1);
        *(uint4*)(g_VF + ((size_t)((bh * 32 + jt) * 8 + dg) * 4 + js) * 128 + lane * 4)
            = make_uint4(h0, h1, l0, l1);
    }
}

// ---------------------------------------------------------------------------
// GEMM core: 3-stage cp.async pipeline (unchanged from R13 known-good).
// ---------------------------------------------------------------------------
template<int KGC>
__device__ __forceinline__ void gemm_core(
    const uint32_t* __restrict__ XA, const uint32_t* __restrict__ WF,
    float C[2][8][4])
{
    extern __shared__ uint32_t sm[];
    uint32_t* AsmB = sm;             // [3][8][2][256]
    uint32_t* BsmB = sm + 12288;     // [3][16][2][128]

    const int tid  = threadIdx.x;
    const int warp = tid >> 5;
    const int lane = tid & 31;
    const int wm = warp >> 1, wn = warp & 1;
    const int m0 = blockIdx.y * 128;
    const int n0 = blockIdx.x * 128;
    const int mgA = (m0 >> 4) + warp;
    const int ngB = (n0 >> 3);

    auto copy_chunk = [&](int ch, int bf) {
        const int kg0 = ch * 2;
        uint32_t* A = AsmB + bf * 4096;
        uint32_t* B = BsmB + bf * 4096;
#pragma unroll
        for (int t = 0; t < 2; t++) {
            const uint32_t* src = XA + ((size_t)(mgA * KGC + kg0 + t) * 2) * 128 + lane * 4;
            cp16(&A[warp * 512 + t * 256 + lane * 4], src);
            cp16(&A[warp * 512 + t * 256 + 128 + lane * 4], src + 128);
        }
#pragma unroll
        for (int t = 0; t < 4; t++) {
            const int ngl = warp * 2 + (t >> 1), ks = t & 1;
            cp16(&B[ngl * 256 + ks * 128 + lane * 4],
                 WF + (size_t)((ngB + ngl) * KGC + kg0 + ks) * 128 + lane * 4);
        }
        CP_COMMIT();
    };

#pragma unroll
    for (int mg = 0; mg < 2; mg++)
#pragma unroll
        for (int ng = 0; ng < 8; ng++)
#pragma unroll
            for (int e = 0; e < 4; e++) C[mg][ng][e] = 0.0f;

    const int NCH = KGC / 2;
    copy_chunk(0, 0);
    copy_chunk(1, 1);

    for (int ch = 0; ch < NCH; ++ch) {
        const int cur = ch % 3;
        if (ch + 1 < NCH) { CP_WAIT1(); } else { CP_WAIT0(); }
        __syncthreads();
        const uint32_t* A = AsmB + cur * 4096;
        const uint32_t* B = BsmB + cur * 4096;
#pragma unroll
        for (int ks = 0; ks < 2; ks++) {
            uint4 a0h = *(const uint4*)&A[(wm * 2 + 0) * 512 + ks * 256 + lane * 4];
            uint4 a0l = *(const uint4*)&A[(wm * 2 + 0) * 512 + ks * 256 + 128 + lane * 4];
            uint4 a1h = *(const uint4*)&A[(wm * 2 + 1) * 512 + ks * 256 + lane * 4];
            uint4 a1l = *(const uint4*)&A[(wm * 2 + 1) * 512 + ks * 256 + 128 + lane * 4];
#pragma unroll
            for (int ng = 0; ng < 8; ng++) {
                uint4 b = *(const uint4*)&B[(wn * 8 + ng) * 256 + ks * 128 + lane * 4];
                mma_bf16_u4(C[0][ng], a0h, b.x, b.y);
                mma_bf16_u4(C[0][ng], a0l, b.x, b.y);
                mma_bf16_u4(C[0][ng], a0h, b.z, b.w);
                mma_bf16_u4(C[1][ng], a1h, b.x, b.y);
                mma_bf16_u4(C[1][ng], a1l, b.x, b.y);
                mma_bf16_u4(C[1][ng], a1h, b.z, b.w);
            }
        }
        if (ch + 2 < NCH) copy_chunk(ch + 2, (ch + 2) % 3);
    }
}

// ---------------------------------------------------------------------------
// Fused Q/K/V projection (unchanged from R13 known-good).
// ---------------------------------------------------------------------------
__global__ __launch_bounds__(256, 2) void proj_qkv(
    const float* __restrict__ bq, const float* __restrict__ bk,
    const float* __restrict__ bv)
{
    const int z = blockIdx.z;
    const uint32_t* WF = (z == 0) ? g_WqF : (z == 1) ? g_WkF : g_WvF;
    const float* bias = (z == 0) ? bq : (z == 1) ? bk : bv;

    float C[2][8][4];
    gemm_core<64>(g_XA, WF, C);

    const int tid  = threadIdx.x;
    const int warp = tid >> 5;
    const int lane = tid & 31;
    const int wm = warp >> 1, wn = warp & 1;
    const int g = lane >> 2, tg = lane & 3;
    const int m0 = blockIdx.y * 128;
    const int n0 = blockIdx.x * 128;
    const int h = (n0 + wn * 64) >> 6;

    float bb[8][2];
#pragma unroll
    for (int ng = 0; ng < 8; ng++) {
        const int n = n0 + wn * 64 + ng * 8 + 2 * tg;
        bb[ng][0] = bias[n];
        bb[ng][1] = bias[n + 1];
    }

#pragma unroll
    for (int mg = 0; mg < 2; mg++) {
        const int mtile = m0 + wm * 32 + mg * 16;
        const int b = mtile >> 11;
        const int stile = mtile & (SEQ - 1);
        const int bh = b * NH + h;
        float v[2][16];
#pragma unroll
        for (int half = 0; half < 2; half++) {
#pragma unroll
            for (int ng = 0; ng < 8; ng++) {
                v[half][2 * ng]     = C[mg][ng][half * 2]     + bb[ng][0];
                v[half][2 * ng + 1] = C[mg][ng][half * 2 + 1] + bb[ng][1];
            }
            if (z < 2) {
                float mx = v[half][0];
#pragma unroll
                for (int e = 1; e < 16; e++) mx = fmaxf(mx, v[half][e]);
                mx = fmaxf(mx, __shfl_xor_sync(0xffffffffu, mx, 1));
                mx = fmaxf(mx, __shfl_xor_sync(0xffffffffu, mx, 2));
                float sum = 0.0f;
#pragma unroll
                for (int e = 0; e < 16; e++) { v[half][e] = __expf(v[half][e] - mx); sum += v[half][e]; }
                sum += __shfl_xor_sync(0xffffffffu, sum, 1);
                sum += __shfl_xor_sync(0xffffffffu, sum, 2);
                const float inv = 1.0f / sum;
#pragma unroll
                for (int e = 0; e < 16; e++) v[half][e] = sqrtf(v[half][e] * inv);
            }
        }

        if (z == 0) {
            const int sg = stile >> 4;
#pragma unroll
            for (int ks = 0; ks < 4; ks++) {
                uint32_t h4[4], l4[4];
                split2(v[0][4 * ks],     v[0][4 * ks + 1], h4[0], l4[0]);
                split2(v[1][4 * ks],     v[1][4 * ks + 1], h4[1], l4[1]);
                split2(v[0][4 * ks + 2], v[0][4 * ks + 3], h4[2], l4[2]);
                split2(v[1][4 * ks + 2], v[1][4 * ks + 3], h4[3], l4[3]);
                uint32_t* dst = g_QA + (((size_t)(bh * 128 + sg) * 4 + ks) * 2) * 128 + lane * 4;
                *(uint4*)dst         = make_uint4(h4[0], h4[1], h4[2], h4[3]);
                *(uint4*)(dst + 128) = make_uint4(l4[0], l4[1], l4[2], l4[3]);
            }
        } else if (z == 1) {
#pragma unroll
            for (int half = 0; half < 2; half++) {
                const int s = stile + g + half * 8;
                const int jt = s >> 6, jg = (s >> 3) & 7;
                const int lp = (s & 7) * 4 + tg;
#pragma unroll
                for (int ks = 0; ks < 4; ks++) {
                    uint32_t h0, l0, h1, l1;
                    split2(v[half][4 * ks],     v[half][4 * ks + 1], h0, l0);
                    split2(v[half][4 * ks + 2], v[half][4 * ks + 3], h1, l1);
                    *(uint4*)(g_KF + (((size_t)((bh * 32 + jt) * 8 + jg) * 4 + ks)) * 128 + lp * 4)
                        = make_uint4(h0, h1, l0, l1);
                }
            }
        } else {
#pragma unroll
            for (int half = 0; half < 2; half++) {
                const int s = stile + g + half * 8;
                float* dst = g_V + ((size_t)bh * SEQ + s) * HD;
#pragma unroll
                for (int ng = 0; ng < 8; ng++) {
                    float2 t = { v[half][2 * ng], v[half][2 * ng + 1] };
                    *(float2*)(dst + ng * 8 + 2 * tg) = t;
                }
            }
        }
    }
}

// ---------------------------------------------------------------------------
__global__ __launch_bounds__(256, 2) void out_gemm(
    const float* __restrict__ bias, float* __restrict__ out)
{
    float C[2][8][4];
    gemm_core<32>(g_AF, g_WoF, C);

    const int tid  = threadIdx.x;
    const int warp = tid >> 5;
    const int lane = tid & 31;
    const int wm = warp >> 1, wn = warp & 1;
    const int g = lane >> 2, tg = lane & 3;
    const int m0 = blockIdx.y * 128;
    const int n0 = blockIdx.x * 128;

    float bb[8][2];
#pragma unroll
    for (int ng = 0; ng < 8; ng++) {
        const int n = n0 + wn * 64 + ng * 8 + 2 * tg;
        bb[ng][0] = bias[n];
        bb[ng][1] = bias[n + 1];
    }
#pragma unroll
    for (int mg = 0; mg < 2; mg++) {
#pragma unroll
        for (int half = 0; half < 2; half++) {
            const int m = m0 + wm * 32 + mg * 16 + g + half * 8;
            float* dst = out + (size_t)m * KIN + n0 + wn * 64;
#pragma unroll
            for (int ng = 0; ng < 8; ng++) {
                float2 t = { C[mg][ng][half * 2]     + bb[ng][0],
                             C[mg][ng][half * 2 + 1] + bb[ng][1] };
                *(float2*)(dst + ng * 8 + 2 * tg) = t;
            }
        }
    }
}

// ---------------------------------------------------------------------------
// Attention v2: 128 threads (4 warps), each warp owns 32 i-rows (2 A-frag
// sets) -> every B-frag LDS.128 feeds 2x the MMAs (smem traffic halved).
// 3-stage cp.async pipeline; 96 KB smem; 2 blocks/SM; grid (16,16) one wave.
// ---------------------------------------------------------------------------
__global__ __launch_bounds__(128, 2) void attn_tc()
{
    extern __shared__ uint32_t sm[];
    uint32_t* QsB = sm;             // [3][8][4][128]
    uint32_t* VsB = sm + 12288;

    const int tid  = threadIdx.x;
    const int warp = tid >> 5;      // 0..3
    const int lane = tid & 31;
    const int bh   = blockIdx.y;
    const int i0   = blockIdx.x * 128;

    // --- preload 2 A-frag sets (32 i-rows) from g_QA ---
    uint4 AhiV[2][4], AloV[2][4];
#pragma unroll
    for (int s = 0; s < 2; s++) {
        const int sg = (i0 >> 4) + warp * 2 + s;
#pragma unroll
        for (int ks = 0; ks < 4; ks++) {
            const uint32_t* src = g_QA + (((size_t)(bh * 128 + sg) * 4 + ks) * 2) * 128 + lane * 4;
            AhiV[s][ks] = *(const uint4*)src;
            AloV[s][ks] = *(const uint4*)(src + 128);
        }
    }

    const u64t K9 = dup2f(-2.0705e-4f);
    const u64t K8 = dup2f(-2.6002e-4f);
    const u64t K7 = dup2f(-6.2160e-4f);
    const u64t K6 = dup2f(-1.52229e-3f);
    const u64t K5 = dup2f(-3.84800e-3f);
    const u64t K4 = dup2f(-1.015873e-2f);
    const u64t K3 = dup2f(-2.8571429e-2f);
    const u64t K2 = dup2f(-8.8888889e-2f);
    const u64t K1 = dup2f(-0.33333333f);
    const u64t K0 = dup2f(-2.0f);
    const u64t CM1 = dup2f(-1.0f);
    const u64t CP1 = dup2f(1.0f);

    // staging: warp stages jg/dg in {warp*2, warp*2+1}
    auto copy_tile = [&](int jt, int bf) {
        uint32_t* Q = QsB + bf * 4096;
        uint32_t* Vv = VsB + bf * 4096;
#pragma unroll
        for (int t = 0; t < 2; t++) {
            const int gidx = warp * 2 + t;
            const uint32_t* qs = g_KF + ((size_t)((bh * 32 + jt) * 8 + gidx) * 4) * 128 + lane * 4;
            const uint32_t* vs = g_VF + ((size_t)((bh * 32 + jt) * 8 + gidx) * 4) * 128 + lane * 4;
#pragma unroll
            for (int ks = 0; ks < 4; ks++) {
                cp16(&Q[gidx * 512 + ks * 128 + lane * 4],  qs + ks * 128);
                cp16(&Vv[gidx * 512 + ks * 128 + lane * 4], vs + ks * 128);
            }
        }
        CP_COMMIT();
    };

    float o[2][8][4];
#pragma unroll
    for (int s = 0; s < 2; s++)
#pragma unroll
        for (int dg = 0; dg < 8; dg++)
#pragma unroll
            for (int e = 0; e < 4; e++) o[s][dg][e] = 0.0f;
    float den[2][2] = { {0.0f, 0.0f}, {0.0f, 0.0f} };

    copy_tile(0, 0);
    copy_tile(1, 1);

    const int NT = SEQ / 64;   // 32
    for (int t = 0; t < NT; ++t) {
        const int cur = t % 3;
        if (t + 1 < NT) { CP_WAIT1(); } else { CP_WAIT0(); }
        __syncthreads();
        const uint32_t* Q = QsB + cur * 4096;
        const uint32_t* Vv = VsB + cur * 4096;

#pragma unroll
        for (int ks2 = 0; ks2 < 4; ks2++) {
            uint32_t Whi4[2][4], Wlo4[2][4];
#pragma unroll
            for (int s = 0; s < 2; s++) {
#pragma unroll
                for (int e = 0; e < 2; e++) {
                    const int jg = 2 * ks2 + e;
                    float acc[4] = { 0.0f, 0.0f, 0.0f, 0.0f };
#pragma unroll
                    for (int ks = 0; ks < 4; ks++) {
                        uint4 q = *(const uint4*)&Q[jg * 512 + ks * 128 + lane * 4];
                        mma_bf16_u4(acc, AhiV[s][ks], q.x, q.y);
                        mma_bf16_u4(acc, AloV[s][ks], q.x, q.y);
                        mma_bf16_u4(acc, AhiV[s][ks], q.z, q.w);
                    }
                    u64t ua = fma2(pk2(acc[0], acc[1]), CM1, CP1);
                    u64t ub = fma2(pk2(acc[2], acc[3]), CM1, CP1);
                    u64t ga = K9, gb = K9;
                    ga = fma2(ga, ua, K8);  gb = fma2(gb, ub, K8);
                    ga = fma2(ga, ua, K7);  gb = fma2(gb, ub, K7);
                    ga = fma2(ga, ua, K6);  gb = fma2(gb, ub, K6);
                    ga = fma2(ga, ua, K5);  gb = fma2(gb, ub, K5);
                    ga = fma2(ga, ua, K4);  gb = fma2(gb, ub, K4);
                    ga = fma2(ga, ua, K3);  gb = fma2(gb, ub, K3);
                    ga = fma2(ga, ua, K2);  gb = fma2(gb, ub, K2);
                    ga = fma2(ga, ua, K1);  gb = fma2(gb, ub, K1);
                    ga = fma2(ga, ua, K0);  gb = fma2(gb, ub, K0);
                    ga = mul2(ga, ua);      gb = mul2(gb, ub);
                    float2 gA = unpk(ga), gB = unpk(gb);
                    float w0 = __expf(gA.x), w1 = __expf(gA.y);
                    float w2 = __expf(gB.x), w3 = __expf(gB.y);
                    den[s][0] += w0 + w1;
                    den[s][1] += w2 + w3;
                    split2(w0, w1, Whi4[s][2 * e + 0], Wlo4[s][2 * e + 0]);
                    split2(w2, w3, Whi4[s][2 * e + 1], Wlo4[s][2 * e + 1]);
                }
            }
            // w @ V for js = ks2, both i-sets share the V frag read
#pragma unroll
            for (int dg = 0; dg < 8; dg++) {
                uint4 v = *(const uint4*)&Vv[dg * 512 + ks2 * 128 + lane * 4];
#pragma unroll
                for (int s = 0; s < 2; s++) {
                    mma_bf16(o[s][dg], Whi4[s], v.x, v.y);
                    mma_bf16(o[s][dg], Wlo4[s], v.x, v.y);
                    mma_bf16(o[s][dg], Whi4[s], v.z, v.w);
                }
            }
        }

        if (t + 2 < NT) copy_tile(t + 2, (t + 2) % 3);
    }

    // epilogue per i-set
    const int b = bh >> 3, hh = bh & 7;
#pragma unroll
    for (int s = 0; s < 2; s++) {
        float d0 = den[s][0], d1 = den[s][1];
        d0 += __shfl_xor_sync(0xffffffffu, d0, 1);
        d0 += __shfl_xor_sync(0xffffffffu, d0, 2);
        d1 += __shfl_xor_sync(0xffffffffu, d1, 1);
        d1 += __shfl_xor_sync(0xffffffffu, d1, 2);
        const float inv0 = 1.0f / d0;
        const float inv1 = 1.0f / d1;

        const int mgg = b * 128 + (i0 >> 4) + warp * 2 + s;
#pragma unroll
        for (int k = 0; k < 4; k++) {
            uint32_t h4[4], l4[4];
            split2(o[s][2 * k][0] * inv0,     o[s][2 * k][1] * inv0,     h4[0], l4[0]);
            split2(o[s][2 * k][2] * inv1,     o[s][2 * k][3] * inv1,     h4[1], l4[1]);
            split2(o[s][2 * k + 1][0] * inv0, o[s][2 * k + 1][1] * inv0, h4[2], l4[2]);
            split2(o[s][2 * k + 1][2] * inv1, o[s][2 * k + 1][3] * inv1, h4[3], l4[3]);
            const int ksg = hh * 4 + k;
            uint32_t* dst = g_AF + ((size_t)(mgg * 32 + ksg) * 2) * 128 + lane * 4;
            *(uint4*)dst         = make_uint4(h4[0], h4[1], h4[2], h4[3]);
            *(uint4*)(dst + 128) = make_uint4(l4[0], l4[1], l4[2], l4[3]);
        }
    }
}

// ---------------------------------------------------------------------------
extern "C" void kernel_launch(void* const* d_in, const int* in_sizes, int n_in,
                              void* d_out, int out_size)
{
    const float* xr = (const float*)d_in[0];
    const float* xi = (const float*)d_in[1];
    const float* Wq = (const float*)d_in[2];
    const float* bq = (const float*)d_in[3];
    const float* Wk = (const float*)d_in[4];
    const float* bk = (const float*)d_in[5];
    const float* Wv = (const float*)d_in[6];
    const float* bv = (const float*)d_in[7];
    const float* Wo = (const float*)d_in[8];
    const float* bo = (const float*)d_in[9];
    float* out = (float*)d_out;

    const int smem = 98304;
    cudaFuncSetAttribute(proj_qkv, cudaFuncAttributeMaxDynamicSharedMemorySize, smem);
    cudaFuncSetAttribute(out_gemm, cudaFuncAttributeMaxDynamicSharedMemorySize, smem);
    cudaFuncSetAttribute(attn_tc,  cudaFuncAttributeMaxDynamicSharedMemorySize, smem);

    prep_xa<<<dim3(32, 64), 256>>>(xr, xi);
    prep_w_all<<<dim3(64, 8, 4), 256>>>(Wq, Wk, Wv, Wo);

    dim3 gp(DIM / 128, MTOT / 128, 3);       // (4, 32, 3)
    proj_qkv<<<gp, 256, smem>>>(bq, bk, bv);

    repack_v<<<dim3(32, 16), 256>>>();

    dim3 ga(SEQ / 128, BATCH * NH);          // (16, 16) = 256 blocks
    attn_tc<<<ga, 128, smem>>>();

    dim3 go(KIN / 128, MTOT / 128);          // (8, 32)
    out_gemm<<<go, 256, smem>>>(bo, out);
}